// round 1
// baseline (speedup 1.0000x reference)
#include <cuda_runtime.h>

// Problem constants (fixed by the dataset).
#define DD 256
static const int NE  = 50000;    // events (= edges in hypergraph, = total_events)
static const int NO  = 100000;   // objects
static const int NN  = 150000;   // nodes = NE + NO
static const int E1N = 400000;   // object-event incidences
static const int E2N = 800000;   // hypergraph incidences

// -------- device scratch (no cudaMalloc allowed) --------
__device__ float    g_X  [(size_t)NN * DD];  // rows [0,NE): ev, rows [NE,NN): obj2
__device__ float    g_obj[(size_t)NO * DD];
__device__ float    g_msg[(size_t)NO * DD];
__device__ float    g_tmp[(size_t)NO * DD];  // pre-LN GEMM output
__device__ float    g_M  [(size_t)NN * DD];  // hgnn m = X @ W
__device__ float    g_H  [(size_t)NN * DD];  // layer-1 out (pre-lrelu)
__device__ float    g_ef [(size_t)NE * DD];  // edge features (sum -> mean)
__device__ float    g_cnt[NE];
__device__ float    g_snode[NN];
__device__ float    g_sedge[NE];
__device__ unsigned g_smax[NN];
__device__ float    g_z[NN];
__device__ float    g_score[E2N];
__device__ float    g_ew[E2N];

// -------- helpers --------
__device__ __forceinline__ float lrelu_f(float x) { return x >= 0.f ? x : 0.2f * x; }

__device__ __forceinline__ unsigned long long fma2(unsigned long long a,
                                                   unsigned long long b,
                                                   unsigned long long c) {
    unsigned long long d;
    asm("fma.rn.f32x2 %0, %1, %2, %3;" : "=l"(d) : "l"(a), "l"(b), "l"(c));
    return d;
}
__device__ __forceinline__ unsigned long long splat2(float a) {
    unsigned long long d;
    asm("mov.b64 %0, {%1, %1};" : "=l"(d) : "f"(a));
    return d;
}
__device__ __forceinline__ void redAdd4(float* p, float4 v) {
    asm volatile("red.global.add.v4.f32 [%0], {%1, %2, %3, %4};"
                 :: "l"(p), "f"(v.x), "f"(v.y), "f"(v.z), "f"(v.w) : "memory");
}

enum { F_BIAS = 1, F_LRELU = 2, F_RES = 4, F_LRELUA = 8 };

// -------- GEMM: C[M,256] = epilogue(A[M,256] @ B[256,256]) --------
// 128x128 tile, BK=16, 256 threads, 8x8 per thread, packed f32x2 FMA.
template <int FLAGS>
__global__ __launch_bounds__(256, 2)
void sgemm256(const float* __restrict__ A, const float* __restrict__ B,
              const float* __restrict__ bias, const float* __restrict__ R,
              float* __restrict__ C, int Mrows)
{
    __shared__ float As[2][16][132];   // k-major (transposed) + pad
    __shared__ float Bs[2][16][128];

    const int tid = threadIdx.x;
    const int tm = tid >> 4;           // 0..15 -> rows tm*8..tm*8+7
    const int tn = tid & 15;           // 0..15 -> cols tn*4 and 64+tn*4
    const int rowBase = blockIdx.y * 128;
    const int colBase = blockIdx.x * 128;

    unsigned long long acc[8][4];
#pragma unroll
    for (int i = 0; i < 8; i++)
#pragma unroll
        for (int j = 0; j < 4; j++) acc[i][j] = 0ull;

    float4 ra[2], rb[2];

    auto ldG = [&](int kt) {
#pragma unroll
        for (int i = 0; i < 2; i++) {
            int idx = tid + i * 256;           // 0..511
            int r = idx >> 2, c4 = idx & 3;    // A tile: 128 rows x 16 cols
            int row = rowBase + r;
            float4 v = make_float4(0.f, 0.f, 0.f, 0.f);
            if (row < Mrows)
                v = *reinterpret_cast<const float4*>(A + (size_t)row * DD + kt * 16 + c4 * 4);
            if (FLAGS & F_LRELUA) {
                v.x = lrelu_f(v.x); v.y = lrelu_f(v.y);
                v.z = lrelu_f(v.z); v.w = lrelu_f(v.w);
            }
            ra[i] = v;
        }
#pragma unroll
        for (int i = 0; i < 2; i++) {
            int idx = tid + i * 256;
            int r = idx >> 5, c4 = idx & 31;   // B tile: 16 rows x 128 cols
            rb[i] = *reinterpret_cast<const float4*>(B + (size_t)(kt * 16 + r) * DD + colBase + c4 * 4);
        }
    };
    auto stS = [&](int s) {
#pragma unroll
        for (int i = 0; i < 2; i++) {
            int idx = tid + i * 256;
            int r = idx >> 2, c4 = idx & 3;
            As[s][c4 * 4 + 0][r] = ra[i].x;
            As[s][c4 * 4 + 1][r] = ra[i].y;
            As[s][c4 * 4 + 2][r] = ra[i].z;
            As[s][c4 * 4 + 3][r] = ra[i].w;
        }
#pragma unroll
        for (int i = 0; i < 2; i++) {
            int idx = tid + i * 256;
            int r = idx >> 5, c4 = idx & 31;
            *reinterpret_cast<float4*>(&Bs[s][r][c4 * 4]) = rb[i];
        }
    };

    ldG(0); stS(0);
    __syncthreads();

    for (int kt = 0; kt < 16; kt++) {
        int s = kt & 1;
        if (kt < 15) ldG(kt + 1);
#pragma unroll
        for (int k = 0; k < 16; k++) {
            float4 a0 = *reinterpret_cast<const float4*>(&As[s][k][tm * 8]);
            float4 a1 = *reinterpret_cast<const float4*>(&As[s][k][tm * 8 + 4]);
            float av[8] = {a0.x, a0.y, a0.z, a0.w, a1.x, a1.y, a1.z, a1.w};
            union { float4 f; unsigned long long u[2]; } b0, b1;
            b0.f = *reinterpret_cast<const float4*>(&Bs[s][k][tn * 4]);
            b1.f = *reinterpret_cast<const float4*>(&Bs[s][k][64 + tn * 4]);
            unsigned long long bp[4] = {b0.u[0], b0.u[1], b1.u[0], b1.u[1]};
#pragma unroll
            for (int i = 0; i < 8; i++) {
                unsigned long long as = splat2(av[i]);
#pragma unroll
                for (int jp = 0; jp < 4; jp++) acc[i][jp] = fma2(as, bp[jp], acc[i][jp]);
            }
        }
        if (kt < 15) { __syncthreads(); stS(s ^ 1); __syncthreads(); }
    }

    float4 bv0 = make_float4(0.f, 0.f, 0.f, 0.f), bv1 = bv0;
    if (FLAGS & F_BIAS) {
        bv0 = *reinterpret_cast<const float4*>(bias + colBase + tn * 4);
        bv1 = *reinterpret_cast<const float4*>(bias + colBase + 64 + tn * 4);
    }
#pragma unroll
    for (int i = 0; i < 8; i++) {
        int row = rowBase + tm * 8 + i;
        if (row >= Mrows) continue;
        union { unsigned long long u; float2 f; } c0, c1, c2, c3;
        c0.u = acc[i][0]; c1.u = acc[i][1]; c2.u = acc[i][2]; c3.u = acc[i][3];
        float4 o0 = make_float4(c0.f.x, c0.f.y, c1.f.x, c1.f.y);
        float4 o1 = make_float4(c2.f.x, c2.f.y, c3.f.x, c3.f.y);
        if (FLAGS & F_BIAS) {
            o0.x += bv0.x; o0.y += bv0.y; o0.z += bv0.z; o0.w += bv0.w;
            o1.x += bv1.x; o1.y += bv1.y; o1.z += bv1.z; o1.w += bv1.w;
        }
        if (FLAGS & F_LRELU) {
            o0.x = lrelu_f(o0.x); o0.y = lrelu_f(o0.y); o0.z = lrelu_f(o0.z); o0.w = lrelu_f(o0.w);
            o1.x = lrelu_f(o1.x); o1.y = lrelu_f(o1.y); o1.z = lrelu_f(o1.z); o1.w = lrelu_f(o1.w);
        }
        if (FLAGS & F_RES) {
            float4 r0 = *reinterpret_cast<const float4*>(R + (size_t)row * DD + colBase + tn * 4);
            float4 r1 = *reinterpret_cast<const float4*>(R + (size_t)row * DD + colBase + 64 + tn * 4);
            o0.x += r0.x; o0.y += r0.y; o0.z += r0.z; o0.w += r0.w;
            o1.x += r1.x; o1.y += r1.y; o1.z += r1.z; o1.w += r1.w;
        }
        *reinterpret_cast<float4*>(C + (size_t)row * DD + colBase + tn * 4) = o0;
        *reinterpret_cast<float4*>(C + (size_t)row * DD + colBase + 64 + tn * 4) = o1;
    }
}

// -------- LayerNorm over rows of 256 (warp per row) --------
__global__ void ln_rows(const float* __restrict__ in, const float* __restrict__ g,
                        const float* __restrict__ b, float* __restrict__ out, int rows)
{
    int row = blockIdx.x * 8 + (threadIdx.x >> 5);
    if (row >= rows) return;
    int lane = threadIdx.x & 31;
    const float4* rp = reinterpret_cast<const float4*>(in + (size_t)row * DD);
    float4 v0 = rp[lane], v1 = rp[lane + 32];
    float s = v0.x + v0.y + v0.z + v0.w + v1.x + v1.y + v1.z + v1.w;
    float q = v0.x*v0.x + v0.y*v0.y + v0.z*v0.z + v0.w*v0.w
            + v1.x*v1.x + v1.y*v1.y + v1.z*v1.z + v1.w*v1.w;
#pragma unroll
    for (int o = 16; o; o >>= 1) {
        s += __shfl_xor_sync(0xFFFFFFFFu, s, o);
        q += __shfl_xor_sync(0xFFFFFFFFu, q, o);
    }
    float mean = s * (1.f / 256.f);
    float var  = q * (1.f / 256.f) - mean * mean;
    float rstd = rsqrtf(var + 1e-5f);
    const float4* gp = reinterpret_cast<const float4*>(g);
    const float4* bp = reinterpret_cast<const float4*>(b);
    float4 g0 = gp[lane], g1 = gp[lane + 32], b0 = bp[lane], b1 = bp[lane + 32];
    float4 o0, o1;
    o0.x = (v0.x - mean) * rstd * g0.x + b0.x;
    o0.y = (v0.y - mean) * rstd * g0.y + b0.y;
    o0.z = (v0.z - mean) * rstd * g0.z + b0.z;
    o0.w = (v0.w - mean) * rstd * g0.w + b0.w;
    o1.x = (v1.x - mean) * rstd * g1.x + b1.x;
    o1.y = (v1.y - mean) * rstd * g1.y + b1.y;
    o1.z = (v1.z - mean) * rstd * g1.z + b1.z;
    o1.w = (v1.w - mean) * rstd * g1.w + b1.w;
    float4* op = reinterpret_cast<float4*>(out + (size_t)row * DD);
    op[lane] = o0; op[lane + 32] = o1;
}

// -------- s[row] = dot(M[row], a) (warp per row) --------
__global__ void rowdot(const float* __restrict__ M, const float* __restrict__ a,
                       float* __restrict__ s, int rows)
{
    int row = blockIdx.x * 8 + (threadIdx.x >> 5);
    if (row >= rows) return;
    int lane = threadIdx.x & 31;
    const float4* rp = reinterpret_cast<const float4*>(M + (size_t)row * DD);
    const float4* ap = reinterpret_cast<const float4*>(a);
    float4 v0 = rp[lane], v1 = rp[lane + 32];
    float4 a0 = ap[lane], a1 = ap[lane + 32];
    float d = v0.x*a0.x + v0.y*a0.y + v0.z*a0.z + v0.w*a0.w
            + v1.x*a1.x + v1.y*a1.y + v1.z*a1.z + v1.w*a1.w;
#pragma unroll
    for (int o = 16; o; o >>= 1) d += __shfl_xor_sync(0xFFFFFFFFu, d, o);
    if (lane == 0) s[row] = d;
}

// -------- scatter-add rows: dst[di[e]] += src[si[e]]  (64 threads/incidence) --------
__global__ void scatter_rows(const float* __restrict__ src, const int* __restrict__ si,
                             const int* __restrict__ di, float* __restrict__ dst,
                             float* __restrict__ cnt, int nE)
{
    long long t = (long long)blockIdx.x * blockDim.x + threadIdx.x;
    int e = (int)(t >> 6);
    if (e >= nE) return;
    int j = (int)(t & 63);
    int sR = si[e], dR = di[e];
    float4 v = *reinterpret_cast<const float4*>(src + (size_t)sR * DD + j * 4);
    redAdd4(dst + (size_t)dR * DD + j * 4, v);
    if (cnt != nullptr && j == 0) atomicAdd(&cnt[dR], 1.0f);
}

// -------- edge finalize: ef /= max(cnt,1); sedge = dot(ef, a2) --------
__global__ void edge_fin(float* __restrict__ ef, const float* __restrict__ cnt,
                         const float* __restrict__ a2, float* __restrict__ sedge, int nEdges)
{
    int ed = blockIdx.x * 8 + (threadIdx.x >> 5);
    if (ed >= nEdges) return;
    int lane = threadIdx.x & 31;
    float inv = 1.f / fmaxf(cnt[ed], 1.f);
    float4* rp = reinterpret_cast<float4*>(ef + (size_t)ed * DD);
    float4 v0 = rp[lane], v1 = rp[lane + 32];
    v0.x *= inv; v0.y *= inv; v0.z *= inv; v0.w *= inv;
    v1.x *= inv; v1.y *= inv; v1.z *= inv; v1.w *= inv;
    rp[lane] = v0; rp[lane + 32] = v1;
    const float4* ap = reinterpret_cast<const float4*>(a2);
    float4 a0 = ap[lane], a1 = ap[lane + 32];
    float d = v0.x*a0.x + v0.y*a0.y + v0.z*a0.z + v0.w*a0.w
            + v1.x*a1.x + v1.y*a1.y + v1.z*a1.z + v1.w*a1.w;
#pragma unroll
    for (int o = 16; o; o >>= 1) d += __shfl_xor_sync(0xFFFFFFFFu, d, o);
    if (lane == 0) sedge[ed] = d;
}

// -------- per-incidence score + segment max (monotone-uint atomicMax) --------
__global__ void score_max(const float* __restrict__ sn, const float* __restrict__ se,
                          const int* __restrict__ hn, const int* __restrict__ he,
                          float* __restrict__ score, unsigned* __restrict__ smax, int nE)
{
    int e = blockIdx.x * blockDim.x + threadIdx.x;
    if (e >= nE) return;
    int n = hn[e], ed = he[e];
    float sc = sn[n] + se[ed];
    sc = sc >= 0.f ? sc : 0.2f * sc;
    score[e] = sc;
    unsigned u = __float_as_uint(sc);
    u = (u & 0x80000000u) ? ~u : (u | 0x80000000u);
    atomicMax(&smax[n], u);
}

// -------- exp + segment sum --------
__global__ void expsum(const float* __restrict__ score, const unsigned* __restrict__ smax,
                       const int* __restrict__ hn, float* __restrict__ ew,
                       float* __restrict__ z, int nE)
{
    int e = blockIdx.x * blockDim.x + threadIdx.x;
    if (e >= nE) return;
    int n = hn[e];
    unsigned u = smax[n];
    u = (u & 0x80000000u) ? (u & 0x7FFFFFFFu) : ~u;
    float mx = __uint_as_float(u);
    float w = expf(score[e] - mx);
    ew[e] = w;
    atomicAdd(&z[n], w);
}

// -------- weighted aggregate: out[node] += attn * ef[edge]; emit attn --------
__global__ void aggregate(const float* __restrict__ ew, const float* __restrict__ z,
                          const int* __restrict__ hn, const int* __restrict__ he,
                          const float* __restrict__ ef, float* __restrict__ out,
                          float* __restrict__ attn, int nE)
{
    long long t = (long long)blockIdx.x * blockDim.x + threadIdx.x;
    int e = (int)(t >> 6);
    if (e >= nE) return;
    int j = (int)(t & 63);
    int n = hn[e], ed = he[e];
    float a = ew[e] / fmaxf(z[n], 1e-9f);
    float4 v = *reinterpret_cast<const float4*>(ef + (size_t)ed * DD + j * 4);
    v.x *= a; v.y *= a; v.z *= a; v.w *= a;
    redAdd4(out + (size_t)n * DD + j * 4, v);
    if (attn != nullptr && j == 0) attn[e] = a;
}

__global__ void lrelu_vec(float* __restrict__ p, long long n4)
{
    long long i = (long long)blockIdx.x * blockDim.x + threadIdx.x;
    if (i >= n4) return;
    float4 v = reinterpret_cast<float4*>(p)[i];
    v.x = lrelu_f(v.x); v.y = lrelu_f(v.y); v.z = lrelu_f(v.z); v.w = lrelu_f(v.w);
    reinterpret_cast<float4*>(p)[i] = v;
}

// ----------------- host orchestration -----------------
struct Ptrs {
    float *X, *obj, *msg, *tmp, *M, *H, *ef, *cnt, *snode, *sedge, *z, *score, *ew;
    unsigned* smax;
};

static void get_ptrs(Ptrs& p) {
    cudaGetSymbolAddress((void**)&p.X,     g_X);
    cudaGetSymbolAddress((void**)&p.obj,   g_obj);
    cudaGetSymbolAddress((void**)&p.msg,   g_msg);
    cudaGetSymbolAddress((void**)&p.tmp,   g_tmp);
    cudaGetSymbolAddress((void**)&p.M,     g_M);
    cudaGetSymbolAddress((void**)&p.H,     g_H);
    cudaGetSymbolAddress((void**)&p.ef,    g_ef);
    cudaGetSymbolAddress((void**)&p.cnt,   g_cnt);
    cudaGetSymbolAddress((void**)&p.snode, g_snode);
    cudaGetSymbolAddress((void**)&p.sedge, g_sedge);
    cudaGetSymbolAddress((void**)&p.z,     g_z);
    cudaGetSymbolAddress((void**)&p.score, g_score);
    cudaGetSymbolAddress((void**)&p.ew,    g_ew);
    cudaGetSymbolAddress((void**)&p.smax,  g_smax);
}

static void hgnn_layer(const Ptrs& p, const float* Xin, const float* W, const float* a,
                       const int* hg_node, const int* hg_edge,
                       float* outbuf, float* attnOut, bool lreluA)
{
    dim3 gg(2, (NN + 127) / 128);
    if (lreluA) sgemm256<F_LRELUA><<<gg, 256>>>(Xin, W, nullptr, nullptr, p.M, NN);
    else        sgemm256<0>      <<<gg, 256>>>(Xin, W, nullptr, nullptr, p.M, NN);
    rowdot<<<(NN + 7) / 8, 256>>>(p.M, a, p.snode, NN);
    cudaMemsetAsync(p.ef, 0, (size_t)NE * DD * sizeof(float));
    cudaMemsetAsync(p.cnt, 0, NE * sizeof(float));
    scatter_rows<<<(int)(((long long)E2N * 64 + 255) / 256), 256>>>(p.M, hg_node, hg_edge, p.ef, p.cnt, E2N);
    edge_fin<<<(NE + 7) / 8, 256>>>(p.ef, p.cnt, a + DD, p.sedge, NE);
    cudaMemsetAsync(p.smax, 0, NN * sizeof(unsigned));
    cudaMemsetAsync(p.z, 0, NN * sizeof(float));
    score_max<<<(E2N + 255) / 256, 256>>>(p.snode, p.sedge, hg_node, hg_edge, p.score, p.smax, E2N);
    expsum<<<(E2N + 255) / 256, 256>>>(p.score, p.smax, hg_node, p.ew, p.z, E2N);
    cudaMemsetAsync(outbuf, 0, (size_t)NN * DD * sizeof(float));
    aggregate<<<(int)(((long long)E2N * 64 + 255) / 256), 256>>>(p.ew, p.z, hg_node, hg_edge, p.ef, outbuf, attnOut, E2N);
}

extern "C" void kernel_launch(void* const* d_in, const int* in_sizes, int n_in,
                              void* d_out, int out_size)
{
    const float* object_X = (const float*)d_in[0];
    const float* event_X  = (const float*)d_in[1];
    const float* Wo = (const float*)d_in[2];  const float* bo  = (const float*)d_in[3];
    const float* go = (const float*)d_in[4];  const float* bon = (const float*)d_in[5];
    const float* We = (const float*)d_in[6];  const float* be  = (const float*)d_in[7];
    const float* ge = (const float*)d_in[8];  const float* ben = (const float*)d_in[9];
    const float* Wu = (const float*)d_in[10]; const float* bu  = (const float*)d_in[11];
    const float* Wl = (const float*)d_in[12]; const float* bl  = (const float*)d_in[13];
    const float* g1 = (const float*)d_in[14]; const float* b1  = (const float*)d_in[15];
    const float* g2 = (const float*)d_in[16]; const float* b2  = (const float*)d_in[17];
    const float* Wh1 = (const float*)d_in[18]; const float* ah1 = (const float*)d_in[19];
    const float* Wh2 = (const float*)d_in[20]; const float* ah2 = (const float*)d_in[21];
    const int* oe_ev   = (const int*)d_in[22];
    const int* oe_obj  = (const int*)d_in[23];
    const int* hg_node = (const int*)d_in[24];
    const int* hg_edge = (const int*)d_in[25];

    Ptrs p; get_ptrs(p);

    dim3 gE(2, (NE + 127) / 128), gO(2, (NO + 127) / 128);

    // 1) ev = LN(lrelu(event_X @ We + be))  -> X[0:NE)
    sgemm256<F_BIAS | F_LRELU><<<gE, 256>>>(event_X, We, be, nullptr, p.tmp, NE);
    ln_rows<<<(NE + 7) / 8, 256>>>(p.tmp, ge, ben, p.X, NE);

    // 2) obj = LN(lrelu(object_X @ Wo + bo))
    sgemm256<F_BIAS | F_LRELU><<<gO, 256>>>(object_X, Wo, bo, nullptr, p.tmp, NO);
    ln_rows<<<(NO + 7) / 8, 256>>>(p.tmp, go, bon, p.obj, NO);

    // 3) msg = segment_sum(ev[oe_ev], oe_obj)
    cudaMemsetAsync(p.msg, 0, (size_t)NO * DD * sizeof(float));
    scatter_rows<<<(int)(((long long)E1N * 64 + 255) / 256), 256>>>(p.X, oe_ev, oe_obj, p.msg, nullptr, E1N);

    // 4) obj1 = LN(lrelu(msg @ Wu + bu) + obj)
    sgemm256<F_BIAS | F_LRELU | F_RES><<<gO, 256>>>(p.msg, Wu, bu, p.obj, p.tmp, NO);
    ln_rows<<<(NO + 7) / 8, 256>>>(p.tmp, g1, b1, p.obj, NO);

    // 5) obj2 = LN(lrelu(obj1 @ Wl + bl) + obj1) -> X[NE:NN)
    sgemm256<F_BIAS | F_LRELU | F_RES><<<gO, 256>>>(p.obj, Wl, bl, p.obj, p.tmp, NO);
    ln_rows<<<(NO + 7) / 8, 256>>>(p.tmp, g2, b2, p.X + (size_t)NE * DD, NO);

    // 6) HGNN layer 1 -> H (pre-lrelu; lrelu fused into layer-2 A load)
    hgnn_layer(p, p.X, Wh1, ah1, hg_node, hg_edge, p.H, nullptr, false);

    // 7) HGNN layer 2 -> d_out (h then attn)
    float* out = (float*)d_out;
    hgnn_layer(p, p.H, Wh2, ah2, hg_node, hg_edge, out, out + (size_t)NN * DD, true);
    lrelu_vec<<<(int)(((long long)NN * DD / 4 + 255) / 256), 256>>>(out, (long long)NN * DD / 4);
}

// round 3
// speedup vs baseline: 1.4536x; 1.4536x over previous
#include <cuda_runtime.h>
#include <cuda_bf16.h>
#include <cstdint>

#define DD 256
static const int NE  = 50000;
static const int NO  = 100000;
static const int NN  = 150000;
static const int E1N = 400000;
static const int E2N = 800000;

// -------- device scratch --------
__device__ float    g_X  [(size_t)NN * DD];
__device__ float    g_obj[(size_t)NO * DD];
__device__ float    g_msg[(size_t)NO * DD];
__device__ float    g_tmp[(size_t)NO * DD];
__device__ float    g_M  [(size_t)NN * DD];
__device__ float    g_H  [(size_t)NN * DD];
__device__ float    g_ef [(size_t)NE * DD];
__device__ float    g_cnt[NE];
__device__ float    g_snode[NN];
__device__ float    g_sedge[NE];
__device__ unsigned g_smax[NN];
__device__ float    g_z[NN];
__device__ float    g_score[E2N];
__device__ float    g_ew[E2N];
// prepped weights: 6 weights x 4 K-chunks x 2 planes (hi,lo) x 256 n-rows x 128B (swizzled)
__device__ unsigned char g_Wprep[6 * 4 * 2 * 256 * 128];

// -------- helpers --------
__device__ __forceinline__ float lrelu_f(float x) { return x >= 0.f ? x : 0.2f * x; }

__device__ __forceinline__ uint32_t smem_to_u32(const void* p) {
    uint32_t a;
    asm("{ .reg .u64 t; cvta.to.shared.u64 t, %1; cvt.u32.u64 %0, t; }" : "=r"(a) : "l"(p));
    return a;
}
__device__ __forceinline__ void redAdd4(float* p, float4 v) {
    asm volatile("red.global.add.v4.f32 [%0], {%1, %2, %3, %4};"
                 :: "l"(p), "f"(v.x), "f"(v.y), "f"(v.z), "f"(v.w) : "memory");
}
__device__ __forceinline__ void ldm_x4(uint32_t addr, uint32_t* r) {
    asm volatile("ldmatrix.sync.aligned.m8n8.x4.shared.b16 {%0,%1,%2,%3}, [%4];"
                 : "=r"(r[0]), "=r"(r[1]), "=r"(r[2]), "=r"(r[3]) : "r"(addr));
}
__device__ __forceinline__ void mma_bf16(float* c, const uint32_t* a, const uint32_t* b) {
    asm volatile("mma.sync.aligned.m16n8k16.row.col.f32.bf16.bf16.f32 "
                 "{%0,%1,%2,%3}, {%4,%5,%6,%7}, {%8,%9}, {%0,%1,%2,%3};"
                 : "+f"(c[0]), "+f"(c[1]), "+f"(c[2]), "+f"(c[3])
                 : "r"(a[0]), "r"(a[1]), "r"(a[2]), "r"(a[3]), "r"(b[0]), "r"(b[1]));
}
// byte offset within a 128-rows x 128B tile, phase-swizzled per row
__device__ __forceinline__ uint32_t swz(uint32_t row, uint32_t cb) {
    return row * 128u + (cb ^ ((row & 7u) << 4));
}

enum { F_BIAS = 1, F_LRELU = 2, F_RES = 4, F_LRELUA = 8, F_SNODE = 16 };

// -------- weight prep: transpose, split hi/lo bf16, swizzle, chunk K by 64 --------
__global__ void prep_w(const float* W0, const float* W1, const float* W2,
                       const float* W3, const float* W4, const float* W5)
{
    const float* Ws[6] = {W0, W1, W2, W3, W4, W5};
    const float* W = Ws[blockIdx.y];
    unsigned char* base = g_Wprep + (size_t)blockIdx.y * 262144;
    int g = blockIdx.x * 256 + threadIdx.x;   // 0..8191
    int n = g >> 5, kg = g & 31, k0 = kg * 8;
    unsigned short hi[8], lo[8];
#pragma unroll
    for (int i = 0; i < 8; i++) {
        float x = W[(size_t)(k0 + i) * DD + n];   // W^T[n][k]
        __nv_bfloat16 h = __float2bfloat16(x);
        __nv_bfloat16 l = __float2bfloat16(x - __bfloat162float(h));
        hi[i] = *reinterpret_cast<unsigned short*>(&h);
        lo[i] = *reinterpret_cast<unsigned short*>(&l);
    }
    int chunk = k0 >> 6, kc = k0 & 63;
    uint32_t off = swz((uint32_t)(n & 255), (uint32_t)kc * 2u) + (uint32_t)(0);
    // rows are 0..255 here; swz handles phase via (n&7)
    off = (uint32_t)n * 128u + (((uint32_t)kc * 2u) ^ (((uint32_t)n & 7u) << 4));
    *reinterpret_cast<uint4*>(base + (size_t)(chunk * 2 + 0) * 32768 + off) =
        *reinterpret_cast<uint4*>(hi);
    *reinterpret_cast<uint4*>(base + (size_t)(chunk * 2 + 1) * 32768 + off) =
        *reinterpret_cast<uint4*>(lo);
}

// -------- tensor-core GEMM via mma.sync: C[M,256] = epi(A[M,256] @ W) --------
// CTA tile 128x128, grid (2, M/128). 256 threads, warp tile 32(M)x64(N).
// smem: Ahi[0,16K) Alo[16K,32K) Bhi[32K,48K) Blo[48K,64K)
static const int SMEM_SZ = 65536;

template <int FLAGS>
__global__ __launch_bounds__(256, 2)
void tgemm256(const float* __restrict__ A, const unsigned char* __restrict__ Wp,
              const float* __restrict__ bias, const float* __restrict__ R,
              const float* __restrict__ av, float* __restrict__ C,
              float* __restrict__ snode, int Mrows)
{
    extern __shared__ __align__(128) unsigned char smem[];
    const uint32_t sb = smem_to_u32(smem);
    const int tid = threadIdx.x, lane = tid & 31, wid = tid >> 5;
    const int warpM = wid >> 1, warpN = wid & 1;
    const int rowBase = blockIdx.y * 128, colBase = blockIdx.x * 128;

    float c[2][8][4];
#pragma unroll
    for (int mt = 0; mt < 2; mt++)
#pragma unroll
        for (int nt = 0; nt < 8; nt++)
#pragma unroll
            for (int q = 0; q < 4; q++) c[mt][nt][q] = 0.f;

    for (int ch = 0; ch < 4; ch++) {
        // ---- fill A (fp32 -> hi/lo bf16, swizzled) ----
#pragma unroll
        for (int i = 0; i < 4; i++) {
            int g = tid + i * 256;            // 0..1023
            int r = g >> 3, cg = g & 7;
            int row = rowBase + r;
            float x[8];
            if (row < Mrows) {
                const float4* src = reinterpret_cast<const float4*>(
                    A + (size_t)row * DD + ch * 64 + cg * 8);
                float4 v0 = src[0], v1 = src[1];
                x[0] = v0.x; x[1] = v0.y; x[2] = v0.z; x[3] = v0.w;
                x[4] = v1.x; x[5] = v1.y; x[6] = v1.z; x[7] = v1.w;
            } else {
#pragma unroll
                for (int j = 0; j < 8; j++) x[j] = 0.f;
            }
            unsigned short hi[8], lo[8];
#pragma unroll
            for (int j = 0; j < 8; j++) {
                if (FLAGS & F_LRELUA) x[j] = lrelu_f(x[j]);
                __nv_bfloat16 h = __float2bfloat16(x[j]);
                __nv_bfloat16 l = __float2bfloat16(x[j] - __bfloat162float(h));
                hi[j] = *reinterpret_cast<unsigned short*>(&h);
                lo[j] = *reinterpret_cast<unsigned short*>(&l);
            }
            uint32_t off = swz((uint32_t)r, (uint32_t)cg * 16u);
            *reinterpret_cast<uint4*>(smem + off)         = *reinterpret_cast<uint4*>(hi);
            *reinterpret_cast<uint4*>(smem + 16384 + off) = *reinterpret_cast<uint4*>(lo);
        }
        // ---- fill B (straight copies; pre-swizzled in gmem) ----
        {
            const uint4* bh = reinterpret_cast<const uint4*>(
                Wp + (size_t)(ch * 2 + 0) * 32768 + (size_t)colBase * 128);
            const uint4* bl = reinterpret_cast<const uint4*>(
                Wp + (size_t)(ch * 2 + 1) * 32768 + (size_t)colBase * 128);
            uint4* sh = reinterpret_cast<uint4*>(smem + 32768);
            uint4* sl = reinterpret_cast<uint4*>(smem + 49152);
#pragma unroll
            for (int i = 0; i < 4; i++) {
                int idx = tid + i * 256;       // 0..1023 (16KB / 16B)
                sh[idx] = bh[idx];
                sl[idx] = bl[idx];
            }
        }
        __syncthreads();

        // ---- 4 k-steps of 16 ----
#pragma unroll
        for (int ks = 0; ks < 4; ks++) {
            uint32_t ah[2][4], al[2][4];
#pragma unroll
            for (int mt = 0; mt < 2; mt++) {
                uint32_t row = (uint32_t)(warpM * 32 + mt * 16 + (lane & 7) + ((lane >> 3) & 1) * 8);
                uint32_t kb  = (uint32_t)(ks * 32 + ((lane >> 4) & 1) * 16);
                uint32_t addr = sb + swz(row, kb);
                ldm_x4(addr,         ah[mt]);
                ldm_x4(addr + 16384, al[mt]);
            }
#pragma unroll
            for (int p = 0; p < 4; p++) {
                uint32_t nrow = (uint32_t)(warpN * 64 + p * 16 + (lane & 7) + ((lane >> 4) & 1) * 8);
                uint32_t kb   = (uint32_t)(ks * 32 + ((lane >> 3) & 1) * 16);
                uint32_t addr = sb + 32768 + swz(nrow, kb);
                uint32_t bh[4], bl[4];
                ldm_x4(addr,         bh);
                ldm_x4(addr + 16384, bl);
#pragma unroll
                for (int s = 0; s < 2; s++) {
                    const uint32_t* Bh = bh + s * 2;
                    const uint32_t* Bl = bl + s * 2;
#pragma unroll
                    for (int mt = 0; mt < 2; mt++) {
                        float* cc = c[mt][p * 2 + s];
                        mma_bf16(cc, ah[mt], Bh);
                        mma_bf16(cc, ah[mt], Bl);
                        mma_bf16(cc, al[mt], Bh);
                    }
                }
            }
        }
        __syncthreads();
    }

    // ---- epilogue ----
    const int gid = lane >> 2, tig = lane & 3;
#pragma unroll
    for (int mt = 0; mt < 2; mt++) {
        int r0 = rowBase + warpM * 32 + mt * 16 + gid;
        int r1 = r0 + 8;
        bool v0 = r0 < Mrows, v1 = r1 < Mrows;
        float s0 = 0.f, s1 = 0.f;
#pragma unroll
        for (int nt = 0; nt < 8; nt++) {
            int col = colBase + warpN * 64 + nt * 8 + tig * 2;
            float o0 = c[mt][nt][0], o1 = c[mt][nt][1];
            float o2 = c[mt][nt][2], o3 = c[mt][nt][3];
            if (FLAGS & F_BIAS) {
                float2 bv = *reinterpret_cast<const float2*>(bias + col);
                o0 += bv.x; o1 += bv.y; o2 += bv.x; o3 += bv.y;
            }
            if (FLAGS & F_LRELU) {
                o0 = lrelu_f(o0); o1 = lrelu_f(o1); o2 = lrelu_f(o2); o3 = lrelu_f(o3);
            }
            if (FLAGS & F_RES) {
                if (v0) {
                    float2 rv = *reinterpret_cast<const float2*>(R + (size_t)r0 * DD + col);
                    o0 += rv.x; o1 += rv.y;
                }
                if (v1) {
                    float2 rv = *reinterpret_cast<const float2*>(R + (size_t)r1 * DD + col);
                    o2 += rv.x; o3 += rv.y;
                }
            }
            if (FLAGS & F_SNODE) {
                float2 avv = *reinterpret_cast<const float2*>(av + col);
                s0 += o0 * avv.x + o1 * avv.y;
                s1 += o2 * avv.x + o3 * avv.y;
            }
            if (v0) *reinterpret_cast<float2*>(C + (size_t)r0 * DD + col) = make_float2(o0, o1);
            if (v1) *reinterpret_cast<float2*>(C + (size_t)r1 * DD + col) = make_float2(o2, o3);
        }
        if (FLAGS & F_SNODE) {
#pragma unroll
            for (int o = 1; o < 4; o <<= 1) {
                s0 += __shfl_xor_sync(0xFFFFFFFFu, s0, o);
                s1 += __shfl_xor_sync(0xFFFFFFFFu, s1, o);
            }
            if (tig == 0) {
                if (v0) atomicAdd(snode + r0, s0);
                if (v1) atomicAdd(snode + r1, s1);
            }
        }
    }
}

// -------- LayerNorm --------
__global__ void ln_rows(const float* __restrict__ in, const float* __restrict__ g,
                        const float* __restrict__ b, float* __restrict__ out, int rows)
{
    int row = blockIdx.x * 8 + (threadIdx.x >> 5);
    if (row >= rows) return;
    int lane = threadIdx.x & 31;
    const float4* rp = reinterpret_cast<const float4*>(in + (size_t)row * DD);
    float4 v0 = rp[lane], v1 = rp[lane + 32];
    float s = v0.x + v0.y + v0.z + v0.w + v1.x + v1.y + v1.z + v1.w;
    float q = v0.x*v0.x + v0.y*v0.y + v0.z*v0.z + v0.w*v0.w
            + v1.x*v1.x + v1.y*v1.y + v1.z*v1.z + v1.w*v1.w;
#pragma unroll
    for (int o = 16; o; o >>= 1) {
        s += __shfl_xor_sync(0xFFFFFFFFu, s, o);
        q += __shfl_xor_sync(0xFFFFFFFFu, q, o);
    }
    float mean = s * (1.f / 256.f);
    float var  = q * (1.f / 256.f) - mean * mean;
    float rstd = rsqrtf(var + 1e-5f);
    const float4* gp = reinterpret_cast<const float4*>(g);
    const float4* bp = reinterpret_cast<const float4*>(b);
    float4 g0 = gp[lane], g1 = gp[lane + 32], b0 = bp[lane], b1 = bp[lane + 32];
    float4 o0, o1;
    o0.x = (v0.x - mean) * rstd * g0.x + b0.x;
    o0.y = (v0.y - mean) * rstd * g0.y + b0.y;
    o0.z = (v0.z - mean) * rstd * g0.z + b0.z;
    o0.w = (v0.w - mean) * rstd * g0.w + b0.w;
    o1.x = (v1.x - mean) * rstd * g1.x + b1.x;
    o1.y = (v1.y - mean) * rstd * g1.y + b1.y;
    o1.z = (v1.z - mean) * rstd * g1.z + b1.z;
    o1.w = (v1.w - mean) * rstd * g1.w + b1.w;
    float4* op = reinterpret_cast<float4*>(out + (size_t)row * DD);
    op[lane] = o0; op[lane + 32] = o1;
}

// -------- scatter-add rows --------
__global__ void scatter_rows(const float* __restrict__ src, const int* __restrict__ si,
                             const int* __restrict__ di, float* __restrict__ dst,
                             float* __restrict__ cnt, int nE)
{
    long long t = (long long)blockIdx.x * blockDim.x + threadIdx.x;
    int e = (int)(t >> 6);
    if (e >= nE) return;
    int j = (int)(t & 63);
    int sR = si[e], dR = di[e];
    float4 v = *reinterpret_cast<const float4*>(src + (size_t)sR * DD + j * 4);
    redAdd4(dst + (size_t)dR * DD + j * 4, v);
    if (cnt != nullptr && j == 0) atomicAdd(&cnt[dR], 1.0f);
}

__global__ void edge_fin(float* __restrict__ ef, const float* __restrict__ cnt,
                         const float* __restrict__ a2, float* __restrict__ sedge, int nEdges)
{
    int ed = blockIdx.x * 8 + (threadIdx.x >> 5);
    if (ed >= nEdges) return;
    int lane = threadIdx.x & 31;
    float inv = 1.f / fmaxf(cnt[ed], 1.f);
    float4* rp = reinterpret_cast<float4*>(ef + (size_t)ed * DD);
    float4 v0 = rp[lane], v1 = rp[lane + 32];
    v0.x *= inv; v0.y *= inv; v0.z *= inv; v0.w *= inv;
    v1.x *= inv; v1.y *= inv; v1.z *= inv; v1.w *= inv;
    rp[lane] = v0; rp[lane + 32] = v1;
    const float4* ap = reinterpret_cast<const float4*>(a2);
    float4 a0 = ap[lane], a1 = ap[lane + 32];
    float d = v0.x*a0.x + v0.y*a0.y + v0.z*a0.z + v0.w*a0.w
            + v1.x*a1.x + v1.y*a1.y + v1.z*a1.z + v1.w*a1.w;
#pragma unroll
    for (int o = 16; o; o >>= 1) d += __shfl_xor_sync(0xFFFFFFFFu, d, o);
    if (lane == 0) sedge[ed] = d;
}

__global__ void score_max(const float* __restrict__ sn, const float* __restrict__ se,
                          const int* __restrict__ hn, const int* __restrict__ he,
                          float* __restrict__ score, unsigned* __restrict__ smax, int nE)
{
    int e = blockIdx.x * blockDim.x + threadIdx.x;
    if (e >= nE) return;
    int n = hn[e], ed = he[e];
    float sc = sn[n] + se[ed];
    sc = sc >= 0.f ? sc : 0.2f * sc;
    score[e] = sc;
    unsigned u = __float_as_uint(sc);
    u = (u & 0x80000000u) ? ~u : (u | 0x80000000u);
    atomicMax(&smax[n], u);
}

__global__ void expsum(const float* __restrict__ score, const unsigned* __restrict__ smax,
                       const int* __restrict__ hn, float* __restrict__ ew,
                       float* __restrict__ z, int nE)
{
    int e = blockIdx.x * blockDim.x + threadIdx.x;
    if (e >= nE) return;
    int n = hn[e];
    unsigned u = smax[n];
    u = (u & 0x80000000u) ? (u & 0x7FFFFFFFu) : ~u;
    float mx = __uint_as_float(u);
    float w = expf(score[e] - mx);
    ew[e] = w;
    atomicAdd(&z[n], w);
}

__global__ void aggregate(const float* __restrict__ ew, const float* __restrict__ z,
                          const int* __restrict__ hn, const int* __restrict__ he,
                          const float* __restrict__ ef, float* __restrict__ out,
                          float* __restrict__ attn, int nE)
{
    long long t = (long long)blockIdx.x * blockDim.x + threadIdx.x;
    int e = (int)(t >> 6);
    if (e >= nE) return;
    int j = (int)(t & 63);
    int n = hn[e], ed = he[e];
    float a = ew[e] / fmaxf(z[n], 1e-9f);
    float4 v = *reinterpret_cast<const float4*>(ef + (size_t)ed * DD + j * 4);
    v.x *= a; v.y *= a; v.z *= a; v.w *= a;
    redAdd4(out + (size_t)n * DD + j * 4, v);
    if (attn != nullptr && j == 0) attn[e] = a;
}

__global__ void lrelu_vec(float* __restrict__ p, long long n4)
{
    long long i = (long long)blockIdx.x * blockDim.x + threadIdx.x;
    if (i >= n4) return;
    float4 v = reinterpret_cast<float4*>(p)[i];
    v.x = lrelu_f(v.x); v.y = lrelu_f(v.y); v.z = lrelu_f(v.z); v.w = lrelu_f(v.w);
    reinterpret_cast<float4*>(p)[i] = v;
}

// ----------------- host orchestration -----------------
struct Ptrs {
    float *X, *obj, *msg, *tmp, *M, *H, *ef, *cnt, *snode, *sedge, *z, *score, *ew;
    unsigned* smax;
    unsigned char* wp;
};

static void get_ptrs(Ptrs& p) {
    cudaGetSymbolAddress((void**)&p.X,     g_X);
    cudaGetSymbolAddress((void**)&p.obj,   g_obj);
    cudaGetSymbolAddress((void**)&p.msg,   g_msg);
    cudaGetSymbolAddress((void**)&p.tmp,   g_tmp);
    cudaGetSymbolAddress((void**)&p.M,     g_M);
    cudaGetSymbolAddress((void**)&p.H,     g_H);
    cudaGetSymbolAddress((void**)&p.ef,    g_ef);
    cudaGetSymbolAddress((void**)&p.cnt,   g_cnt);
    cudaGetSymbolAddress((void**)&p.snode, g_snode);
    cudaGetSymbolAddress((void**)&p.sedge, g_sedge);
    cudaGetSymbolAddress((void**)&p.z,     g_z);
    cudaGetSymbolAddress((void**)&p.score, g_score);
    cudaGetSymbolAddress((void**)&p.ew,    g_ew);
    cudaGetSymbolAddress((void**)&p.smax,  g_smax);
    cudaGetSymbolAddress((void**)&p.wp,    g_Wprep);
}

template <int FLAGS>
static void launch_tgemm(const float* A, const unsigned char* Wp, const float* bias,
                         const float* R, const float* av, float* C, float* snode, int Mrows)
{
    cudaFuncSetAttribute(tgemm256<FLAGS>, cudaFuncAttributeMaxDynamicSharedMemorySize, SMEM_SZ);
    dim3 g(2, (Mrows + 127) / 128);
    tgemm256<FLAGS><<<g, 256, SMEM_SZ>>>(A, Wp, bias, R, av, C, snode, Mrows);
}

static void hgnn_layer(const Ptrs& p, const float* Xin, const unsigned char* Wp, const float* a,
                       const int* hg_node, const int* hg_edge,
                       float* outbuf, float* attnOut, bool lreluA)
{
    cudaMemsetAsync(p.snode, 0, NN * sizeof(float));
    if (lreluA) launch_tgemm<F_SNODE | F_LRELUA>(Xin, Wp, nullptr, nullptr, a, p.M, p.snode, NN);
    else        launch_tgemm<F_SNODE>           (Xin, Wp, nullptr, nullptr, a, p.M, p.snode, NN);
    cudaMemsetAsync(p.ef, 0, (size_t)NE * DD * sizeof(float));
    cudaMemsetAsync(p.cnt, 0, NE * sizeof(float));
    scatter_rows<<<(int)(((long long)E2N * 64 + 255) / 256), 256>>>(p.M, hg_node, hg_edge, p.ef, p.cnt, E2N);
    edge_fin<<<(NE + 7) / 8, 256>>>(p.ef, p.cnt, a + DD, p.sedge, NE);
    cudaMemsetAsync(p.smax, 0, NN * sizeof(unsigned));
    cudaMemsetAsync(p.z, 0, NN * sizeof(float));
    score_max<<<(E2N + 255) / 256, 256>>>(p.snode, p.sedge, hg_node, hg_edge, p.score, p.smax, E2N);
    expsum<<<(E2N + 255) / 256, 256>>>(p.score, p.smax, hg_node, p.ew, p.z, E2N);
    cudaMemsetAsync(outbuf, 0, (size_t)NN * DD * sizeof(float));
    aggregate<<<(int)(((long long)E2N * 64 + 255) / 256), 256>>>(p.ew, p.z, hg_node, hg_edge, p.ef, outbuf, attnOut, E2N);
}

extern "C" void kernel_launch(void* const* d_in, const int* in_sizes, int n_in,
                              void* d_out, int out_size)
{
    const float* object_X = (const float*)d_in[0];
    const float* event_X  = (const float*)d_in[1];
    const float* Wo = (const float*)d_in[2];  const float* bo  = (const float*)d_in[3];
    const float* go = (const float*)d_in[4];  const float* bon = (const float*)d_in[5];
    const float* We = (const float*)d_in[6];  const float* be  = (const float*)d_in[7];
    const float* ge = (const float*)d_in[8];  const float* ben = (const float*)d_in[9];
    const float* Wu = (const float*)d_in[10]; const float* bu  = (const float*)d_in[11];
    const float* Wl = (const float*)d_in[12]; const float* bl  = (const float*)d_in[13];
    const float* g1 = (const float*)d_in[14]; const float* b1  = (const float*)d_in[15];
    const float* g2 = (const float*)d_in[16]; const float* b2  = (const float*)d_in[17];
    const float* Wh1 = (const float*)d_in[18]; const float* ah1 = (const float*)d_in[19];
    const float* Wh2 = (const float*)d_in[20]; const float* ah2 = (const float*)d_in[21];
    const int* oe_ev   = (const int*)d_in[22];
    const int* oe_obj  = (const int*)d_in[23];
    const int* hg_node = (const int*)d_in[24];
    const int* hg_edge = (const int*)d_in[25];

    Ptrs p; get_ptrs(p);

    // 0) preprocess all 6 weights: slot order {We, Wo, Wu, Wl, Wh1, Wh2}
    prep_w<<<dim3(32, 6), 256>>>(We, Wo, Wu, Wl, Wh1, Wh2);
    const unsigned char *wpe = p.wp, *wpo = p.wp + 262144, *wpu = p.wp + 2 * 262144,
                        *wpl = p.wp + 3 * 262144, *wph1 = p.wp + 4 * 262144,
                        *wph2 = p.wp + 5 * 262144;

    // 1) ev = LN(lrelu(event_X @ We + be))  -> X[0:NE)
    launch_tgemm<F_BIAS | F_LRELU>(event_X, wpe, be, nullptr, nullptr, p.tmp, nullptr, NE);
    ln_rows<<<(NE + 7) / 8, 256>>>(p.tmp, ge, ben, p.X, NE);

    // 2) obj = LN(lrelu(object_X @ Wo + bo))
    launch_tgemm<F_BIAS | F_LRELU>(object_X, wpo, bo, nullptr, nullptr, p.tmp, nullptr, NO);
    ln_rows<<<(NO + 7) / 8, 256>>>(p.tmp, go, bon, p.obj, NO);

    // 3) msg = segment_sum(ev[oe_ev], oe_obj)
    cudaMemsetAsync(p.msg, 0, (size_t)NO * DD * sizeof(float));
    scatter_rows<<<(int)(((long long)E1N * 64 + 255) / 256), 256>>>(p.X, oe_ev, oe_obj, p.msg, nullptr, E1N);

    // 4) obj1 = LN(lrelu(msg @ Wu + bu) + obj)
    launch_tgemm<F_BIAS | F_LRELU | F_RES>(p.msg, wpu, bu, p.obj, nullptr, p.tmp, nullptr, NO);
    ln_rows<<<(NO + 7) / 8, 256>>>(p.tmp, g1, b1, p.obj, NO);

    // 5) obj2 = LN(lrelu(obj1 @ Wl + bl) + obj1) -> X[NE:NN)
    launch_tgemm<F_BIAS | F_LRELU | F_RES>(p.obj, wpl, bl, p.obj, nullptr, p.tmp, nullptr, NO);
    ln_rows<<<(NO + 7) / 8, 256>>>(p.tmp, g2, b2, p.X + (size_t)NE * DD, NO);

    // 6) HGNN layer 1 -> H (pre-lrelu; lrelu fused into layer-2 GEMM A-load)
    hgnn_layer(p, p.X, wph1, ah1, hg_node, hg_edge, p.H, nullptr, false);

    // 7) HGNN layer 2 -> d_out (h then attn)
    float* out = (float*)d_out;
    hgnn_layer(p, p.H, wph2, ah2, hg_node, hg_edge, out, out + (size_t)NN * DD, true);
    lrelu_vec<<<(int)(((long long)NN * DD / 4 + 255) / 256), 256>>>(out, (long long)NN * DD / 4);
}

// round 4
// speedup vs baseline: 2.0110x; 1.3835x over previous
#include <cuda_runtime.h>
#include <cuda_bf16.h>
#include <cstdint>

#define DD 256
static const int NE  = 50000;
static const int NO  = 100000;
static const int NN  = 150000;
static const int E1N = 400000;
static const int E2N = 800000;

// -------- device scratch --------
__device__ float    g_X  [(size_t)NN * DD];
__device__ float    g_obj[(size_t)NO * DD];
__device__ float    g_msg[(size_t)NO * DD];
__device__ float    g_tmp[(size_t)NO * DD];
__device__ float    g_M  [(size_t)NN * DD];
__device__ float    g_H  [(size_t)NN * DD];
__device__ float    g_ef [(size_t)NE * DD];
__device__ float    g_snode[NN];
__device__ float    g_sedge[NE];
__device__ float    g_ew[E2N];
// prepped weights
__device__ unsigned char g_Wprep[6 * 4 * 2 * 256 * 128];
// CSR structures
__device__ int g_cntE[NE],  g_offE[NE],  g_permE[E2N];
__device__ int g_cntN[NN],  g_offN[NN],  g_permN[E2N];
__device__ int g_cntO[NO],  g_offO[NO],  g_permO[E1N];
__device__ int g_cur[NN];
__device__ int g_bsum[256];

// -------- helpers --------
__device__ __forceinline__ float lrelu_f(float x) { return x >= 0.f ? x : 0.2f * x; }

__device__ __forceinline__ uint32_t smem_to_u32(const void* p) {
    uint32_t a;
    asm("{ .reg .u64 t; cvta.to.shared.u64 t, %1; cvt.u32.u64 %0, t; }" : "=r"(a) : "l"(p));
    return a;
}
__device__ __forceinline__ void ldm_x4(uint32_t addr, uint32_t* r) {
    asm volatile("ldmatrix.sync.aligned.m8n8.x4.shared.b16 {%0,%1,%2,%3}, [%4];"
                 : "=r"(r[0]), "=r"(r[1]), "=r"(r[2]), "=r"(r[3]) : "r"(addr));
}
__device__ __forceinline__ void mma_bf16(float* c, const uint32_t* a, const uint32_t* b) {
    asm volatile("mma.sync.aligned.m16n8k16.row.col.f32.bf16.bf16.f32 "
                 "{%0,%1,%2,%3}, {%4,%5,%6,%7}, {%8,%9}, {%0,%1,%2,%3};"
                 : "+f"(c[0]), "+f"(c[1]), "+f"(c[2]), "+f"(c[3])
                 : "r"(a[0]), "r"(a[1]), "r"(a[2]), "r"(a[3]), "r"(b[0]), "r"(b[1]));
}
__device__ __forceinline__ uint32_t swz(uint32_t row, uint32_t cb) {
    return row * 128u + (cb ^ ((row & 7u) << 4));
}

enum { F_BIAS = 1, F_LRELU = 2, F_RES = 4, F_LRELUA = 8, F_SNODE = 16 };

// -------- CSR build kernels --------
__global__ void seg_count(const int* __restrict__ idx, int* __restrict__ cnt, int n)
{
    int e = blockIdx.x * blockDim.x + threadIdx.x;
    if (e < n) atomicAdd(&cnt[idx[e]], 1);
}
__global__ void scan_block1024(const int* __restrict__ cnt, int* __restrict__ off,
                               int* __restrict__ bsum, int nseg)
{
    __shared__ int sh[1024];
    int g = blockIdx.x * 1024 + threadIdx.x;
    int v = (g < nseg) ? cnt[g] : 0;
    sh[threadIdx.x] = v;
    __syncthreads();
#pragma unroll
    for (int o = 1; o < 1024; o <<= 1) {
        int t = (threadIdx.x >= o) ? sh[threadIdx.x - o] : 0;
        __syncthreads();
        sh[threadIdx.x] += t;
        __syncthreads();
    }
    if (g < nseg) off[g] = sh[threadIdx.x] - v;   // exclusive
    if (threadIdx.x == 1023) bsum[blockIdx.x] = sh[1023];
}
__global__ void scan_small(int* bsum, int nb)
{
    if (threadIdx.x == 0) {
        int run = 0;
        for (int i = 0; i < nb; i++) { int t = bsum[i]; bsum[i] = run; run += t; }
    }
}
__global__ void add_off(int* __restrict__ off, const int* __restrict__ bsum, int nseg)
{
    int g = blockIdx.x * blockDim.x + threadIdx.x;
    if (g < nseg) off[g] += bsum[g >> 10];
}
__global__ void fill_perm(const int* __restrict__ idx, const int* __restrict__ off,
                          int* __restrict__ cur, int* __restrict__ perm, int n)
{
    int e = blockIdx.x * blockDim.x + threadIdx.x;
    if (e >= n) return;
    int s = idx[e];
    int pos = off[s] + atomicAdd(&cur[s], 1);
    perm[pos] = e;
}

// -------- weight prep --------
__global__ void prep_w(const float* W0, const float* W1, const float* W2,
                       const float* W3, const float* W4, const float* W5)
{
    const float* Ws[6] = {W0, W1, W2, W3, W4, W5};
    const float* W = Ws[blockIdx.y];
    unsigned char* base = g_Wprep + (size_t)blockIdx.y * 262144;
    int g = blockIdx.x * 256 + threadIdx.x;
    int n = g >> 5, kg = g & 31, k0 = kg * 8;
    unsigned short hi[8], lo[8];
#pragma unroll
    for (int i = 0; i < 8; i++) {
        float x = W[(size_t)(k0 + i) * DD + n];
        __nv_bfloat16 h = __float2bfloat16(x);
        __nv_bfloat16 l = __float2bfloat16(x - __bfloat162float(h));
        hi[i] = *reinterpret_cast<unsigned short*>(&h);
        lo[i] = *reinterpret_cast<unsigned short*>(&l);
    }
    int chunk = k0 >> 6, kc = k0 & 63;
    uint32_t off = (uint32_t)n * 128u + (((uint32_t)kc * 2u) ^ (((uint32_t)n & 7u) << 4));
    *reinterpret_cast<uint4*>(base + (size_t)(chunk * 2 + 0) * 32768 + off) =
        *reinterpret_cast<uint4*>(hi);
    *reinterpret_cast<uint4*>(base + (size_t)(chunk * 2 + 1) * 32768 + off) =
        *reinterpret_cast<uint4*>(lo);
}

// -------- tensor-core GEMM via mma.sync --------
static const int SMEM_SZ = 65536;

template <int FLAGS>
__global__ __launch_bounds__(256, 2)
void tgemm256(const float* __restrict__ A, const unsigned char* __restrict__ Wp,
              const float* __restrict__ bias, const float* __restrict__ R,
              const float* __restrict__ av, float* __restrict__ C,
              float* __restrict__ snode, int Mrows)
{
    extern __shared__ __align__(128) unsigned char smem[];
    const uint32_t sb = smem_to_u32(smem);
    const int tid = threadIdx.x, lane = tid & 31, wid = tid >> 5;
    const int warpM = wid >> 1, warpN = wid & 1;
    const int rowBase = blockIdx.y * 128, colBase = blockIdx.x * 128;

    float c[2][8][4];
#pragma unroll
    for (int mt = 0; mt < 2; mt++)
#pragma unroll
        for (int nt = 0; nt < 8; nt++)
#pragma unroll
            for (int q = 0; q < 4; q++) c[mt][nt][q] = 0.f;

    for (int ch = 0; ch < 4; ch++) {
#pragma unroll
        for (int i = 0; i < 4; i++) {
            int g = tid + i * 256;
            int r = g >> 3, cg = g & 7;
            int row = rowBase + r;
            float x[8];
            if (row < Mrows) {
                const float4* src = reinterpret_cast<const float4*>(
                    A + (size_t)row * DD + ch * 64 + cg * 8);
                float4 v0 = src[0], v1 = src[1];
                x[0] = v0.x; x[1] = v0.y; x[2] = v0.z; x[3] = v0.w;
                x[4] = v1.x; x[5] = v1.y; x[6] = v1.z; x[7] = v1.w;
            } else {
#pragma unroll
                for (int j = 0; j < 8; j++) x[j] = 0.f;
            }
            unsigned short hi[8], lo[8];
#pragma unroll
            for (int j = 0; j < 8; j++) {
                if (FLAGS & F_LRELUA) x[j] = lrelu_f(x[j]);
                __nv_bfloat16 h = __float2bfloat16(x[j]);
                __nv_bfloat16 l = __float2bfloat16(x[j] - __bfloat162float(h));
                hi[j] = *reinterpret_cast<unsigned short*>(&h);
                lo[j] = *reinterpret_cast<unsigned short*>(&l);
            }
            uint32_t off = swz((uint32_t)r, (uint32_t)cg * 16u);
            *reinterpret_cast<uint4*>(smem + off)         = *reinterpret_cast<uint4*>(hi);
            *reinterpret_cast<uint4*>(smem + 16384 + off) = *reinterpret_cast<uint4*>(lo);
        }
        {
            const uint4* bh = reinterpret_cast<const uint4*>(
                Wp + (size_t)(ch * 2 + 0) * 32768 + (size_t)colBase * 128);
            const uint4* bl = reinterpret_cast<const uint4*>(
                Wp + (size_t)(ch * 2 + 1) * 32768 + (size_t)colBase * 128);
            uint4* sh = reinterpret_cast<uint4*>(smem + 32768);
            uint4* sl = reinterpret_cast<uint4*>(smem + 49152);
#pragma unroll
            for (int i = 0; i < 4; i++) {
                int idx = tid + i * 256;
                sh[idx] = bh[idx];
                sl[idx] = bl[idx];
            }
        }
        __syncthreads();

#pragma unroll
        for (int ks = 0; ks < 4; ks++) {
            uint32_t ah[2][4], al[2][4];
#pragma unroll
            for (int mt = 0; mt < 2; mt++) {
                uint32_t row = (uint32_t)(warpM * 32 + mt * 16 + (lane & 7) + ((lane >> 3) & 1) * 8);
                uint32_t kb  = (uint32_t)(ks * 32 + ((lane >> 4) & 1) * 16);
                uint32_t addr = sb + swz(row, kb);
                ldm_x4(addr,         ah[mt]);
                ldm_x4(addr + 16384, al[mt]);
            }
#pragma unroll
            for (int p = 0; p < 4; p++) {
                uint32_t nrow = (uint32_t)(warpN * 64 + p * 16 + (lane & 7) + ((lane >> 4) & 1) * 8);
                uint32_t kb   = (uint32_t)(ks * 32 + ((lane >> 3) & 1) * 16);
                uint32_t addr = sb + 32768 + swz(nrow, kb);
                uint32_t bh[4], bl[4];
                ldm_x4(addr,         bh);
                ldm_x4(addr + 16384, bl);
#pragma unroll
                for (int s = 0; s < 2; s++) {
                    const uint32_t* Bh = bh + s * 2;
                    const uint32_t* Bl = bl + s * 2;
#pragma unroll
                    for (int mt = 0; mt < 2; mt++) {
                        float* cc = c[mt][p * 2 + s];
                        mma_bf16(cc, ah[mt], Bh);
                        mma_bf16(cc, ah[mt], Bl);
                        mma_bf16(cc, al[mt], Bh);
                    }
                }
            }
        }
        __syncthreads();
    }

    const int gid = lane >> 2, tig = lane & 3;
#pragma unroll
    for (int mt = 0; mt < 2; mt++) {
        int r0 = rowBase + warpM * 32 + mt * 16 + gid;
        int r1 = r0 + 8;
        bool v0 = r0 < Mrows, v1 = r1 < Mrows;
        float s0 = 0.f, s1 = 0.f;
#pragma unroll
        for (int nt = 0; nt < 8; nt++) {
            int col = colBase + warpN * 64 + nt * 8 + tig * 2;
            float o0 = c[mt][nt][0], o1 = c[mt][nt][1];
            float o2 = c[mt][nt][2], o3 = c[mt][nt][3];
            if (FLAGS & F_BIAS) {
                float2 bv = *reinterpret_cast<const float2*>(bias + col);
                o0 += bv.x; o1 += bv.y; o2 += bv.x; o3 += bv.y;
            }
            if (FLAGS & F_LRELU) {
                o0 = lrelu_f(o0); o1 = lrelu_f(o1); o2 = lrelu_f(o2); o3 = lrelu_f(o3);
            }
            if (FLAGS & F_RES) {
                if (v0) {
                    float2 rv = *reinterpret_cast<const float2*>(R + (size_t)r0 * DD + col);
                    o0 += rv.x; o1 += rv.y;
                }
                if (v1) {
                    float2 rv = *reinterpret_cast<const float2*>(R + (size_t)r1 * DD + col);
                    o2 += rv.x; o3 += rv.y;
                }
            }
            if (FLAGS & F_SNODE) {
                float2 avv = *reinterpret_cast<const float2*>(av + col);
                s0 += o0 * avv.x + o1 * avv.y;
                s1 += o2 * avv.x + o3 * avv.y;
            }
            if (v0) *reinterpret_cast<float2*>(C + (size_t)r0 * DD + col) = make_float2(o0, o1);
            if (v1) *reinterpret_cast<float2*>(C + (size_t)r1 * DD + col) = make_float2(o2, o3);
        }
        if (FLAGS & F_SNODE) {
#pragma unroll
            for (int o = 1; o < 4; o <<= 1) {
                s0 += __shfl_xor_sync(0xFFFFFFFFu, s0, o);
                s1 += __shfl_xor_sync(0xFFFFFFFFu, s1, o);
            }
            if (tig == 0) {
                if (v0) atomicAdd(snode + r0, s0);
                if (v1) atomicAdd(snode + r1, s1);
            }
        }
    }
}

// -------- LayerNorm --------
__global__ void ln_rows(const float* __restrict__ in, const float* __restrict__ g,
                        const float* __restrict__ b, float* __restrict__ out, int rows)
{
    int row = blockIdx.x * 8 + (threadIdx.x >> 5);
    if (row >= rows) return;
    int lane = threadIdx.x & 31;
    const float4* rp = reinterpret_cast<const float4*>(in + (size_t)row * DD);
    float4 v0 = rp[lane], v1 = rp[lane + 32];
    float s = v0.x + v0.y + v0.z + v0.w + v1.x + v1.y + v1.z + v1.w;
    float q = v0.x*v0.x + v0.y*v0.y + v0.z*v0.z + v0.w*v0.w
            + v1.x*v1.x + v1.y*v1.y + v1.z*v1.z + v1.w*v1.w;
#pragma unroll
    for (int o = 16; o; o >>= 1) {
        s += __shfl_xor_sync(0xFFFFFFFFu, s, o);
        q += __shfl_xor_sync(0xFFFFFFFFu, q, o);
    }
    float mean = s * (1.f / 256.f);
    float var  = q * (1.f / 256.f) - mean * mean;
    float rstd = rsqrtf(var + 1e-5f);
    const float4* gp = reinterpret_cast<const float4*>(g);
    const float4* bp = reinterpret_cast<const float4*>(b);
    float4 g0 = gp[lane], g1 = gp[lane + 32], b0 = bp[lane], b1 = bp[lane + 32];
    float4 o0, o1;
    o0.x = (v0.x - mean) * rstd * g0.x + b0.x;
    o0.y = (v0.y - mean) * rstd * g0.y + b0.y;
    o0.z = (v0.z - mean) * rstd * g0.z + b0.z;
    o0.w = (v0.w - mean) * rstd * g0.w + b0.w;
    o1.x = (v1.x - mean) * rstd * g1.x + b1.x;
    o1.y = (v1.y - mean) * rstd * g1.y + b1.y;
    o1.z = (v1.z - mean) * rstd * g1.z + b1.z;
    o1.w = (v1.w - mean) * rstd * g1.w + b1.w;
    float4* op = reinterpret_cast<float4*>(out + (size_t)row * DD);
    op[lane] = o0; op[lane + 32] = o1;
}

// -------- edge gather: ef[ed]=mean of M rows; sedge=ef.a2 (warp/edge) --------
__global__ void edge_gather(const float* __restrict__ M, const int* __restrict__ hn,
                            const int* __restrict__ permE, const int* __restrict__ offE,
                            const int* __restrict__ cntE, const float* __restrict__ a2,
                            float* __restrict__ ef, float* __restrict__ sedge, int nEdges)
{
    int ed = blockIdx.x * 8 + (threadIdx.x >> 5);
    if (ed >= nEdges) return;
    int lane = threadIdx.x & 31;
    int start = offE[ed], deg = cntE[ed];
    float4 a0 = make_float4(0.f,0.f,0.f,0.f), a1 = a0;
    for (int base = 0; base < deg; base += 32) {
        int m = min(32, deg - base);
        int src = 0;
        if (lane < m) src = hn[permE[start + base + lane]];
        for (int i = 0; i < m; i++) {
            int node = __shfl_sync(0xFFFFFFFFu, src, i);
            const float4* rp = reinterpret_cast<const float4*>(M + (size_t)node * DD + lane * 8);
            float4 v0 = rp[0], v1 = rp[1];
            a0.x += v0.x; a0.y += v0.y; a0.z += v0.z; a0.w += v0.w;
            a1.x += v1.x; a1.y += v1.y; a1.z += v1.z; a1.w += v1.w;
        }
    }
    float inv = 1.f / fmaxf((float)deg, 1.f);
    a0.x *= inv; a0.y *= inv; a0.z *= inv; a0.w *= inv;
    a1.x *= inv; a1.y *= inv; a1.z *= inv; a1.w *= inv;
    float4* op = reinterpret_cast<float4*>(ef + (size_t)ed * DD + lane * 8);
    op[0] = a0; op[1] = a1;
    const float4* ap = reinterpret_cast<const float4*>(a2 + lane * 8);
    float4 c0 = ap[0], c1 = ap[1];
    float d = a0.x*c0.x + a0.y*c0.y + a0.z*c0.z + a0.w*c0.w
            + a1.x*c1.x + a1.y*c1.y + a1.z*c1.z + a1.w*c1.w;
#pragma unroll
    for (int o = 16; o; o >>= 1) d += __shfl_xor_sync(0xFFFFFFFFu, d, o);
    if (lane == 0) sedge[ed] = d;
}

// -------- per-node softmax over incidences (thread/node) --------
__global__ void node_softmax(const float* __restrict__ sn, const float* __restrict__ se,
                             const int* __restrict__ he, const int* __restrict__ permN,
                             const int* __restrict__ offN, const int* __restrict__ cntN,
                             float* __restrict__ attn, int nNodes)
{
    int n = blockIdx.x * blockDim.x + threadIdx.x;
    if (n >= nNodes) return;
    int st = offN[n], deg = cntN[n];
    if (deg == 0) return;
    float s0 = sn[n];
    float mx = -3.4e38f;
    for (int i = 0; i < deg; i++) {
        int inc = permN[st + i];
        float sc = lrelu_f(s0 + se[he[inc]]);
        mx = fmaxf(mx, sc);
    }
    float z = 0.f;
    for (int i = 0; i < deg; i++) {
        int inc = permN[st + i];
        float sc = lrelu_f(s0 + se[he[inc]]);
        float e = expf(sc - mx);
        attn[inc] = e;
        z += e;
    }
    float inv = 1.f / fmaxf(z, 1e-9f);
    for (int i = 0; i < deg; i++) {
        int inc = permN[st + i];
        attn[inc] *= inv;
    }
}

// -------- node aggregate: out[n] = (lrelu?) sum attn*ef[edge]  (warp/node) --------
__global__ void node_aggregate(const float* __restrict__ ef, const int* __restrict__ he,
                               const int* __restrict__ permN, const int* __restrict__ offN,
                               const int* __restrict__ cntN, const float* __restrict__ attn,
                               float* __restrict__ out, int doLrelu, int nNodes)
{
    int n = blockIdx.x * 8 + (threadIdx.x >> 5);
    if (n >= nNodes) return;
    int lane = threadIdx.x & 31;
    int start = offN[n], deg = cntN[n];
    float4 a0 = make_float4(0.f,0.f,0.f,0.f), a1 = a0;
    for (int base = 0; base < deg; base += 32) {
        int m = min(32, deg - base);
        int ed = 0; float w = 0.f;
        if (lane < m) {
            int inc = permN[start + base + lane];
            ed = he[inc];
            w = attn[inc];
        }
        for (int i = 0; i < m; i++) {
            int e_  = __shfl_sync(0xFFFFFFFFu, ed, i);
            float w_ = __shfl_sync(0xFFFFFFFFu, w, i);
            const float4* rp = reinterpret_cast<const float4*>(ef + (size_t)e_ * DD + lane * 8);
            float4 v0 = rp[0], v1 = rp[1];
            a0.x += w_*v0.x; a0.y += w_*v0.y; a0.z += w_*v0.z; a0.w += w_*v0.w;
            a1.x += w_*v1.x; a1.y += w_*v1.y; a1.z += w_*v1.z; a1.w += w_*v1.w;
        }
    }
    if (doLrelu) {
        a0.x = lrelu_f(a0.x); a0.y = lrelu_f(a0.y); a0.z = lrelu_f(a0.z); a0.w = lrelu_f(a0.w);
        a1.x = lrelu_f(a1.x); a1.y = lrelu_f(a1.y); a1.z = lrelu_f(a1.z); a1.w = lrelu_f(a1.w);
    }
    float4* op = reinterpret_cast<float4*>(out + (size_t)n * DD + lane * 8);
    op[0] = a0; op[1] = a1;
}

// -------- object message gather: msg[o] = sum ev[oe_ev[inc]]  (warp/object) --------
__global__ void obj_gather(const float* __restrict__ ev, const int* __restrict__ oe_ev,
                           const int* __restrict__ permO, const int* __restrict__ offO,
                           const int* __restrict__ cntO, float* __restrict__ msg, int nObj)
{
    int o = blockIdx.x * 8 + (threadIdx.x >> 5);
    if (o >= nObj) return;
    int lane = threadIdx.x & 31;
    int start = offO[o], deg = cntO[o];
    float4 a0 = make_float4(0.f,0.f,0.f,0.f), a1 = a0;
    for (int base = 0; base < deg; base += 32) {
        int m = min(32, deg - base);
        int src = 0;
        if (lane < m) src = oe_ev[permO[start + base + lane]];
        for (int i = 0; i < m; i++) {
            int row = __shfl_sync(0xFFFFFFFFu, src, i);
            const float4* rp = reinterpret_cast<const float4*>(ev + (size_t)row * DD + lane * 8);
            float4 v0 = rp[0], v1 = rp[1];
            a0.x += v0.x; a0.y += v0.y; a0.z += v0.z; a0.w += v0.w;
            a1.x += v1.x; a1.y += v1.y; a1.z += v1.z; a1.w += v1.w;
        }
    }
    float4* op = reinterpret_cast<float4*>(msg + (size_t)o * DD + lane * 8);
    op[0] = a0; op[1] = a1;
}

// ----------------- host orchestration -----------------
struct Ptrs {
    float *X, *obj, *msg, *tmp, *M, *H, *ef, *snode, *sedge, *ew;
    unsigned char* wp;
    int *cntE, *offE, *permE, *cntN, *offN, *permN, *cntO, *offO, *permO, *cur, *bsum;
};

static void get_ptrs(Ptrs& p) {
    cudaGetSymbolAddress((void**)&p.X,     g_X);
    cudaGetSymbolAddress((void**)&p.obj,   g_obj);
    cudaGetSymbolAddress((void**)&p.msg,   g_msg);
    cudaGetSymbolAddress((void**)&p.tmp,   g_tmp);
    cudaGetSymbolAddress((void**)&p.M,     g_M);
    cudaGetSymbolAddress((void**)&p.H,     g_H);
    cudaGetSymbolAddress((void**)&p.ef,    g_ef);
    cudaGetSymbolAddress((void**)&p.snode, g_snode);
    cudaGetSymbolAddress((void**)&p.sedge, g_sedge);
    cudaGetSymbolAddress((void**)&p.ew,    g_ew);
    cudaGetSymbolAddress((void**)&p.wp,    g_Wprep);
    cudaGetSymbolAddress((void**)&p.cntE,  g_cntE);
    cudaGetSymbolAddress((void**)&p.offE,  g_offE);
    cudaGetSymbolAddress((void**)&p.permE, g_permE);
    cudaGetSymbolAddress((void**)&p.cntN,  g_cntN);
    cudaGetSymbolAddress((void**)&p.offN,  g_offN);
    cudaGetSymbolAddress((void**)&p.permN, g_permN);
    cudaGetSymbolAddress((void**)&p.cntO,  g_cntO);
    cudaGetSymbolAddress((void**)&p.offO,  g_offO);
    cudaGetSymbolAddress((void**)&p.permO, g_permO);
    cudaGetSymbolAddress((void**)&p.cur,   g_cur);
    cudaGetSymbolAddress((void**)&p.bsum,  g_bsum);
}

static void build_csr(const int* idx, int n, int nseg,
                      int* cnt, int* off, int* perm, int* cur, int* bsum)
{
    cudaMemsetAsync(cnt, 0, (size_t)nseg * sizeof(int));
    seg_count<<<(n + 255) / 256, 256>>>(idx, cnt, n);
    int nb = (nseg + 1023) / 1024;
    scan_block1024<<<nb, 1024>>>(cnt, off, bsum, nseg);
    scan_small<<<1, 32>>>(bsum, nb);
    add_off<<<(nseg + 255) / 256, 256>>>(off, bsum, nseg);
    cudaMemsetAsync(cur, 0, (size_t)nseg * sizeof(int));
    fill_perm<<<(n + 255) / 256, 256>>>(idx, off, cur, perm, n);
}

template <int FLAGS>
static void launch_tgemm(const float* A, const unsigned char* Wp, const float* bias,
                         const float* R, const float* av, float* C, float* snode, int Mrows)
{
    cudaFuncSetAttribute(tgemm256<FLAGS>, cudaFuncAttributeMaxDynamicSharedMemorySize, SMEM_SZ);
    dim3 g(2, (Mrows + 127) / 128);
    tgemm256<FLAGS><<<g, 256, SMEM_SZ>>>(A, Wp, bias, R, av, C, snode, Mrows);
}

static void hgnn_layer(const Ptrs& p, const float* Xin, const unsigned char* Wp, const float* a,
                       const int* hg_node, const int* hg_edge,
                       float* outbuf, float* attnOut, bool lreluA, bool lreluOut)
{
    cudaMemsetAsync(p.snode, 0, NN * sizeof(float));
    if (lreluA) launch_tgemm<F_SNODE | F_LRELUA>(Xin, Wp, nullptr, nullptr, a, p.M, p.snode, NN);
    else        launch_tgemm<F_SNODE>           (Xin, Wp, nullptr, nullptr, a, p.M, p.snode, NN);
    edge_gather<<<(NE + 7) / 8, 256>>>(p.M, hg_node, p.permE, p.offE, p.cntE,
                                       a + DD, p.ef, p.sedge, NE);
    node_softmax<<<(NN + 255) / 256, 256>>>(p.snode, p.sedge, hg_edge, p.permN,
                                            p.offN, p.cntN, attnOut, NN);
    node_aggregate<<<(NN + 7) / 8, 256>>>(p.ef, hg_edge, p.permN, p.offN, p.cntN,
                                          attnOut, outbuf, lreluOut ? 1 : 0, NN);
}

extern "C" void kernel_launch(void* const* d_in, const int* in_sizes, int n_in,
                              void* d_out, int out_size)
{
    const float* object_X = (const float*)d_in[0];
    const float* event_X  = (const float*)d_in[1];
    const float* Wo = (const float*)d_in[2];  const float* bo  = (const float*)d_in[3];
    const float* go = (const float*)d_in[4];  const float* bon = (const float*)d_in[5];
    const float* We = (const float*)d_in[6];  const float* be  = (const float*)d_in[7];
    const float* ge = (const float*)d_in[8];  const float* ben = (const float*)d_in[9];
    const float* Wu = (const float*)d_in[10]; const float* bu  = (const float*)d_in[11];
    const float* Wl = (const float*)d_in[12]; const float* bl  = (const float*)d_in[13];
    const float* g1 = (const float*)d_in[14]; const float* b1  = (const float*)d_in[15];
    const float* g2 = (const float*)d_in[16]; const float* b2  = (const float*)d_in[17];
    const float* Wh1 = (const float*)d_in[18]; const float* ah1 = (const float*)d_in[19];
    const float* Wh2 = (const float*)d_in[20]; const float* ah2 = (const float*)d_in[21];
    const int* oe_ev   = (const int*)d_in[22];
    const int* oe_obj  = (const int*)d_in[23];
    const int* hg_node = (const int*)d_in[24];
    const int* hg_edge = (const int*)d_in[25];

    Ptrs p; get_ptrs(p);

    // 0) weight prep + CSR builds (indices fixed per launch)
    prep_w<<<dim3(32, 6), 256>>>(We, Wo, Wu, Wl, Wh1, Wh2);
    build_csr(hg_edge, E2N, NE, p.cntE, p.offE, p.permE, p.cur, p.bsum);
    build_csr(hg_node, E2N, NN, p.cntN, p.offN, p.permN, p.cur, p.bsum);
    build_csr(oe_obj,  E1N, NO, p.cntO, p.offO, p.permO, p.cur, p.bsum);
    const unsigned char *wpe = p.wp, *wpo = p.wp + 262144, *wpu = p.wp + 2 * 262144,
                        *wpl = p.wp + 3 * 262144, *wph1 = p.wp + 4 * 262144,
                        *wph2 = p.wp + 5 * 262144;

    // 1) ev = LN(lrelu(event_X @ We + be)) -> X[0:NE)
    launch_tgemm<F_BIAS | F_LRELU>(event_X, wpe, be, nullptr, nullptr, p.tmp, nullptr, NE);
    ln_rows<<<(NE + 7) / 8, 256>>>(p.tmp, ge, ben, p.X, NE);

    // 2) obj = LN(lrelu(object_X @ Wo + bo))
    launch_tgemm<F_BIAS | F_LRELU>(object_X, wpo, bo, nullptr, nullptr, p.tmp, nullptr, NO);
    ln_rows<<<(NO + 7) / 8, 256>>>(p.tmp, go, bon, p.obj, NO);

    // 3) msg = segment_sum(ev[oe_ev], oe_obj)  (gather via obj-CSR)
    obj_gather<<<(NO + 7) / 8, 256>>>(p.X, oe_ev, p.permO, p.offO, p.cntO, p.msg, NO);

    // 4) obj1 = LN(lrelu(msg @ Wu + bu) + obj)
    launch_tgemm<F_BIAS | F_LRELU | F_RES>(p.msg, wpu, bu, p.obj, nullptr, p.tmp, nullptr, NO);
    ln_rows<<<(NO + 7) / 8, 256>>>(p.tmp, g1, b1, p.obj, NO);

    // 5) obj2 = LN(lrelu(obj1 @ Wl + bl) + obj1) -> X[NE:NN)
    launch_tgemm<F_BIAS | F_LRELU | F_RES>(p.obj, wpl, bl, p.obj, nullptr, p.tmp, nullptr, NO);
    ln_rows<<<(NO + 7) / 8, 256>>>(p.tmp, g2, b2, p.X + (size_t)NE * DD, NO);

    // 6) HGNN layer 1 -> H (pre-lrelu; lrelu fused into layer-2 GEMM A-load)
    hgnn_layer(p, p.X, wph1, ah1, hg_node, hg_edge, p.H, p.ew, false, false);

    // 7) HGNN layer 2 -> d_out (h with lrelu fused, then attn)
    float* out = (float*)d_out;
    hgnn_layer(p, p.H, wph2, ah2, hg_node, hg_edge, out, out + (size_t)NN * DD, true, true);
}

// round 5
// speedup vs baseline: 2.0262x; 1.0076x over previous
#include <cuda_runtime.h>
#include <cuda_bf16.h>
#include <cstdint>

#define DD 256
static const int NE  = 50000;
static const int NO  = 100000;
static const int NN  = 150000;
static const int E1N = 400000;
static const int E2N = 800000;

// -------- device scratch --------
__device__ float    g_X  [(size_t)NN * DD];
__device__ float    g_obj[(size_t)NO * DD];
__device__ float    g_msg[(size_t)NO * DD];
__device__ float    g_M  [(size_t)NN * DD];
__device__ float    g_H  [(size_t)NN * DD];
__device__ float    g_ef [(size_t)NE * DD];
__device__ float    g_snode[NN];
__device__ float    g_sedge[NE];
__device__ float    g_ew[E2N];
__device__ unsigned char g_Wprep[6 * 4 * 2 * 256 * 128];
// CSR structures
__device__ int g_cntE[NE],  g_offE[NE],  g_permE[E2N];
__device__ int g_cntN[NN],  g_offN[NN],  g_permN[E2N];
__device__ int g_cntO[NO],  g_offO[NO],  g_permO[E1N];
__device__ int g_cur[NN];
__device__ int g_bsum[256];

// -------- helpers --------
__device__ __forceinline__ float lrelu_f(float x) { return x >= 0.f ? x : 0.2f * x; }

__device__ __forceinline__ uint32_t smem_to_u32(const void* p) {
    uint32_t a;
    asm("{ .reg .u64 t; cvta.to.shared.u64 t, %1; cvt.u32.u64 %0, t; }" : "=r"(a) : "l"(p));
    return a;
}
__device__ __forceinline__ void ldm_x4(uint32_t addr, uint32_t* r) {
    asm volatile("ldmatrix.sync.aligned.m8n8.x4.shared.b16 {%0,%1,%2,%3}, [%4];"
                 : "=r"(r[0]), "=r"(r[1]), "=r"(r[2]), "=r"(r[3]) : "r"(addr));
}
__device__ __forceinline__ void mma_bf16(float* c, const uint32_t* a, const uint32_t* b) {
    asm volatile("mma.sync.aligned.m16n8k16.row.col.f32.bf16.bf16.f32 "
                 "{%0,%1,%2,%3}, {%4,%5,%6,%7}, {%8,%9}, {%0,%1,%2,%3};"
                 : "+f"(c[0]), "+f"(c[1]), "+f"(c[2]), "+f"(c[3])
                 : "r"(a[0]), "r"(a[1]), "r"(a[2]), "r"(a[3]), "r"(b[0]), "r"(b[1]));
}
__device__ __forceinline__ uint32_t swz(uint32_t row, uint32_t cb) {
    return row * 128u + (cb ^ ((row & 7u) << 4));
}

enum { F_BIAS = 1, F_LRELU = 2, F_RES = 4, F_LRELUA = 8, F_SNODE = 16, F_LN = 32 };

// -------- CSR build kernels --------
__global__ void seg_count(const int* __restrict__ idx, int* __restrict__ cnt, int n)
{
    int e = blockIdx.x * blockDim.x + threadIdx.x;
    if (e < n) atomicAdd(&cnt[idx[e]], 1);
}
__global__ void scan_block1024(const int* __restrict__ cnt, int* __restrict__ off,
                               int* __restrict__ bsum, int nseg)
{
    __shared__ int sh[1024];
    int g = blockIdx.x * 1024 + threadIdx.x;
    int v = (g < nseg) ? cnt[g] : 0;
    sh[threadIdx.x] = v;
    __syncthreads();
#pragma unroll
    for (int o = 1; o < 1024; o <<= 1) {
        int t = (threadIdx.x >= o) ? sh[threadIdx.x - o] : 0;
        __syncthreads();
        sh[threadIdx.x] += t;
        __syncthreads();
    }
    if (g < nseg) off[g] = sh[threadIdx.x] - v;
    if (threadIdx.x == 1023) bsum[blockIdx.x] = sh[1023];
}
__global__ void scan_small(int* bsum, int nb)
{
    if (threadIdx.x == 0) {
        int run = 0;
        for (int i = 0; i < nb; i++) { int t = bsum[i]; bsum[i] = run; run += t; }
    }
}
__global__ void add_off(int* __restrict__ off, const int* __restrict__ bsum, int nseg)
{
    int g = blockIdx.x * blockDim.x + threadIdx.x;
    if (g < nseg) off[g] += bsum[g >> 10];
}
__global__ void fill_perm(const int* __restrict__ idx, const int* __restrict__ off,
                          int* __restrict__ cur, int* __restrict__ perm, int n)
{
    int e = blockIdx.x * blockDim.x + threadIdx.x;
    if (e >= n) return;
    int s = idx[e];
    int pos = off[s] + atomicAdd(&cur[s], 1);
    perm[pos] = e;
}

// -------- weight prep --------
__global__ void prep_w(const float* W0, const float* W1, const float* W2,
                       const float* W3, const float* W4, const float* W5)
{
    const float* Ws[6] = {W0, W1, W2, W3, W4, W5};
    const float* W = Ws[blockIdx.y];
    unsigned char* base = g_Wprep + (size_t)blockIdx.y * 262144;
    int g = blockIdx.x * 256 + threadIdx.x;
    int n = g >> 5, kg = g & 31, k0 = kg * 8;
    unsigned short hi[8], lo[8];
#pragma unroll
    for (int i = 0; i < 8; i++) {
        float x = W[(size_t)(k0 + i) * DD + n];
        __nv_bfloat16 h = __float2bfloat16(x);
        __nv_bfloat16 l = __float2bfloat16(x - __bfloat162float(h));
        hi[i] = *reinterpret_cast<unsigned short*>(&h);
        lo[i] = *reinterpret_cast<unsigned short*>(&l);
    }
    int chunk = k0 >> 6, kc = k0 & 63;
    uint32_t off = (uint32_t)n * 128u + (((uint32_t)kc * 2u) ^ (((uint32_t)n & 7u) << 4));
    *reinterpret_cast<uint4*>(base + (size_t)(chunk * 2 + 0) * 32768 + off) =
        *reinterpret_cast<uint4*>(hi);
    *reinterpret_cast<uint4*>(base + (size_t)(chunk * 2 + 1) * 32768 + off) =
        *reinterpret_cast<uint4*>(lo);
}

// -------- tensor-core GEMM, tile 128x256 (full row), fused LN/snode epilogue --------
// smem: A_hi[0,16K) A_lo[16K,32K) B_hi[32K,64K) B_lo[64K,96K); reduce buf aliases A.
static const int SMEM_SZ = 98304;

template <int FLAGS>
__global__ __launch_bounds__(512, 1)
void tgemm256(const float* __restrict__ A, const unsigned char* __restrict__ Wp,
              const float* __restrict__ bias, const float* __restrict__ R,
              const float* __restrict__ av, const float* __restrict__ lng,
              const float* __restrict__ lnb, float* __restrict__ C,
              float* __restrict__ snode, int Mrows)
{
    extern __shared__ __align__(128) unsigned char smem[];
    const uint32_t sb = smem_to_u32(smem);
    const int tid = threadIdx.x, lane = tid & 31, wid = tid >> 5;
    const int warpM = wid >> 2, warpN = wid & 3;
    const int rowBase = blockIdx.x * 128;

    float c[2][8][4];
#pragma unroll
    for (int mt = 0; mt < 2; mt++)
#pragma unroll
        for (int nt = 0; nt < 8; nt++)
#pragma unroll
            for (int q = 0; q < 4; q++) c[mt][nt][q] = 0.f;

    for (int ch = 0; ch < 4; ch++) {
        // ---- A fill: 128 rows x 64 cols fp32 -> hi/lo bf16, swizzled ----
#pragma unroll
        for (int i = 0; i < 2; i++) {
            int g = tid + i * 512;            // 0..1023
            int r = g >> 3, cg = g & 7;
            int row = rowBase + r;
            float x[8];
            if (row < Mrows) {
                const float4* src = reinterpret_cast<const float4*>(
                    A + (size_t)row * DD + ch * 64 + cg * 8);
                float4 v0 = src[0], v1 = src[1];
                x[0] = v0.x; x[1] = v0.y; x[2] = v0.z; x[3] = v0.w;
                x[4] = v1.x; x[5] = v1.y; x[6] = v1.z; x[7] = v1.w;
            } else {
#pragma unroll
                for (int j = 0; j < 8; j++) x[j] = 0.f;
            }
            unsigned short hi[8], lo[8];
#pragma unroll
            for (int j = 0; j < 8; j++) {
                if (FLAGS & F_LRELUA) x[j] = lrelu_f(x[j]);
                __nv_bfloat16 h = __float2bfloat16(x[j]);
                __nv_bfloat16 l = __float2bfloat16(x[j] - __bfloat162float(h));
                hi[j] = *reinterpret_cast<unsigned short*>(&h);
                lo[j] = *reinterpret_cast<unsigned short*>(&l);
            }
            uint32_t off = swz((uint32_t)r, (uint32_t)cg * 16u);
            *reinterpret_cast<uint4*>(smem + off)         = *reinterpret_cast<uint4*>(hi);
            *reinterpret_cast<uint4*>(smem + 16384 + off) = *reinterpret_cast<uint4*>(lo);
        }
        // ---- B fill: full 256-row planes (pre-swizzled in gmem) ----
        {
            const uint4* bh = reinterpret_cast<const uint4*>(Wp + (size_t)(ch * 2 + 0) * 32768);
            const uint4* bl = reinterpret_cast<const uint4*>(Wp + (size_t)(ch * 2 + 1) * 32768);
            uint4* sh = reinterpret_cast<uint4*>(smem + 32768);
            uint4* sl = reinterpret_cast<uint4*>(smem + 65536);
#pragma unroll
            for (int i = 0; i < 4; i++) {
                int idx = tid + i * 512;      // 0..2047
                sh[idx] = bh[idx];
                sl[idx] = bl[idx];
            }
        }
        __syncthreads();

#pragma unroll
        for (int ks = 0; ks < 4; ks++) {
            uint32_t ah[2][4], al[2][4];
#pragma unroll
            for (int mt = 0; mt < 2; mt++) {
                uint32_t row = (uint32_t)(warpM * 32 + mt * 16 + (lane & 7) + ((lane >> 3) & 1) * 8);
                uint32_t kb  = (uint32_t)(ks * 32 + ((lane >> 4) & 1) * 16);
                uint32_t addr = sb + swz(row, kb);
                ldm_x4(addr,         ah[mt]);
                ldm_x4(addr + 16384, al[mt]);
            }
#pragma unroll
            for (int p = 0; p < 4; p++) {
                uint32_t nrow = (uint32_t)(warpN * 64 + p * 16 + (lane & 7) + ((lane >> 4) & 1) * 8);
                uint32_t kb   = (uint32_t)(ks * 32 + ((lane >> 3) & 1) * 16);
                uint32_t addr = sb + 32768 + swz(nrow, kb);
                uint32_t bh[4], bl[4];
                ldm_x4(addr,         bh);
                ldm_x4(addr + 32768, bl);
#pragma unroll
                for (int s = 0; s < 2; s++) {
                    const uint32_t* Bh = bh + s * 2;
                    const uint32_t* Bl = bl + s * 2;
#pragma unroll
                    for (int mt = 0; mt < 2; mt++) {
                        float* cc = c[mt][p * 2 + s];
                        mma_bf16(cc, ah[mt], Bh);
                        mma_bf16(cc, ah[mt], Bl);
                        mma_bf16(cc, al[mt], Bh);
                    }
                }
            }
        }
        __syncthreads();
    }

    // ---- epilogue ----
    const int gid = lane >> 2, tig = lane & 3;
    float2* rb = reinterpret_cast<float2*>(smem);   // [128 rows][4 warpN] partials

    // transform in place (bias, lrelu, residual)
#pragma unroll
    for (int mt = 0; mt < 2; mt++) {
        int r0 = rowBase + warpM * 32 + mt * 16 + gid;
        int r1 = r0 + 8;
        bool v0 = r0 < Mrows, v1 = r1 < Mrows;
#pragma unroll
        for (int nt = 0; nt < 8; nt++) {
            int col = warpN * 64 + nt * 8 + tig * 2;
            float o0 = c[mt][nt][0], o1 = c[mt][nt][1];
            float o2 = c[mt][nt][2], o3 = c[mt][nt][3];
            if (FLAGS & F_BIAS) {
                float2 bv = *reinterpret_cast<const float2*>(bias + col);
                o0 += bv.x; o1 += bv.y; o2 += bv.x; o3 += bv.y;
            }
            if (FLAGS & F_LRELU) {
                o0 = lrelu_f(o0); o1 = lrelu_f(o1); o2 = lrelu_f(o2); o3 = lrelu_f(o3);
            }
            if (FLAGS & F_RES) {
                if (v0) {
                    float2 rv = *reinterpret_cast<const float2*>(R + (size_t)r0 * DD + col);
                    o0 += rv.x; o1 += rv.y;
                }
                if (v1) {
                    float2 rv = *reinterpret_cast<const float2*>(R + (size_t)r1 * DD + col);
                    o2 += rv.x; o3 += rv.y;
                }
            }
            c[mt][nt][0] = o0; c[mt][nt][1] = o1; c[mt][nt][2] = o2; c[mt][nt][3] = o3;
            if (!(FLAGS & F_LN)) {
                // store raw output now (snode GEMMs)
                if (v0) *reinterpret_cast<float2*>(C + (size_t)r0 * DD + col) = make_float2(o0, o1);
                if (v1) *reinterpret_cast<float2*>(C + (size_t)r1 * DD + col) = make_float2(o2, o3);
            }
        }
    }

    if (FLAGS & F_SNODE) {
#pragma unroll
        for (int mt = 0; mt < 2; mt++) {
            float s0 = 0.f, s1 = 0.f;
#pragma unroll
            for (int nt = 0; nt < 8; nt++) {
                int col = warpN * 64 + nt * 8 + tig * 2;
                float2 avv = *reinterpret_cast<const float2*>(av + col);
                s0 += c[mt][nt][0] * avv.x + c[mt][nt][1] * avv.y;
                s1 += c[mt][nt][2] * avv.x + c[mt][nt][3] * avv.y;
            }
#pragma unroll
            for (int o = 1; o < 4; o <<= 1) {
                s0 += __shfl_xor_sync(0xFFFFFFFFu, s0, o);
                s1 += __shfl_xor_sync(0xFFFFFFFFu, s1, o);
            }
            if (tig == 0) {
                int lr0 = warpM * 32 + mt * 16 + gid;
                rb[lr0 * 4 + warpN]       = make_float2(s0, 0.f);
                rb[(lr0 + 8) * 4 + warpN] = make_float2(s1, 0.f);
            }
        }
        __syncthreads();
        if (warpN == 0 && tig == 0) {
#pragma unroll
            for (int mt = 0; mt < 2; mt++) {
                int lr0 = warpM * 32 + mt * 16 + gid;
#pragma unroll
                for (int h = 0; h < 2; h++) {
                    int lr = lr0 + h * 8;
                    int row = rowBase + lr;
                    if (row < Mrows) {
                        float s = rb[lr * 4 + 0].x + rb[lr * 4 + 1].x
                                + rb[lr * 4 + 2].x + rb[lr * 4 + 3].x;
                        snode[row] = s;
                    }
                }
            }
        }
    }

    if (FLAGS & F_LN) {
        // row stats: sum + sumsq partials per warpN
#pragma unroll
        for (int mt = 0; mt < 2; mt++) {
            float s0 = 0.f, q0 = 0.f, s1 = 0.f, q1 = 0.f;
#pragma unroll
            for (int nt = 0; nt < 8; nt++) {
                float o0 = c[mt][nt][0], o1 = c[mt][nt][1];
                float o2 = c[mt][nt][2], o3 = c[mt][nt][3];
                s0 += o0 + o1; q0 += o0 * o0 + o1 * o1;
                s1 += o2 + o3; q1 += o2 * o2 + o3 * o3;
            }
#pragma unroll
            for (int o = 1; o < 4; o <<= 1) {
                s0 += __shfl_xor_sync(0xFFFFFFFFu, s0, o);
                q0 += __shfl_xor_sync(0xFFFFFFFFu, q0, o);
                s1 += __shfl_xor_sync(0xFFFFFFFFu, s1, o);
                q1 += __shfl_xor_sync(0xFFFFFFFFu, q1, o);
            }
            if (tig == 0) {
                int lr0 = warpM * 32 + mt * 16 + gid;
                rb[lr0 * 4 + warpN]       = make_float2(s0, q0);
                rb[(lr0 + 8) * 4 + warpN] = make_float2(s1, q1);
            }
        }
        __syncthreads();
#pragma unroll
        for (int mt = 0; mt < 2; mt++) {
            int lr0 = warpM * 32 + mt * 16 + gid;
            int lr1 = lr0 + 8;
            float2 p00 = rb[lr0*4+0], p01 = rb[lr0*4+1], p02 = rb[lr0*4+2], p03 = rb[lr0*4+3];
            float2 p10 = rb[lr1*4+0], p11 = rb[lr1*4+1], p12 = rb[lr1*4+2], p13 = rb[lr1*4+3];
            float sum0 = p00.x + p01.x + p02.x + p03.x;
            float sq0  = p00.y + p01.y + p02.y + p03.y;
            float sum1 = p10.x + p11.x + p12.x + p13.x;
            float sq1  = p10.y + p11.y + p12.y + p13.y;
            float mean0 = sum0 * (1.f / 256.f);
            float var0  = sq0 * (1.f / 256.f) - mean0 * mean0;
            float rstd0 = rsqrtf(var0 + 1e-5f);
            float mean1 = sum1 * (1.f / 256.f);
            float var1  = sq1 * (1.f / 256.f) - mean1 * mean1;
            float rstd1 = rsqrtf(var1 + 1e-5f);
            int r0 = rowBase + lr0, r1 = rowBase + lr1;
            bool v0 = r0 < Mrows, v1 = r1 < Mrows;
#pragma unroll
            for (int nt = 0; nt < 8; nt++) {
                int col = warpN * 64 + nt * 8 + tig * 2;
                float2 gv = *reinterpret_cast<const float2*>(lng + col);
                float2 bv = *reinterpret_cast<const float2*>(lnb + col);
                if (v0) {
                    float o0 = (c[mt][nt][0] - mean0) * rstd0 * gv.x + bv.x;
                    float o1 = (c[mt][nt][1] - mean0) * rstd0 * gv.y + bv.y;
                    *reinterpret_cast<float2*>(C + (size_t)r0 * DD + col) = make_float2(o0, o1);
                }
                if (v1) {
                    float o2 = (c[mt][nt][2] - mean1) * rstd1 * gv.x + bv.x;
                    float o3 = (c[mt][nt][3] - mean1) * rstd1 * gv.y + bv.y;
                    *reinterpret_cast<float2*>(C + (size_t)r1 * DD + col) = make_float2(o2, o3);
                }
            }
        }
    }
}

// -------- edge gather --------
__global__ void edge_gather(const float* __restrict__ M, const int* __restrict__ hn,
                            const int* __restrict__ permE, const int* __restrict__ offE,
                            const int* __restrict__ cntE, const float* __restrict__ a2,
                            float* __restrict__ ef, float* __restrict__ sedge, int nEdges)
{
    int ed = blockIdx.x * 8 + (threadIdx.x >> 5);
    if (ed >= nEdges) return;
    int lane = threadIdx.x & 31;
    int start = offE[ed], deg = cntE[ed];
    float4 a0 = make_float4(0.f,0.f,0.f,0.f), a1 = a0;
    for (int base = 0; base < deg; base += 32) {
        int m = min(32, deg - base);
        int src = 0;
        if (lane < m) src = hn[permE[start + base + lane]];
        for (int i = 0; i < m; i++) {
            int node = __shfl_sync(0xFFFFFFFFu, src, i);
            const float4* rp = reinterpret_cast<const float4*>(M + (size_t)node * DD + lane * 8);
            float4 v0 = rp[0], v1 = rp[1];
            a0.x += v0.x; a0.y += v0.y; a0.z += v0.z; a0.w += v0.w;
            a1.x += v1.x; a1.y += v1.y; a1.z += v1.z; a1.w += v1.w;
        }
    }
    float inv = 1.f / fmaxf((float)deg, 1.f);
    a0.x *= inv; a0.y *= inv; a0.z *= inv; a0.w *= inv;
    a1.x *= inv; a1.y *= inv; a1.z *= inv; a1.w *= inv;
    float4* op = reinterpret_cast<float4*>(ef + (size_t)ed * DD + lane * 8);
    op[0] = a0; op[1] = a1;
    const float4* ap = reinterpret_cast<const float4*>(a2 + lane * 8);
    float4 c0 = ap[0], c1 = ap[1];
    float d = a0.x*c0.x + a0.y*c0.y + a0.z*c0.z + a0.w*c0.w
            + a1.x*c1.x + a1.y*c1.y + a1.z*c1.z + a1.w*c1.w;
#pragma unroll
    for (int o = 16; o; o >>= 1) d += __shfl_xor_sync(0xFFFFFFFFu, d, o);
    if (lane == 0) sedge[ed] = d;
}

// -------- per-node softmax (thread/node), cached for deg<=16 --------
__global__ void node_softmax(const float* __restrict__ sn, const float* __restrict__ se,
                             const int* __restrict__ he, const int* __restrict__ permN,
                             const int* __restrict__ offN, const int* __restrict__ cntN,
                             float* __restrict__ attn, int nNodes)
{
    int n = blockIdx.x * blockDim.x + threadIdx.x;
    if (n >= nNodes) return;
    int st = offN[n], deg = cntN[n];
    if (deg == 0) return;
    float s0 = sn[n];
    if (deg <= 16) {
        int   incs[16];
        float scs[16];
        float mx = -3.4e38f;
        for (int i = 0; i < deg; i++) {
            int inc = permN[st + i];
            incs[i] = inc;
            float sc = lrelu_f(s0 + se[he[inc]]);
            scs[i] = sc;
            mx = fmaxf(mx, sc);
        }
        float z = 0.f;
        for (int i = 0; i < deg; i++) {
            float e = expf(scs[i] - mx);
            scs[i] = e;
            z += e;
        }
        float inv = 1.f / fmaxf(z, 1e-9f);
        for (int i = 0; i < deg; i++) attn[incs[i]] = scs[i] * inv;
    } else {
        float mx = -3.4e38f;
        for (int i = 0; i < deg; i++) {
            int inc = permN[st + i];
            mx = fmaxf(mx, lrelu_f(s0 + se[he[inc]]));
        }
        float z = 0.f;
        for (int i = 0; i < deg; i++) {
            int inc = permN[st + i];
            float e = expf(lrelu_f(s0 + se[he[inc]]) - mx);
            attn[inc] = e;
            z += e;
        }
        float inv = 1.f / fmaxf(z, 1e-9f);
        for (int i = 0; i < deg; i++) attn[permN[st + i]] *= inv;
    }
}

// -------- node aggregate --------
__global__ void node_aggregate(const float* __restrict__ ef, const int* __restrict__ he,
                               const int* __restrict__ permN, const int* __restrict__ offN,
                               const int* __restrict__ cntN, const float* __restrict__ attn,
                               float* __restrict__ out, int doLrelu, int nNodes)
{
    int n = blockIdx.x * 8 + (threadIdx.x >> 5);
    if (n >= nNodes) return;
    int lane = threadIdx.x & 31;
    int start = offN[n], deg = cntN[n];
    float4 a0 = make_float4(0.f,0.f,0.f,0.f), a1 = a0;
    for (int base = 0; base < deg; base += 32) {
        int m = min(32, deg - base);
        int ed = 0; float w = 0.f;
        if (lane < m) {
            int inc = permN[start + base + lane];
            ed = he[inc];
            w = attn[inc];
        }
        for (int i = 0; i < m; i++) {
            int e_  = __shfl_sync(0xFFFFFFFFu, ed, i);
            float w_ = __shfl_sync(0xFFFFFFFFu, w, i);
            const float4* rp = reinterpret_cast<const float4*>(ef + (size_t)e_ * DD + lane * 8);
            float4 v0 = rp[0], v1 = rp[1];
            a0.x += w_*v0.x; a0.y += w_*v0.y; a0.z += w_*v0.z; a0.w += w_*v0.w;
            a1.x += w_*v1.x; a1.y += w_*v1.y; a1.z += w_*v1.z; a1.w += w_*v1.w;
        }
    }
    if (doLrelu) {
        a0.x = lrelu_f(a0.x); a0.y = lrelu_f(a0.y); a0.z = lrelu_f(a0.z); a0.w = lrelu_f(a0.w);
        a1.x = lrelu_f(a1.x); a1.y = lrelu_f(a1.y); a1.z = lrelu_f(a1.z); a1.w = lrelu_f(a1.w);
    }
    float4* op = reinterpret_cast<float4*>(out + (size_t)n * DD + lane * 8);
    op[0] = a0; op[1] = a1;
}

// -------- object message gather --------
__global__ void obj_gather(const float* __restrict__ ev, const int* __restrict__ oe_ev,
                           const int* __restrict__ permO, const int* __restrict__ offO,
                           const int* __restrict__ cntO, float* __restrict__ msg, int nObj)
{
    int o = blockIdx.x * 8 + (threadIdx.x >> 5);
    if (o >= nObj) return;
    int lane = threadIdx.x & 31;
    int start = offO[o], deg = cntO[o];
    float4 a0 = make_float4(0.f,0.f,0.f,0.f), a1 = a0;
    for (int base = 0; base < deg; base += 32) {
        int m = min(32, deg - base);
        int src = 0;
        if (lane < m) src = oe_ev[permO[start + base + lane]];
        for (int i = 0; i < m; i++) {
            int row = __shfl_sync(0xFFFFFFFFu, src, i);
            const float4* rp = reinterpret_cast<const float4*>(ev + (size_t)row * DD + lane * 8);
            float4 v0 = rp[0], v1 = rp[1];
            a0.x += v0.x; a0.y += v0.y; a0.z += v0.z; a0.w += v0.w;
            a1.x += v1.x; a1.y += v1.y; a1.z += v1.z; a1.w += v1.w;
        }
    }
    float4* op = reinterpret_cast<float4*>(msg + (size_t)o * DD + lane * 8);
    op[0] = a0; op[1] = a1;
}

// ----------------- host orchestration -----------------
struct Ptrs {
    float *X, *obj, *msg, *M, *H, *ef, *snode, *sedge, *ew;
    unsigned char* wp;
    int *cntE, *offE, *permE, *cntN, *offN, *permN, *cntO, *offO, *permO, *cur, *bsum;
};

static void get_ptrs(Ptrs& p) {
    cudaGetSymbolAddress((void**)&p.X,     g_X);
    cudaGetSymbolAddress((void**)&p.obj,   g_obj);
    cudaGetSymbolAddress((void**)&p.msg,   g_msg);
    cudaGetSymbolAddress((void**)&p.M,     g_M);
    cudaGetSymbolAddress((void**)&p.H,     g_H);
    cudaGetSymbolAddress((void**)&p.ef,    g_ef);
    cudaGetSymbolAddress((void**)&p.snode, g_snode);
    cudaGetSymbolAddress((void**)&p.sedge, g_sedge);
    cudaGetSymbolAddress((void**)&p.ew,    g_ew);
    cudaGetSymbolAddress((void**)&p.wp,    g_Wprep);
    cudaGetSymbolAddress((void**)&p.cntE,  g_cntE);
    cudaGetSymbolAddress((void**)&p.offE,  g_offE);
    cudaGetSymbolAddress((void**)&p.permE, g_permE);
    cudaGetSymbolAddress((void**)&p.cntN,  g_cntN);
    cudaGetSymbolAddress((void**)&p.offN,  g_offN);
    cudaGetSymbolAddress((void**)&p.permN, g_permN);
    cudaGetSymbolAddress((void**)&p.cntO,  g_cntO);
    cudaGetSymbolAddress((void**)&p.offO,  g_offO);
    cudaGetSymbolAddress((void**)&p.permO, g_permO);
    cudaGetSymbolAddress((void**)&p.cur,   g_cur);
    cudaGetSymbolAddress((void**)&p.bsum,  g_bsum);
}

static void build_csr(const int* idx, int n, int nseg,
                      int* cnt, int* off, int* perm, int* cur, int* bsum)
{
    cudaMemsetAsync(cnt, 0, (size_t)nseg * sizeof(int));
    seg_count<<<(n + 255) / 256, 256>>>(idx, cnt, n);
    int nb = (nseg + 1023) / 1024;
    scan_block1024<<<nb, 1024>>>(cnt, off, bsum, nseg);
    scan_small<<<1, 32>>>(bsum, nb);
    add_off<<<(nseg + 255) / 256, 256>>>(off, bsum, nseg);
    cudaMemsetAsync(cur, 0, (size_t)nseg * sizeof(int));
    fill_perm<<<(n + 255) / 256, 256>>>(idx, off, cur, perm, n);
}

template <int FLAGS>
static void launch_tgemm(const float* A, const unsigned char* Wp, const float* bias,
                         const float* R, const float* av, const float* lng, const float* lnb,
                         float* C, float* snode, int Mrows)
{
    cudaFuncSetAttribute(tgemm256<FLAGS>, cudaFuncAttributeMaxDynamicSharedMemorySize, SMEM_SZ);
    tgemm256<FLAGS><<<(Mrows + 127) / 128, 512, SMEM_SZ>>>(A, Wp, bias, R, av, lng, lnb, C, snode, Mrows);
}

static void hgnn_layer(const Ptrs& p, const float* Xin, const unsigned char* Wp, const float* a,
                       const int* hg_node, const int* hg_edge,
                       float* outbuf, float* attnOut, bool lreluA, bool lreluOut)
{
    if (lreluA) launch_tgemm<F_SNODE | F_LRELUA>(Xin, Wp, nullptr, nullptr, a, nullptr, nullptr, p.M, p.snode, NN);
    else        launch_tgemm<F_SNODE>           (Xin, Wp, nullptr, nullptr, a, nullptr, nullptr, p.M, p.snode, NN);
    edge_gather<<<(NE + 7) / 8, 256>>>(p.M, hg_node, p.permE, p.offE, p.cntE,
                                       a + DD, p.ef, p.sedge, NE);
    node_softmax<<<(NN + 255) / 256, 256>>>(p.snode, p.sedge, hg_edge, p.permN,
                                            p.offN, p.cntN, attnOut, NN);
    node_aggregate<<<(NN + 7) / 8, 256>>>(p.ef, hg_edge, p.permN, p.offN, p.cntN,
                                          attnOut, outbuf, lreluOut ? 1 : 0, NN);
}

extern "C" void kernel_launch(void* const* d_in, const int* in_sizes, int n_in,
                              void* d_out, int out_size)
{
    const float* object_X = (const float*)d_in[0];
    const float* event_X  = (const float*)d_in[1];
    const float* Wo = (const float*)d_in[2];  const float* bo  = (const float*)d_in[3];
    const float* go = (const float*)d_in[4];  const float* bon = (const float*)d_in[5];
    const float* We = (const float*)d_in[6];  const float* be  = (const float*)d_in[7];
    const float* ge = (const float*)d_in[8];  const float* ben = (const float*)d_in[9];
    const float* Wu = (const float*)d_in[10]; const float* bu  = (const float*)d_in[11];
    const float* Wl = (const float*)d_in[12]; const float* bl  = (const float*)d_in[13];
    const float* g1 = (const float*)d_in[14]; const float* b1  = (const float*)d_in[15];
    const float* g2 = (const float*)d_in[16]; const float* b2  = (const float*)d_in[17];
    const float* Wh1 = (const float*)d_in[18]; const float* ah1 = (const float*)d_in[19];
    const float* Wh2 = (const float*)d_in[20]; const float* ah2 = (const float*)d_in[21];
    const int* oe_ev   = (const int*)d_in[22];
    const int* oe_obj  = (const int*)d_in[23];
    const int* hg_node = (const int*)d_in[24];
    const int* hg_edge = (const int*)d_in[25];

    Ptrs p; get_ptrs(p);

    // 0) weight prep + CSR builds
    prep_w<<<dim3(32, 6), 256>>>(We, Wo, Wu, Wl, Wh1, Wh2);
    build_csr(hg_edge, E2N, NE, p.cntE, p.offE, p.permE, p.cur, p.bsum);
    build_csr(hg_node, E2N, NN, p.cntN, p.offN, p.permN, p.cur, p.bsum);
    build_csr(oe_obj,  E1N, NO, p.cntO, p.offO, p.permO, p.cur, p.bsum);
    const unsigned char *wpe = p.wp, *wpo = p.wp + 262144, *wpu = p.wp + 2 * 262144,
                        *wpl = p.wp + 3 * 262144, *wph1 = p.wp + 4 * 262144,
                        *wph2 = p.wp + 5 * 262144;

    // 1) ev = LN(lrelu(event_X @ We + be)) -> X[0:NE)   (fully fused)
    launch_tgemm<F_BIAS | F_LRELU | F_LN>(event_X, wpe, be, nullptr, nullptr, ge, ben, p.X, nullptr, NE);

    // 2) obj = LN(lrelu(object_X @ Wo + bo))
    launch_tgemm<F_BIAS | F_LRELU | F_LN>(object_X, wpo, bo, nullptr, nullptr, go, bon, p.obj, nullptr, NO);

    // 3) msg = segment_sum(ev[oe_ev], oe_obj)
    obj_gather<<<(NO + 7) / 8, 256>>>(p.X, oe_ev, p.permO, p.offO, p.cntO, p.msg, NO);

    // 4) obj1 = LN(lrelu(msg @ Wu + bu) + obj)  (in-place safe: row-local)
    launch_tgemm<F_BIAS | F_LRELU | F_RES | F_LN>(p.msg, wpu, bu, p.obj, nullptr, g1, b1, p.obj, nullptr, NO);

    // 5) obj2 = LN(lrelu(obj1 @ Wl + bl) + obj1) -> X[NE:NN)
    launch_tgemm<F_BIAS | F_LRELU | F_RES | F_LN>(p.obj, wpl, bl, p.obj, nullptr, g2, b2, p.X + (size_t)NE * DD, nullptr, NO);

    // 6) HGNN layer 1 -> H
    hgnn_layer(p, p.X, wph1, ah1, hg_node, hg_edge, p.H, p.ew, false, false);

    // 7) HGNN layer 2 -> d_out
    float* out = (float*)d_out;
    hgnn_layer(p, p.H, wph2, ah2, hg_node, hg_edge, out, out + (size_t)NN * DD, true, true);
}

// round 6
// speedup vs baseline: 2.1815x; 1.0767x over previous
#include <cuda_runtime.h>
#include <cuda_bf16.h>
#include <cstdint>

#define DD 256
static const int NE  = 50000;
static const int NO  = 100000;
static const int NN  = 150000;
static const int E1N = 400000;
static const int E2N = 800000;

// -------- device scratch --------
__device__ float    g_X  [(size_t)NN * DD];
__device__ float    g_obj[(size_t)NO * DD];
__device__ float    g_msg[(size_t)NO * DD];
__device__ float    g_M  [(size_t)NN * DD];
__device__ float    g_H  [(size_t)NN * DD];
__device__ float    g_ef [(size_t)NE * DD];
__device__ float    g_snode[NN];
__device__ float    g_sedge[NE];
__device__ float    g_ew[E2N];
__device__ unsigned char g_Wprep[6 * 4 * 2 * 256 * 128];
// CSR structures
__device__ int g_cntE[NE],  g_offE[NE],  g_permE[E2N];
__device__ int g_cntN[NN],  g_offN[NN],  g_permN[E2N];
__device__ int g_cntO[NO],  g_offO[NO],  g_permO[E1N];
__device__ int g_cur[NN];
__device__ int g_bsum[256];

// -------- helpers --------
__device__ __forceinline__ float lrelu_f(float x) { return x >= 0.f ? x : 0.2f * x; }

__device__ __forceinline__ uint32_t smem_to_u32(const void* p) {
    uint32_t a;
    asm("{ .reg .u64 t; cvta.to.shared.u64 t, %1; cvt.u32.u64 %0, t; }" : "=r"(a) : "l"(p));
    return a;
}
__device__ __forceinline__ void ldm_x4(uint32_t addr, uint32_t* r) {
    asm volatile("ldmatrix.sync.aligned.m8n8.x4.shared.b16 {%0,%1,%2,%3}, [%4];"
                 : "=r"(r[0]), "=r"(r[1]), "=r"(r[2]), "=r"(r[3]) : "r"(addr));
}
__device__ __forceinline__ void mma_bf16(float* c, const uint32_t* a, const uint32_t* b) {
    asm volatile("mma.sync.aligned.m16n8k16.row.col.f32.bf16.bf16.f32 "
                 "{%0,%1,%2,%3}, {%4,%5,%6,%7}, {%8,%9}, {%0,%1,%2,%3};"
                 : "+f"(c[0]), "+f"(c[1]), "+f"(c[2]), "+f"(c[3])
                 : "r"(a[0]), "r"(a[1]), "r"(a[2]), "r"(a[3]), "r"(b[0]), "r"(b[1]));
}
__device__ __forceinline__ uint32_t swz(uint32_t row, uint32_t cb) {
    return row * 128u + (cb ^ ((row & 7u) << 4));
}
#define CP_ASYNC16(dst, src) \
    asm volatile("cp.async.cg.shared.global [%0], [%1], 16;" :: "r"(dst), "l"(src) : "memory")
#define CP_COMMIT() asm volatile("cp.async.commit_group;" ::: "memory")
#define CP_WAIT(n)  asm volatile("cp.async.wait_group %0;" :: "n"(n) : "memory")

enum { F_BIAS = 1, F_LRELU = 2, F_RES = 4, F_LRELUA = 8, F_SNODE = 16, F_LN = 32 };

// -------- CSR build kernels --------
__global__ void seg_count(const int* __restrict__ idx, int* __restrict__ cnt, int n)
{
    int e = blockIdx.x * blockDim.x + threadIdx.x;
    if (e < n) atomicAdd(&cnt[idx[e]], 1);
}
__global__ void scan_block1024(const int* __restrict__ cnt, int* __restrict__ off,
                               int* __restrict__ bsum, int nseg)
{
    __shared__ int sh[1024];
    int g = blockIdx.x * 1024 + threadIdx.x;
    int v = (g < nseg) ? cnt[g] : 0;
    sh[threadIdx.x] = v;
    __syncthreads();
#pragma unroll
    for (int o = 1; o < 1024; o <<= 1) {
        int t = (threadIdx.x >= o) ? sh[threadIdx.x - o] : 0;
        __syncthreads();
        sh[threadIdx.x] += t;
        __syncthreads();
    }
    if (g < nseg) off[g] = sh[threadIdx.x] - v;
    if (threadIdx.x == 1023) bsum[blockIdx.x] = sh[1023];
}
__global__ void scan_small(int* bsum, int nb)
{
    if (threadIdx.x == 0) {
        int run = 0;
        for (int i = 0; i < nb; i++) { int t = bsum[i]; bsum[i] = run; run += t; }
    }
}
__global__ void add_off(int* __restrict__ off, const int* __restrict__ bsum, int nseg)
{
    int g = blockIdx.x * blockDim.x + threadIdx.x;
    if (g < nseg) off[g] += bsum[g >> 10];
}
__global__ void fill_perm(const int* __restrict__ idx, const int* __restrict__ off,
                          int* __restrict__ cur, int* __restrict__ perm, int n)
{
    int e = blockIdx.x * blockDim.x + threadIdx.x;
    if (e >= n) return;
    int s = idx[e];
    int pos = off[s] + atomicAdd(&cur[s], 1);
    perm[pos] = e;
}

// -------- weight prep --------
__global__ void prep_w(const float* W0, const float* W1, const float* W2,
                       const float* W3, const float* W4, const float* W5)
{
    const float* Ws[6] = {W0, W1, W2, W3, W4, W5};
    const float* W = Ws[blockIdx.y];
    unsigned char* base = g_Wprep + (size_t)blockIdx.y * 262144;
    int g = blockIdx.x * 256 + threadIdx.x;
    int n = g >> 5, kg = g & 31, k0 = kg * 8;
    unsigned short hi[8], lo[8];
#pragma unroll
    for (int i = 0; i < 8; i++) {
        float x = W[(size_t)(k0 + i) * DD + n];
        __nv_bfloat16 h = __float2bfloat16(x);
        __nv_bfloat16 l = __float2bfloat16(x - __bfloat162float(h));
        hi[i] = *reinterpret_cast<unsigned short*>(&h);
        lo[i] = *reinterpret_cast<unsigned short*>(&l);
    }
    int chunk = k0 >> 6, kc = k0 & 63;
    uint32_t off = (uint32_t)n * 128u + (((uint32_t)kc * 2u) ^ (((uint32_t)n & 7u) << 4));
    *reinterpret_cast<uint4*>(base + (size_t)(chunk * 2 + 0) * 32768 + off) =
        *reinterpret_cast<uint4*>(hi);
    *reinterpret_cast<uint4*>(base + (size_t)(chunk * 2 + 1) * 32768 + off) =
        *reinterpret_cast<uint4*>(lo);
}

// -------- tensor-core GEMM, tile 128x256, double-buffered + cp.async pipeline --------
// smem: Abuf[s] hi @ s*32768, lo @ s*32768+16384   (64 KB)
//       Bbuf[s] hi @ 65536+s*65536, lo @ +32768    (128 KB)   total 192 KB
static const int SMEM_SZ = 196608;

template <int FLAGS>
__global__ __launch_bounds__(512, 1)
void tgemm256(const float* __restrict__ A, const unsigned char* __restrict__ Wp,
              const float* __restrict__ bias, const float* __restrict__ R,
              const float* __restrict__ av, const float* __restrict__ lng,
              const float* __restrict__ lnb, float* __restrict__ C,
              float* __restrict__ snode, int Mrows)
{
    extern __shared__ __align__(128) unsigned char smem[];
    const uint32_t sb = smem_to_u32(smem);
    const int tid = threadIdx.x, lane = tid & 31, wid = tid >> 5;
    const int warpM = wid >> 2, warpN = wid & 3;
    const int rowBase = blockIdx.x * 128;

    // A-fill geometry: 2 slots per thread, slot i covers (r, cg)
    int rA[2], cgA[2];
#pragma unroll
    for (int i = 0; i < 2; i++) {
        int g = tid + i * 512;
        rA[i] = g >> 3; cgA[i] = g & 7;
    }

    float4 pref[4];   // prefetched A fp32 (2 slots x 2 float4)

    auto issueA = [&](int ch) {
#pragma unroll
        for (int i = 0; i < 2; i++) {
            int row = rowBase + rA[i];
            if (row < Mrows) {
                const float4* src = reinterpret_cast<const float4*>(
                    A + (size_t)row * DD + ch * 64 + cgA[i] * 8);
                pref[i * 2]     = src[0];
                pref[i * 2 + 1] = src[1];
            } else {
                pref[i * 2]     = make_float4(0.f, 0.f, 0.f, 0.f);
                pref[i * 2 + 1] = make_float4(0.f, 0.f, 0.f, 0.f);
            }
        }
    };
    auto storeA = [&](int s) {
#pragma unroll
        for (int i = 0; i < 2; i++) {
            float x[8];
            float4 v0 = pref[i * 2], v1 = pref[i * 2 + 1];
            x[0] = v0.x; x[1] = v0.y; x[2] = v0.z; x[3] = v0.w;
            x[4] = v1.x; x[5] = v1.y; x[6] = v1.z; x[7] = v1.w;
            unsigned short hi[8], lo[8];
#pragma unroll
            for (int j = 0; j < 8; j++) {
                if (FLAGS & F_LRELUA) x[j] = lrelu_f(x[j]);
                __nv_bfloat16 h = __float2bfloat16(x[j]);
                __nv_bfloat16 l = __float2bfloat16(x[j] - __bfloat162float(h));
                hi[j] = *reinterpret_cast<unsigned short*>(&h);
                lo[j] = *reinterpret_cast<unsigned short*>(&l);
            }
            uint32_t off = s * 32768u + swz((uint32_t)rA[i], (uint32_t)cgA[i] * 16u);
            *reinterpret_cast<uint4*>(smem + off)         = *reinterpret_cast<uint4*>(hi);
            *reinterpret_cast<uint4*>(smem + 16384 + off) = *reinterpret_cast<uint4*>(lo);
        }
    };
    auto issueB = [&](int ch, int s) {
        const unsigned char* bh = Wp + (size_t)(ch * 2 + 0) * 32768;
        const unsigned char* bl = Wp + (size_t)(ch * 2 + 1) * 32768;
        uint32_t dh = sb + 65536u + (uint32_t)s * 65536u;
        uint32_t dl = dh + 32768u;
#pragma unroll
        for (int i = 0; i < 4; i++) {
            int idx = (tid + i * 512) * 16;
            CP_ASYNC16(dh + idx, bh + idx);
            CP_ASYNC16(dl + idx, bl + idx);
        }
        CP_COMMIT();
    };

    float c[2][8][4];
#pragma unroll
    for (int mt = 0; mt < 2; mt++)
#pragma unroll
        for (int nt = 0; nt < 8; nt++)
#pragma unroll
            for (int q = 0; q < 4; q++) c[mt][nt][q] = 0.f;

    // prologue: chunk 0
    issueA(0);
    issueB(0, 0);
    storeA(0);

    for (int ch = 0; ch < 4; ch++) {
        const int s = ch & 1;
        if (ch < 3) {
            issueA(ch + 1);
            issueB(ch + 1, s ^ 1);
            CP_WAIT(1);
        } else {
            CP_WAIT(0);
        }
        __syncthreads();

        const uint32_t aBase = sb + (uint32_t)s * 32768u;
        const uint32_t bBase = sb + 65536u + (uint32_t)s * 65536u;
#pragma unroll
        for (int ks = 0; ks < 4; ks++) {
            uint32_t ah[2][4], al[2][4];
#pragma unroll
            for (int mt = 0; mt < 2; mt++) {
                uint32_t row = (uint32_t)(warpM * 32 + mt * 16 + (lane & 7) + ((lane >> 3) & 1) * 8);
                uint32_t kb  = (uint32_t)(ks * 32 + ((lane >> 4) & 1) * 16);
                uint32_t addr = aBase + swz(row, kb);
                ldm_x4(addr,         ah[mt]);
                ldm_x4(addr + 16384, al[mt]);
            }
#pragma unroll
            for (int p = 0; p < 4; p++) {
                uint32_t nrow = (uint32_t)(warpN * 64 + p * 16 + (lane & 7) + ((lane >> 4) & 1) * 8);
                uint32_t kb   = (uint32_t)(ks * 32 + ((lane >> 3) & 1) * 16);
                uint32_t addr = bBase + swz(nrow, kb);
                uint32_t bh[4], bl[4];
                ldm_x4(addr,         bh);
                ldm_x4(addr + 32768, bl);
#pragma unroll
                for (int t = 0; t < 2; t++) {
                    const uint32_t* Bh = bh + t * 2;
                    const uint32_t* Bl = bl + t * 2;
#pragma unroll
                    for (int mt = 0; mt < 2; mt++) {
                        float* cc = c[mt][p * 2 + t];
                        mma_bf16(cc, ah[mt], Bh);
                        mma_bf16(cc, ah[mt], Bl);
                        mma_bf16(cc, al[mt], Bh);
                    }
                }
            }
        }
        if (ch < 3) storeA(s ^ 1);
        __syncthreads();
    }

    // ---- epilogue ----
    const int gid = lane >> 2, tig = lane & 3;
    float2* rb = reinterpret_cast<float2*>(smem);   // [128 rows][4 warpN] partials

#pragma unroll
    for (int mt = 0; mt < 2; mt++) {
        int r0 = rowBase + warpM * 32 + mt * 16 + gid;
        int r1 = r0 + 8;
        bool v0 = r0 < Mrows, v1 = r1 < Mrows;
#pragma unroll
        for (int nt = 0; nt < 8; nt++) {
            int col = warpN * 64 + nt * 8 + tig * 2;
            float o0 = c[mt][nt][0], o1 = c[mt][nt][1];
            float o2 = c[mt][nt][2], o3 = c[mt][nt][3];
            if (FLAGS & F_BIAS) {
                float2 bv = *reinterpret_cast<const float2*>(bias + col);
                o0 += bv.x; o1 += bv.y; o2 += bv.x; o3 += bv.y;
            }
            if (FLAGS & F_LRELU) {
                o0 = lrelu_f(o0); o1 = lrelu_f(o1); o2 = lrelu_f(o2); o3 = lrelu_f(o3);
            }
            if (FLAGS & F_RES) {
                if (v0) {
                    float2 rv = *reinterpret_cast<const float2*>(R + (size_t)r0 * DD + col);
                    o0 += rv.x; o1 += rv.y;
                }
                if (v1) {
                    float2 rv = *reinterpret_cast<const float2*>(R + (size_t)r1 * DD + col);
                    o2 += rv.x; o3 += rv.y;
                }
            }
            c[mt][nt][0] = o0; c[mt][nt][1] = o1; c[mt][nt][2] = o2; c[mt][nt][3] = o3;
            if (!(FLAGS & F_LN)) {
                if (v0) *reinterpret_cast<float2*>(C + (size_t)r0 * DD + col) = make_float2(o0, o1);
                if (v1) *reinterpret_cast<float2*>(C + (size_t)r1 * DD + col) = make_float2(o2, o3);
            }
        }
    }

    if (FLAGS & F_SNODE) {
#pragma unroll
        for (int mt = 0; mt < 2; mt++) {
            float s0 = 0.f, s1 = 0.f;
#pragma unroll
            for (int nt = 0; nt < 8; nt++) {
                int col = warpN * 64 + nt * 8 + tig * 2;
                float2 avv = *reinterpret_cast<const float2*>(av + col);
                s0 += c[mt][nt][0] * avv.x + c[mt][nt][1] * avv.y;
                s1 += c[mt][nt][2] * avv.x + c[mt][nt][3] * avv.y;
            }
#pragma unroll
            for (int o = 1; o < 4; o <<= 1) {
                s0 += __shfl_xor_sync(0xFFFFFFFFu, s0, o);
                s1 += __shfl_xor_sync(0xFFFFFFFFu, s1, o);
            }
            if (tig == 0) {
                int lr0 = warpM * 32 + mt * 16 + gid;
                rb[lr0 * 4 + warpN]       = make_float2(s0, 0.f);
                rb[(lr0 + 8) * 4 + warpN] = make_float2(s1, 0.f);
            }
        }
        __syncthreads();
        if (warpN == 0 && tig == 0) {
#pragma unroll
            for (int mt = 0; mt < 2; mt++) {
                int lr0 = warpM * 32 + mt * 16 + gid;
#pragma unroll
                for (int h = 0; h < 2; h++) {
                    int lr = lr0 + h * 8;
                    int row = rowBase + lr;
                    if (row < Mrows) {
                        float s = rb[lr * 4 + 0].x + rb[lr * 4 + 1].x
                                + rb[lr * 4 + 2].x + rb[lr * 4 + 3].x;
                        snode[row] = s;
                    }
                }
            }
        }
    }

    if (FLAGS & F_LN) {
#pragma unroll
        for (int mt = 0; mt < 2; mt++) {
            float s0 = 0.f, q0 = 0.f, s1 = 0.f, q1 = 0.f;
#pragma unroll
            for (int nt = 0; nt < 8; nt++) {
                float o0 = c[mt][nt][0], o1 = c[mt][nt][1];
                float o2 = c[mt][nt][2], o3 = c[mt][nt][3];
                s0 += o0 + o1; q0 += o0 * o0 + o1 * o1;
                s1 += o2 + o3; q1 += o2 * o2 + o3 * o3;
            }
#pragma unroll
            for (int o = 1; o < 4; o <<= 1) {
                s0 += __shfl_xor_sync(0xFFFFFFFFu, s0, o);
                q0 += __shfl_xor_sync(0xFFFFFFFFu, q0, o);
                s1 += __shfl_xor_sync(0xFFFFFFFFu, s1, o);
                q1 += __shfl_xor_sync(0xFFFFFFFFu, q1, o);
            }
            if (tig == 0) {
                int lr0 = warpM * 32 + mt * 16 + gid;
                rb[lr0 * 4 + warpN]       = make_float2(s0, q0);
                rb[(lr0 + 8) * 4 + warpN] = make_float2(s1, q1);
            }
        }
        __syncthreads();
#pragma unroll
        for (int mt = 0; mt < 2; mt++) {
            int lr0 = warpM * 32 + mt * 16 + gid;
            int lr1 = lr0 + 8;
            float2 p00 = rb[lr0*4+0], p01 = rb[lr0*4+1], p02 = rb[lr0*4+2], p03 = rb[lr0*4+3];
            float2 p10 = rb[lr1*4+0], p11 = rb[lr1*4+1], p12 = rb[lr1*4+2], p13 = rb[lr1*4+3];
            float sum0 = p00.x + p01.x + p02.x + p03.x;
            float sq0  = p00.y + p01.y + p02.y + p03.y;
            float sum1 = p10.x + p11.x + p12.x + p13.x;
            float sq1  = p10.y + p11.y + p12.y + p13.y;
            float mean0 = sum0 * (1.f / 256.f);
            float var0  = sq0 * (1.f / 256.f) - mean0 * mean0;
            float rstd0 = rsqrtf(var0 + 1e-5f);
            float mean1 = sum1 * (1.f / 256.f);
            float var1  = sq1 * (1.f / 256.f) - mean1 * mean1;
            float rstd1 = rsqrtf(var1 + 1e-5f);
            int r0 = rowBase + lr0, r1 = rowBase + lr1;
            bool v0 = r0 < Mrows, v1 = r1 < Mrows;
#pragma unroll
            for (int nt = 0; nt < 8; nt++) {
                int col = warpN * 64 + nt * 8 + tig * 2;
                float2 gv = *reinterpret_cast<const float2*>(lng + col);
                float2 bv = *reinterpret_cast<const float2*>(lnb + col);
                if (v0) {
                    float o0 = (c[mt][nt][0] - mean0) * rstd0 * gv.x + bv.x;
                    float o1 = (c[mt][nt][1] - mean0) * rstd0 * gv.y + bv.y;
                    *reinterpret_cast<float2*>(C + (size_t)r0 * DD + col) = make_float2(o0, o1);
                }
                if (v1) {
                    float o2 = (c[mt][nt][2] - mean1) * rstd1 * gv.x + bv.x;
                    float o3 = (c[mt][nt][3] - mean1) * rstd1 * gv.y + bv.y;
                    *reinterpret_cast<float2*>(C + (size_t)r1 * DD + col) = make_float2(o2, o3);
                }
            }
        }
    }
}

// -------- edge gather --------
__global__ void edge_gather(const float* __restrict__ M, const int* __restrict__ hn,
                            const int* __restrict__ permE, const int* __restrict__ offE,
                            const int* __restrict__ cntE, const float* __restrict__ a2,
                            float* __restrict__ ef, float* __restrict__ sedge, int nEdges)
{
    int ed = blockIdx.x * 8 + (threadIdx.x >> 5);
    if (ed >= nEdges) return;
    int lane = threadIdx.x & 31;
    int start = offE[ed], deg = cntE[ed];
    float4 a0 = make_float4(0.f,0.f,0.f,0.f), a1 = a0;
    for (int base = 0; base < deg; base += 32) {
        int m = min(32, deg - base);
        int src = 0;
        if (lane < m) src = hn[permE[start + base + lane]];
        for (int i = 0; i < m; i++) {
            int node = __shfl_sync(0xFFFFFFFFu, src, i);
            const float4* rp = reinterpret_cast<const float4*>(M + (size_t)node * DD + lane * 8);
            float4 v0 = rp[0], v1 = rp[1];
            a0.x += v0.x; a0.y += v0.y; a0.z += v0.z; a0.w += v0.w;
            a1.x += v1.x; a1.y += v1.y; a1.z += v1.z; a1.w += v1.w;
        }
    }
    float inv = 1.f / fmaxf((float)deg, 1.f);
    a0.x *= inv; a0.y *= inv; a0.z *= inv; a0.w *= inv;
    a1.x *= inv; a1.y *= inv; a1.z *= inv; a1.w *= inv;
    float4* op = reinterpret_cast<float4*>(ef + (size_t)ed * DD + lane * 8);
    op[0] = a0; op[1] = a1;
    const float4* ap = reinterpret_cast<const float4*>(a2 + lane * 8);
    float4 c0 = ap[0], c1 = ap[1];
    float d = a0.x*c0.x + a0.y*c0.y + a0.z*c0.z + a0.w*c0.w
            + a1.x*c1.x + a1.y*c1.y + a1.z*c1.z + a1.w*c1.w;
#pragma unroll
    for (int o = 16; o; o >>= 1) d += __shfl_xor_sync(0xFFFFFFFFu, d, o);
    if (lane == 0) sedge[ed] = d;
}

// -------- per-node softmax --------
__global__ void node_softmax(const float* __restrict__ sn, const float* __restrict__ se,
                             const int* __restrict__ he, const int* __restrict__ permN,
                             const int* __restrict__ offN, const int* __restrict__ cntN,
                             float* __restrict__ attn, int nNodes)
{
    int n = blockIdx.x * blockDim.x + threadIdx.x;
    if (n >= nNodes) return;
    int st = offN[n], deg = cntN[n];
    if (deg == 0) return;
    float s0 = sn[n];
    if (deg <= 16) {
        int   incs[16];
        float scs[16];
        float mx = -3.4e38f;
        for (int i = 0; i < deg; i++) {
            int inc = permN[st + i];
            incs[i] = inc;
            float sc = lrelu_f(s0 + se[he[inc]]);
            scs[i] = sc;
            mx = fmaxf(mx, sc);
        }
        float z = 0.f;
        for (int i = 0; i < deg; i++) {
            float e = expf(scs[i] - mx);
            scs[i] = e;
            z += e;
        }
        float inv = 1.f / fmaxf(z, 1e-9f);
        for (int i = 0; i < deg; i++) attn[incs[i]] = scs[i] * inv;
    } else {
        float mx = -3.4e38f;
        for (int i = 0; i < deg; i++) {
            int inc = permN[st + i];
            mx = fmaxf(mx, lrelu_f(s0 + se[he[inc]]));
        }
        float z = 0.f;
        for (int i = 0; i < deg; i++) {
            int inc = permN[st + i];
            float e = expf(lrelu_f(s0 + se[he[inc]]) - mx);
            attn[inc] = e;
            z += e;
        }
        float inv = 1.f / fmaxf(z, 1e-9f);
        for (int i = 0; i < deg; i++) attn[permN[st + i]] *= inv;
    }
}

// -------- node aggregate --------
__global__ void node_aggregate(const float* __restrict__ ef, const int* __restrict__ he,
                               const int* __restrict__ permN, const int* __restrict__ offN,
                               const int* __restrict__ cntN, const float* __restrict__ attn,
                               float* __restrict__ out, int doLrelu, int nNodes)
{
    int n = blockIdx.x * 8 + (threadIdx.x >> 5);
    if (n >= nNodes) return;
    int lane = threadIdx.x & 31;
    int start = offN[n], deg = cntN[n];
    float4 a0 = make_float4(0.f,0.f,0.f,0.f), a1 = a0;
    for (int base = 0; base < deg; base += 32) {
        int m = min(32, deg - base);
        int ed = 0; float w = 0.f;
        if (lane < m) {
            int inc = permN[start + base + lane];
            ed = he[inc];
            w = attn[inc];
        }
        for (int i = 0; i < m; i++) {
            int e_  = __shfl_sync(0xFFFFFFFFu, ed, i);
            float w_ = __shfl_sync(0xFFFFFFFFu, w, i);
            const float4* rp = reinterpret_cast<const float4*>(ef + (size_t)e_ * DD + lane * 8);
            float4 v0 = rp[0], v1 = rp[1];
            a0.x += w_*v0.x; a0.y += w_*v0.y; a0.z += w_*v0.z; a0.w += w_*v0.w;
            a1.x += w_*v1.x; a1.y += w_*v1.y; a1.z += w_*v1.z; a1.w += w_*v1.w;
        }
    }
    if (doLrelu) {
        a0.x = lrelu_f(a0.x); a0.y = lrelu_f(a0.y); a0.z = lrelu_f(a0.z); a0.w = lrelu_f(a0.w);
        a1.x = lrelu_f(a1.x); a1.y = lrelu_f(a1.y); a1.z = lrelu_f(a1.z); a1.w = lrelu_f(a1.w);
    }
    float4* op = reinterpret_cast<float4*>(out + (size_t)n * DD + lane * 8);
    op[0] = a0; op[1] = a1;
}

// -------- object message gather --------
__global__ void obj_gather(const float* __restrict__ ev, const int* __restrict__ oe_ev,
                           const int* __restrict__ permO, const int* __restrict__ offO,
                           const int* __restrict__ cntO, float* __restrict__ msg, int nObj)
{
    int o = blockIdx.x * 8 + (threadIdx.x >> 5);
    if (o >= nObj) return;
    int lane = threadIdx.x & 31;
    int start = offO[o], deg = cntO[o];
    float4 a0 = make_float4(0.f,0.f,0.f,0.f), a1 = a0;
    for (int base = 0; base < deg; base += 32) {
        int m = min(32, deg - base);
        int src = 0;
        if (lane < m) src = oe_ev[permO[start + base + lane]];
        for (int i = 0; i < m; i++) {
            int row = __shfl_sync(0xFFFFFFFFu, src, i);
            const float4* rp = reinterpret_cast<const float4*>(ev + (size_t)row * DD + lane * 8);
            float4 v0 = rp[0], v1 = rp[1];
            a0.x += v0.x; a0.y += v0.y; a0.z += v0.z; a0.w += v0.w;
            a1.x += v1.x; a1.y += v1.y; a1.z += v1.z; a1.w += v1.w;
        }
    }
    float4* op = reinterpret_cast<float4*>(msg + (size_t)o * DD + lane * 8);
    op[0] = a0; op[1] = a1;
}

// ----------------- host orchestration -----------------
struct Ptrs {
    float *X, *obj, *msg, *M, *H, *ef, *snode, *sedge, *ew;
    unsigned char* wp;
    int *cntE, *offE, *permE, *cntN, *offN, *permN, *cntO, *offO, *permO, *cur, *bsum;
};

static void get_ptrs(Ptrs& p) {
    cudaGetSymbolAddress((void**)&p.X,     g_X);
    cudaGetSymbolAddress((void**)&p.obj,   g_obj);
    cudaGetSymbolAddress((void**)&p.msg,   g_msg);
    cudaGetSymbolAddress((void**)&p.M,     g_M);
    cudaGetSymbolAddress((void**)&p.H,     g_H);
    cudaGetSymbolAddress((void**)&p.ef,    g_ef);
    cudaGetSymbolAddress((void**)&p.snode, g_snode);
    cudaGetSymbolAddress((void**)&p.sedge, g_sedge);
    cudaGetSymbolAddress((void**)&p.ew,    g_ew);
    cudaGetSymbolAddress((void**)&p.wp,    g_Wprep);
    cudaGetSymbolAddress((void**)&p.cntE,  g_cntE);
    cudaGetSymbolAddress((void**)&p.offE,  g_offE);
    cudaGetSymbolAddress((void**)&p.permE, g_permE);
    cudaGetSymbolAddress((void**)&p.cntN,  g_cntN);
    cudaGetSymbolAddress((void**)&p.offN,  g_offN);
    cudaGetSymbolAddress((void**)&p.permN, g_permN);
    cudaGetSymbolAddress((void**)&p.cntO,  g_cntO);
    cudaGetSymbolAddress((void**)&p.offO,  g_offO);
    cudaGetSymbolAddress((void**)&p.permO, g_permO);
    cudaGetSymbolAddress((void**)&p.cur,   g_cur);
    cudaGetSymbolAddress((void**)&p.bsum,  g_bsum);
}

static void build_csr(const int* idx, int n, int nseg,
                      int* cnt, int* off, int* perm, int* cur, int* bsum)
{
    cudaMemsetAsync(cnt, 0, (size_t)nseg * sizeof(int));
    seg_count<<<(n + 255) / 256, 256>>>(idx, cnt, n);
    int nb = (nseg + 1023) / 1024;
    scan_block1024<<<nb, 1024>>>(cnt, off, bsum, nseg);
    scan_small<<<1, 32>>>(bsum, nb);
    add_off<<<(nseg + 255) / 256, 256>>>(off, bsum, nseg);
    cudaMemsetAsync(cur, 0, (size_t)nseg * sizeof(int));
    fill_perm<<<(n + 255) / 256, 256>>>(idx, off, cur, perm, n);
}

template <int FLAGS>
static void launch_tgemm(const float* A, const unsigned char* Wp, const float* bias,
                         const float* R, const float* av, const float* lng, const float* lnb,
                         float* C, float* snode, int Mrows)
{
    cudaFuncSetAttribute(tgemm256<FLAGS>, cudaFuncAttributeMaxDynamicSharedMemorySize, SMEM_SZ);
    tgemm256<FLAGS><<<(Mrows + 127) / 128, 512, SMEM_SZ>>>(A, Wp, bias, R, av, lng, lnb, C, snode, Mrows);
}

static void hgnn_layer(const Ptrs& p, const float* Xin, const unsigned char* Wp, const float* a,
                       const int* hg_node, const int* hg_edge,
                       float* outbuf, float* attnOut, bool lreluA, bool lreluOut)
{
    if (lreluA) launch_tgemm<F_SNODE | F_LRELUA>(Xin, Wp, nullptr, nullptr, a, nullptr, nullptr, p.M, p.snode, NN);
    else        launch_tgemm<F_SNODE>           (Xin, Wp, nullptr, nullptr, a, nullptr, nullptr, p.M, p.snode, NN);
    edge_gather<<<(NE + 7) / 8, 256>>>(p.M, hg_node, p.permE, p.offE, p.cntE,
                                       a + DD, p.ef, p.sedge, NE);
    node_softmax<<<(NN + 255) / 256, 256>>>(p.snode, p.sedge, hg_edge, p.permN,
                                            p.offN, p.cntN, attnOut, NN);
    node_aggregate<<<(NN + 7) / 8, 256>>>(p.ef, hg_edge, p.permN, p.offN, p.cntN,
                                          attnOut, outbuf, lreluOut ? 1 : 0, NN);
}

extern "C" void kernel_launch(void* const* d_in, const int* in_sizes, int n_in,
                              void* d_out, int out_size)
{
    const float* object_X = (const float*)d_in[0];
    const float* event_X  = (const float*)d_in[1];
    const float* Wo = (const float*)d_in[2];  const float* bo  = (const float*)d_in[3];
    const float* go = (const float*)d_in[4];  const float* bon = (const float*)d_in[5];
    const float* We = (const float*)d_in[6];  const float* be  = (const float*)d_in[7];
    const float* ge = (const float*)d_in[8];  const float* ben = (const float*)d_in[9];
    const float* Wu = (const float*)d_in[10]; const float* bu  = (const float*)d_in[11];
    const float* Wl = (const float*)d_in[12]; const float* bl  = (const float*)d_in[13];
    const float* g1 = (const float*)d_in[14]; const float* b1  = (const float*)d_in[15];
    const float* g2 = (const float*)d_in[16]; const float* b2  = (const float*)d_in[17];
    const float* Wh1 = (const float*)d_in[18]; const float* ah1 = (const float*)d_in[19];
    const float* Wh2 = (const float*)d_in[20]; const float* ah2 = (const float*)d_in[21];
    const int* oe_ev   = (const int*)d_in[22];
    const int* oe_obj  = (const int*)d_in[23];
    const int* hg_node = (const int*)d_in[24];
    const int* hg_edge = (const int*)d_in[25];

    Ptrs p; get_ptrs(p);

    // 0) weight prep + CSR builds
    prep_w<<<dim3(32, 6), 256>>>(We, Wo, Wu, Wl, Wh1, Wh2);
    build_csr(hg_edge, E2N, NE, p.cntE, p.offE, p.permE, p.cur, p.bsum);
    build_csr(hg_node, E2N, NN, p.cntN, p.offN, p.permN, p.cur, p.bsum);
    build_csr(oe_obj,  E1N, NO, p.cntO, p.offO, p.permO, p.cur, p.bsum);
    const unsigned char *wpe = p.wp, *wpo = p.wp + 262144, *wpu = p.wp + 2 * 262144,
                        *wpl = p.wp + 3 * 262144, *wph1 = p.wp + 4 * 262144,
                        *wph2 = p.wp + 5 * 262144;

    // 1) ev = LN(lrelu(event_X @ We + be)) -> X[0:NE)
    launch_tgemm<F_BIAS | F_LRELU | F_LN>(event_X, wpe, be, nullptr, nullptr, ge, ben, p.X, nullptr, NE);

    // 2) obj = LN(lrelu(object_X @ Wo + bo))
    launch_tgemm<F_BIAS | F_LRELU | F_LN>(object_X, wpo, bo, nullptr, nullptr, go, bon, p.obj, nullptr, NO);

    // 3) msg = segment_sum(ev[oe_ev], oe_obj)
    obj_gather<<<(NO + 7) / 8, 256>>>(p.X, oe_ev, p.permO, p.offO, p.cntO, p.msg, NO);

    // 4) obj1 = LN(lrelu(msg @ Wu + bu) + obj)
    launch_tgemm<F_BIAS | F_LRELU | F_RES | F_LN>(p.msg, wpu, bu, p.obj, nullptr, g1, b1, p.obj, nullptr, NO);

    // 5) obj2 = LN(lrelu(obj1 @ Wl + bl) + obj1) -> X[NE:NN)
    launch_tgemm<F_BIAS | F_LRELU | F_RES | F_LN>(p.obj, wpl, bl, p.obj, nullptr, g2, b2, p.X + (size_t)NE * DD, nullptr, NO);

    // 6) HGNN layer 1 -> H
    hgnn_layer(p, p.X, wph1, ah1, hg_node, hg_edge, p.H, p.ew, false, false);

    // 7) HGNN layer 2 -> d_out
    float* out = (float*)d_out;
    hgnn_layer(p, p.H, wph2, ah2, hg_node, hg_edge, out, out + (size_t)NN * DD, true, true);
}

// round 7
// speedup vs baseline: 2.4732x; 1.1337x over previous
#include <cuda_runtime.h>
#include <cuda_bf16.h>
#include <cstdint>

#define DD 256
static const int NE  = 50000;
static const int NO  = 100000;
static const int NN  = 150000;
static const int E1N = 400000;
static const int E2N = 800000;

// -------- device scratch --------
__device__ float    g_X  [(size_t)NN * DD];
__device__ float    g_obj[(size_t)NO * DD];
__device__ float    g_msg[(size_t)NO * DD];   // also reused as Xmean[NE*DD] in hgnn layers
__device__ float    g_H  [(size_t)NN * DD];
__device__ float    g_ef [(size_t)NE * DD];
__device__ float    g_snode[NN];
__device__ float    g_sedge[NE];
__device__ float    g_ew[E2N];
__device__ float    g_wav[DD];
__device__ unsigned char g_Wprep[6 * 4 * 2 * 256 * 128];
// CSR structures
__device__ int g_cntE[NE],  g_offE[NE],  g_permE[E2N];
__device__ int g_cntN[NN],  g_offN[NN],  g_permN[E2N];
__device__ int g_cntO[NO],  g_offO[NO],  g_permO[E1N];
__device__ int g_cur[NN];
__device__ int g_bsum[256];

// -------- helpers --------
__device__ __forceinline__ float lrelu_f(float x) { return x >= 0.f ? x : 0.2f * x; }

__device__ __forceinline__ uint32_t smem_to_u32(const void* p) {
    uint32_t a;
    asm("{ .reg .u64 t; cvta.to.shared.u64 t, %1; cvt.u32.u64 %0, t; }" : "=r"(a) : "l"(p));
    return a;
}
__device__ __forceinline__ void ldm_x4(uint32_t addr, uint32_t* r) {
    asm volatile("ldmatrix.sync.aligned.m8n8.x4.shared.b16 {%0,%1,%2,%3}, [%4];"
                 : "=r"(r[0]), "=r"(r[1]), "=r"(r[2]), "=r"(r[3]) : "r"(addr));
}
__device__ __forceinline__ void mma_bf16(float* c, const uint32_t* a, const uint32_t* b) {
    asm volatile("mma.sync.aligned.m16n8k16.row.col.f32.bf16.bf16.f32 "
                 "{%0,%1,%2,%3}, {%4,%5,%6,%7}, {%8,%9}, {%0,%1,%2,%3};"
                 : "+f"(c[0]), "+f"(c[1]), "+f"(c[2]), "+f"(c[3])
                 : "r"(a[0]), "r"(a[1]), "r"(a[2]), "r"(a[3]), "r"(b[0]), "r"(b[1]));
}
__device__ __forceinline__ uint32_t swz(uint32_t row, uint32_t cb) {
    return row * 128u + (cb ^ ((row & 7u) << 4));
}
#define CP_ASYNC16(dst, src) \
    asm volatile("cp.async.cg.shared.global [%0], [%1], 16;" :: "r"(dst), "l"(src) : "memory")
#define CP_COMMIT() asm volatile("cp.async.commit_group;" ::: "memory")
#define CP_WAIT(n)  asm volatile("cp.async.wait_group %0;" :: "n"(n) : "memory")

enum { F_BIAS = 1, F_LRELU = 2, F_RES = 4, F_LRELUA = 8, F_SNODE = 16, F_LN = 32 };

// -------- CSR build kernels --------
__global__ void seg_count(const int* __restrict__ idx, int* __restrict__ cnt, int n)
{
    int e = blockIdx.x * blockDim.x + threadIdx.x;
    if (e < n) atomicAdd(&cnt[idx[e]], 1);
}
__global__ void scan_block1024(const int* __restrict__ cnt, int* __restrict__ off,
                               int* __restrict__ bsum, int nseg)
{
    __shared__ int sh[1024];
    int g = blockIdx.x * 1024 + threadIdx.x;
    int v = (g < nseg) ? cnt[g] : 0;
    sh[threadIdx.x] = v;
    __syncthreads();
#pragma unroll
    for (int o = 1; o < 1024; o <<= 1) {
        int t = (threadIdx.x >= o) ? sh[threadIdx.x - o] : 0;
        __syncthreads();
        sh[threadIdx.x] += t;
        __syncthreads();
    }
    if (g < nseg) off[g] = sh[threadIdx.x] - v;
    if (threadIdx.x == 1023) bsum[blockIdx.x] = sh[1023];
}
__global__ void scan_small(int* bsum, int nb)
{
    if (threadIdx.x == 0) {
        int run = 0;
        for (int i = 0; i < nb; i++) { int t = bsum[i]; bsum[i] = run; run += t; }
    }
}
__global__ void add_off(int* __restrict__ off, const int* __restrict__ bsum, int nseg)
{
    int g = blockIdx.x * blockDim.x + threadIdx.x;
    if (g < nseg) off[g] += bsum[g >> 10];
}
__global__ void fill_perm(const int* __restrict__ idx, const int* __restrict__ off,
                          int* __restrict__ cur, int* __restrict__ perm, int n)
{
    int e = blockIdx.x * blockDim.x + threadIdx.x;
    if (e >= n) return;
    int s = idx[e];
    int pos = off[s] + atomicAdd(&cur[s], 1);
    perm[pos] = e;
}

// -------- weight prep --------
__global__ void prep_w(const float* W0, const float* W1, const float* W2,
                       const float* W3, const float* W4, const float* W5)
{
    const float* Ws[6] = {W0, W1, W2, W3, W4, W5};
    const float* W = Ws[blockIdx.y];
    unsigned char* base = g_Wprep + (size_t)blockIdx.y * 262144;
    int g = blockIdx.x * 256 + threadIdx.x;
    int n = g >> 5, kg = g & 31, k0 = kg * 8;
    unsigned short hi[8], lo[8];
#pragma unroll
    for (int i = 0; i < 8; i++) {
        float x = W[(size_t)(k0 + i) * DD + n];
        __nv_bfloat16 h = __float2bfloat16(x);
        __nv_bfloat16 l = __float2bfloat16(x - __bfloat162float(h));
        hi[i] = *reinterpret_cast<unsigned short*>(&h);
        lo[i] = *reinterpret_cast<unsigned short*>(&l);
    }
    int chunk = k0 >> 6, kc = k0 & 63;
    uint32_t off = (uint32_t)n * 128u + (((uint32_t)kc * 2u) ^ (((uint32_t)n & 7u) << 4));
    *reinterpret_cast<uint4*>(base + (size_t)(chunk * 2 + 0) * 32768 + off) =
        *reinterpret_cast<uint4*>(hi);
    *reinterpret_cast<uint4*>(base + (size_t)(chunk * 2 + 1) * 32768 + off) =
        *reinterpret_cast<uint4*>(lo);
}

// w[k] = dot(W[k][:], a[0:256])   (warp per k)
__global__ void prep_wav(const float* __restrict__ W, const float* __restrict__ a,
                         float* __restrict__ w)
{
    int k = blockIdx.x * 8 + (threadIdx.x >> 5);
    if (k >= DD) return;
    int lane = threadIdx.x & 31;
    const float4* rp = reinterpret_cast<const float4*>(W + (size_t)k * DD);
    const float4* ap = reinterpret_cast<const float4*>(a);
    float4 v0 = rp[lane], v1 = rp[lane + 32];
    float4 a0 = ap[lane], a1 = ap[lane + 32];
    float d = v0.x*a0.x + v0.y*a0.y + v0.z*a0.z + v0.w*a0.w
            + v1.x*a1.x + v1.y*a1.y + v1.z*a1.z + v1.w*a1.w;
#pragma unroll
    for (int o = 16; o; o >>= 1) d += __shfl_xor_sync(0xFFFFFFFFu, d, o);
    if (lane == 0) w[k] = d;
}

// snode[r] = dot(act(X[r]), w)   (warp per row)
__global__ void snode_dot(const float* __restrict__ X, const float* __restrict__ w,
                          float* __restrict__ snode, int rows, int act)
{
    int row = blockIdx.x * 8 + (threadIdx.x >> 5);
    if (row >= rows) return;
    int lane = threadIdx.x & 31;
    const float4* rp = reinterpret_cast<const float4*>(X + (size_t)row * DD);
    const float4* ap = reinterpret_cast<const float4*>(w);
    float4 v0 = rp[lane], v1 = rp[lane + 32];
    if (act) {
        v0.x = lrelu_f(v0.x); v0.y = lrelu_f(v0.y); v0.z = lrelu_f(v0.z); v0.w = lrelu_f(v0.w);
        v1.x = lrelu_f(v1.x); v1.y = lrelu_f(v1.y); v1.z = lrelu_f(v1.z); v1.w = lrelu_f(v1.w);
    }
    float4 a0 = ap[lane], a1 = ap[lane + 32];
    float d = v0.x*a0.x + v0.y*a0.y + v0.z*a0.z + v0.w*a0.w
            + v1.x*a1.x + v1.y*a1.y + v1.z*a1.z + v1.w*a1.w;
#pragma unroll
    for (int o = 16; o; o >>= 1) d += __shfl_xor_sync(0xFFFFFFFFu, d, o);
    if (lane == 0) snode[row] = d;
}

// -------- tensor-core GEMM, tile 128x256, double-buffered + cp.async pipeline --------
static const int SMEM_SZ = 196608;

template <int FLAGS>
__global__ __launch_bounds__(512, 1)
void tgemm256(const float* __restrict__ A, const unsigned char* __restrict__ Wp,
              const float* __restrict__ bias, const float* __restrict__ R,
              const float* __restrict__ av, const float* __restrict__ lng,
              const float* __restrict__ lnb, float* __restrict__ C,
              float* __restrict__ snode, int Mrows)
{
    extern __shared__ __align__(128) unsigned char smem[];
    const uint32_t sb = smem_to_u32(smem);
    const int tid = threadIdx.x, lane = tid & 31, wid = tid >> 5;
    const int warpM = wid >> 2, warpN = wid & 3;
    const int rowBase = blockIdx.x * 128;

    int rA[2], cgA[2];
#pragma unroll
    for (int i = 0; i < 2; i++) {
        int g = tid + i * 512;
        rA[i] = g >> 3; cgA[i] = g & 7;
    }
    float4 pref[4];

    auto issueA = [&](int ch) {
#pragma unroll
        for (int i = 0; i < 2; i++) {
            int row = rowBase + rA[i];
            if (row < Mrows) {
                const float4* src = reinterpret_cast<const float4*>(
                    A + (size_t)row * DD + ch * 64 + cgA[i] * 8);
                pref[i * 2]     = src[0];
                pref[i * 2 + 1] = src[1];
            } else {
                pref[i * 2]     = make_float4(0.f, 0.f, 0.f, 0.f);
                pref[i * 2 + 1] = make_float4(0.f, 0.f, 0.f, 0.f);
            }
        }
    };
    auto storeA = [&](int s) {
#pragma unroll
        for (int i = 0; i < 2; i++) {
            float x[8];
            float4 v0 = pref[i * 2], v1 = pref[i * 2 + 1];
            x[0] = v0.x; x[1] = v0.y; x[2] = v0.z; x[3] = v0.w;
            x[4] = v1.x; x[5] = v1.y; x[6] = v1.z; x[7] = v1.w;
            unsigned short hi[8], lo[8];
#pragma unroll
            for (int j = 0; j < 8; j++) {
                if (FLAGS & F_LRELUA) x[j] = lrelu_f(x[j]);
                __nv_bfloat16 h = __float2bfloat16(x[j]);
                __nv_bfloat16 l = __float2bfloat16(x[j] - __bfloat162float(h));
                hi[j] = *reinterpret_cast<unsigned short*>(&h);
                lo[j] = *reinterpret_cast<unsigned short*>(&l);
            }
            uint32_t off = s * 32768u + swz((uint32_t)rA[i], (uint32_t)cgA[i] * 16u);
            *reinterpret_cast<uint4*>(smem + off)         = *reinterpret_cast<uint4*>(hi);
            *reinterpret_cast<uint4*>(smem + 16384 + off) = *reinterpret_cast<uint4*>(lo);
        }
    };
    auto issueB = [&](int ch, int s) {
        const unsigned char* bh = Wp + (size_t)(ch * 2 + 0) * 32768;
        const unsigned char* bl = Wp + (size_t)(ch * 2 + 1) * 32768;
        uint32_t dh = sb + 65536u + (uint32_t)s * 65536u;
        uint32_t dl = dh + 32768u;
#pragma unroll
        for (int i = 0; i < 4; i++) {
            int idx = (tid + i * 512) * 16;
            CP_ASYNC16(dh + idx, bh + idx);
            CP_ASYNC16(dl + idx, bl + idx);
        }
        CP_COMMIT();
    };

    float c[2][8][4];
#pragma unroll
    for (int mt = 0; mt < 2; mt++)
#pragma unroll
        for (int nt = 0; nt < 8; nt++)
#pragma unroll
            for (int q = 0; q < 4; q++) c[mt][nt][q] = 0.f;

    issueA(0);
    issueB(0, 0);
    storeA(0);

    for (int ch = 0; ch < 4; ch++) {
        const int s = ch & 1;
        if (ch < 3) {
            issueA(ch + 1);
            issueB(ch + 1, s ^ 1);
            CP_WAIT(1);
        } else {
            CP_WAIT(0);
        }
        __syncthreads();

        const uint32_t aBase = sb + (uint32_t)s * 32768u;
        const uint32_t bBase = sb + 65536u + (uint32_t)s * 65536u;
#pragma unroll
        for (int ks = 0; ks < 4; ks++) {
            uint32_t ah[2][4], al[2][4];
#pragma unroll
            for (int mt = 0; mt < 2; mt++) {
                uint32_t row = (uint32_t)(warpM * 32 + mt * 16 + (lane & 7) + ((lane >> 3) & 1) * 8);
                uint32_t kb  = (uint32_t)(ks * 32 + ((lane >> 4) & 1) * 16);
                uint32_t addr = aBase + swz(row, kb);
                ldm_x4(addr,         ah[mt]);
                ldm_x4(addr + 16384, al[mt]);
            }
#pragma unroll
            for (int p = 0; p < 4; p++) {
                uint32_t nrow = (uint32_t)(warpN * 64 + p * 16 + (lane & 7) + ((lane >> 4) & 1) * 8);
                uint32_t kb   = (uint32_t)(ks * 32 + ((lane >> 3) & 1) * 16);
                uint32_t addr = bBase + swz(nrow, kb);
                uint32_t bh[4], bl[4];
                ldm_x4(addr,         bh);
                ldm_x4(addr + 32768, bl);
#pragma unroll
                for (int t = 0; t < 2; t++) {
                    const uint32_t* Bh = bh + t * 2;
                    const uint32_t* Bl = bl + t * 2;
#pragma unroll
                    for (int mt = 0; mt < 2; mt++) {
                        float* cc = c[mt][p * 2 + t];
                        mma_bf16(cc, ah[mt], Bh);
                        mma_bf16(cc, ah[mt], Bl);
                        mma_bf16(cc, al[mt], Bh);
                    }
                }
            }
        }
        if (ch < 3) storeA(s ^ 1);
        __syncthreads();
    }

    const int gid = lane >> 2, tig = lane & 3;
    float2* rb = reinterpret_cast<float2*>(smem);

#pragma unroll
    for (int mt = 0; mt < 2; mt++) {
        int r0 = rowBase + warpM * 32 + mt * 16 + gid;
        int r1 = r0 + 8;
        bool v0 = r0 < Mrows, v1 = r1 < Mrows;
#pragma unroll
        for (int nt = 0; nt < 8; nt++) {
            int col = warpN * 64 + nt * 8 + tig * 2;
            float o0 = c[mt][nt][0], o1 = c[mt][nt][1];
            float o2 = c[mt][nt][2], o3 = c[mt][nt][3];
            if (FLAGS & F_BIAS) {
                float2 bv = *reinterpret_cast<const float2*>(bias + col);
                o0 += bv.x; o1 += bv.y; o2 += bv.x; o3 += bv.y;
            }
            if (FLAGS & F_LRELU) {
                o0 = lrelu_f(o0); o1 = lrelu_f(o1); o2 = lrelu_f(o2); o3 = lrelu_f(o3);
            }
            if (FLAGS & F_RES) {
                if (v0) {
                    float2 rv = *reinterpret_cast<const float2*>(R + (size_t)r0 * DD + col);
                    o0 += rv.x; o1 += rv.y;
                }
                if (v1) {
                    float2 rv = *reinterpret_cast<const float2*>(R + (size_t)r1 * DD + col);
                    o2 += rv.x; o3 += rv.y;
                }
            }
            c[mt][nt][0] = o0; c[mt][nt][1] = o1; c[mt][nt][2] = o2; c[mt][nt][3] = o3;
            if (!(FLAGS & F_LN)) {
                if (v0) *reinterpret_cast<float2*>(C + (size_t)r0 * DD + col) = make_float2(o0, o1);
                if (v1) *reinterpret_cast<float2*>(C + (size_t)r1 * DD + col) = make_float2(o2, o3);
            }
        }
    }

    if (FLAGS & F_SNODE) {
#pragma unroll
        for (int mt = 0; mt < 2; mt++) {
            float s0 = 0.f, s1 = 0.f;
#pragma unroll
            for (int nt = 0; nt < 8; nt++) {
                int col = warpN * 64 + nt * 8 + tig * 2;
                float2 avv = *reinterpret_cast<const float2*>(av + col);
                s0 += c[mt][nt][0] * avv.x + c[mt][nt][1] * avv.y;
                s1 += c[mt][nt][2] * avv.x + c[mt][nt][3] * avv.y;
            }
#pragma unroll
            for (int o = 1; o < 4; o <<= 1) {
                s0 += __shfl_xor_sync(0xFFFFFFFFu, s0, o);
                s1 += __shfl_xor_sync(0xFFFFFFFFu, s1, o);
            }
            if (tig == 0) {
                int lr0 = warpM * 32 + mt * 16 + gid;
                rb[lr0 * 4 + warpN]       = make_float2(s0, 0.f);
                rb[(lr0 + 8) * 4 + warpN] = make_float2(s1, 0.f);
            }
        }
        __syncthreads();
        if (warpN == 0 && tig == 0) {
#pragma unroll
            for (int mt = 0; mt < 2; mt++) {
                int lr0 = warpM * 32 + mt * 16 + gid;
#pragma unroll
                for (int h = 0; h < 2; h++) {
                    int lr = lr0 + h * 8;
                    int row = rowBase + lr;
                    if (row < Mrows) {
                        float s = rb[lr * 4 + 0].x + rb[lr * 4 + 1].x
                                + rb[lr * 4 + 2].x + rb[lr * 4 + 3].x;
                        snode[row] = s;
                    }
                }
            }
        }
    }

    if (FLAGS & F_LN) {
#pragma unroll
        for (int mt = 0; mt < 2; mt++) {
            float s0 = 0.f, q0 = 0.f, s1 = 0.f, q1 = 0.f;
#pragma unroll
            for (int nt = 0; nt < 8; nt++) {
                float o0 = c[mt][nt][0], o1 = c[mt][nt][1];
                float o2 = c[mt][nt][2], o3 = c[mt][nt][3];
                s0 += o0 + o1; q0 += o0 * o0 + o1 * o1;
                s1 += o2 + o3; q1 += o2 * o2 + o3 * o3;
            }
#pragma unroll
            for (int o = 1; o < 4; o <<= 1) {
                s0 += __shfl_xor_sync(0xFFFFFFFFu, s0, o);
                q0 += __shfl_xor_sync(0xFFFFFFFFu, q0, o);
                s1 += __shfl_xor_sync(0xFFFFFFFFu, s1, o);
                q1 += __shfl_xor_sync(0xFFFFFFFFu, q1, o);
            }
            if (tig == 0) {
                int lr0 = warpM * 32 + mt * 16 + gid;
                rb[lr0 * 4 + warpN]       = make_float2(s0, q0);
                rb[(lr0 + 8) * 4 + warpN] = make_float2(s1, q1);
            }
        }
        __syncthreads();
#pragma unroll
        for (int mt = 0; mt < 2; mt++) {
            int lr0 = warpM * 32 + mt * 16 + gid;
            int lr1 = lr0 + 8;
            float2 p00 = rb[lr0*4+0], p01 = rb[lr0*4+1], p02 = rb[lr0*4+2], p03 = rb[lr0*4+3];
            float2 p10 = rb[lr1*4+0], p11 = rb[lr1*4+1], p12 = rb[lr1*4+2], p13 = rb[lr1*4+3];
            float sum0 = p00.x + p01.x + p02.x + p03.x;
            float sq0  = p00.y + p01.y + p02.y + p03.y;
            float sum1 = p10.x + p11.x + p12.x + p13.x;
            float sq1  = p10.y + p11.y + p12.y + p13.y;
            float mean0 = sum0 * (1.f / 256.f);
            float var0  = sq0 * (1.f / 256.f) - mean0 * mean0;
            float rstd0 = rsqrtf(var0 + 1e-5f);
            float mean1 = sum1 * (1.f / 256.f);
            float var1  = sq1 * (1.f / 256.f) - mean1 * mean1;
            float rstd1 = rsqrtf(var1 + 1e-5f);
            int r0 = rowBase + lr0, r1 = rowBase + lr1;
            bool v0 = r0 < Mrows, v1 = r1 < Mrows;
#pragma unroll
            for (int nt = 0; nt < 8; nt++) {
                int col = warpN * 64 + nt * 8 + tig * 2;
                float2 gv = *reinterpret_cast<const float2*>(lng + col);
                float2 bv = *reinterpret_cast<const float2*>(lnb + col);
                if (v0) {
                    float o0 = (c[mt][nt][0] - mean0) * rstd0 * gv.x + bv.x;
                    float o1 = (c[mt][nt][1] - mean0) * rstd0 * gv.y + bv.y;
                    *reinterpret_cast<float2*>(C + (size_t)r0 * DD + col) = make_float2(o0, o1);
                }
                if (v1) {
                    float o2 = (c[mt][nt][2] - mean1) * rstd1 * gv.x + bv.x;
                    float o3 = (c[mt][nt][3] - mean1) * rstd1 * gv.y + bv.y;
                    *reinterpret_cast<float2*>(C + (size_t)r1 * DD + col) = make_float2(o2, o3);
                }
            }
        }
    }
}

// -------- edge gather on raw X: Xmean[ed] = mean(act(X[node]))  (warp/edge) --------
__global__ void edge_gatherX(const float* __restrict__ X, const int* __restrict__ hn,
                             const int* __restrict__ permE, const int* __restrict__ offE,
                             const int* __restrict__ cntE, float* __restrict__ Xmean,
                             int act, int nEdges)
{
    int ed = blockIdx.x * 8 + (threadIdx.x >> 5);
    if (ed >= nEdges) return;
    int lane = threadIdx.x & 31;
    int start = offE[ed], deg = cntE[ed];
    float4 a0 = make_float4(0.f,0.f,0.f,0.f), a1 = a0;
    for (int base = 0; base < deg; base += 32) {
        int m = min(32, deg - base);
        int src = 0;
        if (lane < m) src = hn[permE[start + base + lane]];
        for (int i = 0; i < m; i++) {
            int node = __shfl_sync(0xFFFFFFFFu, src, i);
            const float4* rp = reinterpret_cast<const float4*>(X + (size_t)node * DD + lane * 8);
            float4 v0 = rp[0], v1 = rp[1];
            if (act) {
                v0.x = lrelu_f(v0.x); v0.y = lrelu_f(v0.y); v0.z = lrelu_f(v0.z); v0.w = lrelu_f(v0.w);
                v1.x = lrelu_f(v1.x); v1.y = lrelu_f(v1.y); v1.z = lrelu_f(v1.z); v1.w = lrelu_f(v1.w);
            }
            a0.x += v0.x; a0.y += v0.y; a0.z += v0.z; a0.w += v0.w;
            a1.x += v1.x; a1.y += v1.y; a1.z += v1.z; a1.w += v1.w;
        }
    }
    float inv = 1.f / fmaxf((float)deg, 1.f);
    a0.x *= inv; a0.y *= inv; a0.z *= inv; a0.w *= inv;
    a1.x *= inv; a1.y *= inv; a1.z *= inv; a1.w *= inv;
    float4* op = reinterpret_cast<float4*>(Xmean + (size_t)ed * DD + lane * 8);
    op[0] = a0; op[1] = a1;
}

// -------- fused per-node softmax + aggregate (warp per node) --------
__global__ void node_attn_agg(const float* __restrict__ ef, const float* __restrict__ sn,
                              const float* __restrict__ se, const int* __restrict__ he,
                              const int* __restrict__ permN, const int* __restrict__ offN,
                              const int* __restrict__ cntN, float* __restrict__ attn,
                              float* __restrict__ out, int doLrelu, int nNodes)
{
    int n = blockIdx.x * 8 + (threadIdx.x >> 5);
    if (n >= nNodes) return;
    int lane = threadIdx.x & 31;
    int st = offN[n], deg = cntN[n];
    float4 a0 = make_float4(0.f,0.f,0.f,0.f), a1 = a0;

    if (deg > 0) {
        float s0 = sn[n];
        if (deg <= 32) {
            int inc = 0, ed = 0;
            float sc = -3.4e38f;
            if (lane < deg) {
                inc = permN[st + lane];
                ed = he[inc];
                sc = lrelu_f(s0 + se[ed]);
            }
            float mx = sc;
#pragma unroll
            for (int o = 16; o; o >>= 1) mx = fmaxf(mx, __shfl_xor_sync(0xFFFFFFFFu, mx, o));
            float e = (lane < deg) ? expf(sc - mx) : 0.f;
            float z = e;
#pragma unroll
            for (int o = 16; o; o >>= 1) z += __shfl_xor_sync(0xFFFFFFFFu, z, o);
            float w = e / fmaxf(z, 1e-9f);
            if (lane < deg) attn[inc] = w;
            for (int i = 0; i < deg; i++) {
                int e_   = __shfl_sync(0xFFFFFFFFu, ed, i);
                float w_ = __shfl_sync(0xFFFFFFFFu, w, i);
                const float4* rp = reinterpret_cast<const float4*>(ef + (size_t)e_ * DD + lane * 8);
                float4 v0 = rp[0], v1 = rp[1];
                a0.x += w_*v0.x; a0.y += w_*v0.y; a0.z += w_*v0.z; a0.w += w_*v0.w;
                a1.x += w_*v1.x; a1.y += w_*v1.y; a1.z += w_*v1.z; a1.w += w_*v1.w;
            }
        } else {
            // rare large-degree path: 3 scalar passes + aggregate
            float mx = -3.4e38f;
            for (int base = 0; base < deg; base += 32) {
                float sc = -3.4e38f;
                if (base + lane < deg) {
                    int inc = permN[st + base + lane];
                    sc = lrelu_f(s0 + se[he[inc]]);
                }
                mx = fmaxf(mx, sc);
            }
#pragma unroll
            for (int o = 16; o; o >>= 1) mx = fmaxf(mx, __shfl_xor_sync(0xFFFFFFFFu, mx, o));
            float z = 0.f;
            for (int base = 0; base < deg; base += 32) {
                if (base + lane < deg) {
                    int inc = permN[st + base + lane];
                    z += expf(lrelu_f(s0 + se[he[inc]]) - mx);
                }
            }
#pragma unroll
            for (int o = 16; o; o >>= 1) z += __shfl_xor_sync(0xFFFFFFFFu, z, o);
            float invz = 1.f / fmaxf(z, 1e-9f);
            for (int base = 0; base < deg; base += 32) {
                int m = min(32, deg - base);
                int ed = 0; float w = 0.f;
                if (lane < m) {
                    int inc = permN[st + base + lane];
                    ed = he[inc];
                    w = expf(lrelu_f(s0 + se[ed]) - mx) * invz;
                    attn[inc] = w;
                }
                for (int i = 0; i < m; i++) {
                    int e_   = __shfl_sync(0xFFFFFFFFu, ed, i);
                    float w_ = __shfl_sync(0xFFFFFFFFu, w, i);
                    const float4* rp = reinterpret_cast<const float4*>(ef + (size_t)e_ * DD + lane * 8);
                    float4 v0 = rp[0], v1 = rp[1];
                    a0.x += w_*v0.x; a0.y += w_*v0.y; a0.z += w_*v0.z; a0.w += w_*v0.w;
                    a1.x += w_*v1.x; a1.y += w_*v1.y; a1.z += w_*v1.z; a1.w += w_*v1.w;
                }
            }
        }
    }
    if (doLrelu) {
        a0.x = lrelu_f(a0.x); a0.y = lrelu_f(a0.y); a0.z = lrelu_f(a0.z); a0.w = lrelu_f(a0.w);
        a1.x = lrelu_f(a1.x); a1.y = lrelu_f(a1.y); a1.z = lrelu_f(a1.z); a1.w = lrelu_f(a1.w);
    }
    float4* op = reinterpret_cast<float4*>(out + (size_t)n * DD + lane * 8);
    op[0] = a0; op[1] = a1;
}

// -------- object message gather --------
__global__ void obj_gather(const float* __restrict__ ev, const int* __restrict__ oe_ev,
                           const int* __restrict__ permO, const int* __restrict__ offO,
                           const int* __restrict__ cntO, float* __restrict__ msg, int nObj)
{
    int o = blockIdx.x * 8 + (threadIdx.x >> 5);
    if (o >= nObj) return;
    int lane = threadIdx.x & 31;
    int start = offO[o], deg = cntO[o];
    float4 a0 = make_float4(0.f,0.f,0.f,0.f), a1 = a0;
    for (int base = 0; base < deg; base += 32) {
        int m = min(32, deg - base);
        int src = 0;
        if (lane < m) src = oe_ev[permO[start + base + lane]];
        for (int i = 0; i < m; i++) {
            int row = __shfl_sync(0xFFFFFFFFu, src, i);
            const float4* rp = reinterpret_cast<const float4*>(ev + (size_t)row * DD + lane * 8);
            float4 v0 = rp[0], v1 = rp[1];
            a0.x += v0.x; a0.y += v0.y; a0.z += v0.z; a0.w += v0.w;
            a1.x += v1.x; a1.y += v1.y; a1.z += v1.z; a1.w += v1.w;
        }
    }
    float4* op = reinterpret_cast<float4*>(msg + (size_t)o * DD + lane * 8);
    op[0] = a0; op[1] = a1;
}

// ----------------- host orchestration -----------------
struct Ptrs {
    float *X, *obj, *msg, *H, *ef, *snode, *sedge, *ew, *wav;
    unsigned char* wp;
    int *cntE, *offE, *permE, *cntN, *offN, *permN, *cntO, *offO, *permO, *cur, *bsum;
};

static void get_ptrs(Ptrs& p) {
    cudaGetSymbolAddress((void**)&p.X,     g_X);
    cudaGetSymbolAddress((void**)&p.obj,   g_obj);
    cudaGetSymbolAddress((void**)&p.msg,   g_msg);
    cudaGetSymbolAddress((void**)&p.H,     g_H);
    cudaGetSymbolAddress((void**)&p.ef,    g_ef);
    cudaGetSymbolAddress((void**)&p.snode, g_snode);
    cudaGetSymbolAddress((void**)&p.sedge, g_sedge);
    cudaGetSymbolAddress((void**)&p.ew,    g_ew);
    cudaGetSymbolAddress((void**)&p.wav,   g_wav);
    cudaGetSymbolAddress((void**)&p.wp,    g_Wprep);
    cudaGetSymbolAddress((void**)&p.cntE,  g_cntE);
    cudaGetSymbolAddress((void**)&p.offE,  g_offE);
    cudaGetSymbolAddress((void**)&p.permE, g_permE);
    cudaGetSymbolAddress((void**)&p.cntN,  g_cntN);
    cudaGetSymbolAddress((void**)&p.offN,  g_offN);
    cudaGetSymbolAddress((void**)&p.permN, g_permN);
    cudaGetSymbolAddress((void**)&p.cntO,  g_cntO);
    cudaGetSymbolAddress((void**)&p.offO,  g_offO);
    cudaGetSymbolAddress((void**)&p.permO, g_permO);
    cudaGetSymbolAddress((void**)&p.cur,   g_cur);
    cudaGetSymbolAddress((void**)&p.bsum,  g_bsum);
}

static void build_csr(const int* idx, int n, int nseg,
                      int* cnt, int* off, int* perm, int* cur, int* bsum)
{
    cudaMemsetAsync(cnt, 0, (size_t)nseg * sizeof(int));
    seg_count<<<(n + 255) / 256, 256>>>(idx, cnt, n);
    int nb = (nseg + 1023) / 1024;
    scan_block1024<<<nb, 1024>>>(cnt, off, bsum, nseg);
    scan_small<<<1, 32>>>(bsum, nb);
    add_off<<<(nseg + 255) / 256, 256>>>(off, bsum, nseg);
    cudaMemsetAsync(cur, 0, (size_t)nseg * sizeof(int));
    fill_perm<<<(n + 255) / 256, 256>>>(idx, off, cur, perm, n);
}

template <int FLAGS>
static void launch_tgemm(const float* A, const unsigned char* Wp, const float* bias,
                         const float* R, const float* av, const float* lng, const float* lnb,
                         float* C, float* snode, int Mrows)
{
    cudaFuncSetAttribute(tgemm256<FLAGS>, cudaFuncAttributeMaxDynamicSharedMemorySize, SMEM_SZ);
    tgemm256<FLAGS><<<(Mrows + 127) / 128, 512, SMEM_SZ>>>(A, Wp, bias, R, av, lng, lnb, C, snode, Mrows);
}

// HGNN layer (linearity-restructured):
//   snode = act(X)·(W@a1);  Xmean[ed] = mean(act(X[node]));  ef = Xmean@W (+sedge=ef·a2);
//   out[n] = (lrelu?) softmax-weighted sum of ef.
static void hgnn_layer(const Ptrs& p, const float* Xin, const float* Wraw,
                       const unsigned char* Wp, const float* a,
                       const int* hg_node, const int* hg_edge,
                       float* outbuf, float* attnOut, bool act, bool lreluOut)
{
    prep_wav<<<(DD + 7) / 8, 256>>>(Wraw, a, p.wav);
    snode_dot<<<(NN + 7) / 8, 256>>>(Xin, p.wav, p.snode, NN, act ? 1 : 0);
    edge_gatherX<<<(NE + 7) / 8, 256>>>(Xin, hg_node, p.permE, p.offE, p.cntE,
                                        p.msg, act ? 1 : 0, NE);
    launch_tgemm<F_SNODE>(p.msg, Wp, nullptr, nullptr, a + DD, nullptr, nullptr,
                          p.ef, p.sedge, NE);
    node_attn_agg<<<(NN + 7) / 8, 256>>>(p.ef, p.snode, p.sedge, hg_edge,
                                         p.permN, p.offN, p.cntN,
                                         attnOut, outbuf, lreluOut ? 1 : 0, NN);
}

extern "C" void kernel_launch(void* const* d_in, const int* in_sizes, int n_in,
                              void* d_out, int out_size)
{
    const float* object_X = (const float*)d_in[0];
    const float* event_X  = (const float*)d_in[1];
    const float* Wo = (const float*)d_in[2];  const float* bo  = (const float*)d_in[3];
    const float* go = (const float*)d_in[4];  const float* bon = (const float*)d_in[5];
    const float* We = (const float*)d_in[6];  const float* be  = (const float*)d_in[7];
    const float* ge = (const float*)d_in[8];  const float* ben = (const float*)d_in[9];
    const float* Wu = (const float*)d_in[10]; const float* bu  = (const float*)d_in[11];
    const float* Wl = (const float*)d_in[12]; const float* bl  = (const float*)d_in[13];
    const float* g1 = (const float*)d_in[14]; const float* b1  = (const float*)d_in[15];
    const float* g2 = (const float*)d_in[16]; const float* b2  = (const float*)d_in[17];
    const float* Wh1 = (const float*)d_in[18]; const float* ah1 = (const float*)d_in[19];
    const float* Wh2 = (const float*)d_in[20]; const float* ah2 = (const float*)d_in[21];
    const int* oe_ev   = (const int*)d_in[22];
    const int* oe_obj  = (const int*)d_in[23];
    const int* hg_node = (const int*)d_in[24];
    const int* hg_edge = (const int*)d_in[25];

    Ptrs p; get_ptrs(p);

    // 0) weight prep + CSR builds
    prep_w<<<dim3(32, 6), 256>>>(We, Wo, Wu, Wl, Wh1, Wh2);
    build_csr(hg_edge, E2N, NE, p.cntE, p.offE, p.permE, p.cur, p.bsum);
    build_csr(hg_node, E2N, NN, p.cntN, p.offN, p.permN, p.cur, p.bsum);
    build_csr(oe_obj,  E1N, NO, p.cntO, p.offO, p.permO, p.cur, p.bsum);
    const unsigned char *wpe = p.wp, *wpo = p.wp + 262144, *wpu = p.wp + 2 * 262144,
                        *wpl = p.wp + 3 * 262144, *wph1 = p.wp + 4 * 262144,
                        *wph2 = p.wp + 5 * 262144;

    // 1) ev = LN(lrelu(event_X @ We + be)) -> X[0:NE)
    launch_tgemm<F_BIAS | F_LRELU | F_LN>(event_X, wpe, be, nullptr, nullptr, ge, ben, p.X, nullptr, NE);

    // 2) obj = LN(lrelu(object_X @ Wo + bo))
    launch_tgemm<F_BIAS | F_LRELU | F_LN>(object_X, wpo, bo, nullptr, nullptr, go, bon, p.obj, nullptr, NO);

    // 3) msg = segment_sum(ev[oe_ev], oe_obj)
    obj_gather<<<(NO + 7) / 8, 256>>>(p.X, oe_ev, p.permO, p.offO, p.cntO, p.msg, NO);

    // 4) obj1 = LN(lrelu(msg @ Wu + bu) + obj)
    launch_tgemm<F_BIAS | F_LRELU | F_RES | F_LN>(p.msg, wpu, bu, p.obj, nullptr, g1, b1, p.obj, nullptr, NO);

    // 5) obj2 = LN(lrelu(obj1 @ Wl + bl) + obj1) -> X[NE:NN)
    launch_tgemm<F_BIAS | F_LRELU | F_RES | F_LN>(p.obj, wpl, bl, p.obj, nullptr, g2, b2, p.X + (size_t)NE * DD, nullptr, NO);

    // 6) HGNN layer 1 -> H (pre-lrelu)
    hgnn_layer(p, p.X, Wh1, wph1, ah1, hg_node, hg_edge, p.H, p.ew, false, false);

    // 7) HGNN layer 2 -> d_out (act on input, lrelu on output)
    float* out = (float*)d_out;
    hgnn_layer(p, p.H, Wh2, wph2, ah2, hg_node, hg_edge, out, out + (size_t)NN * DD, true, true);
}

// round 8
// speedup vs baseline: 2.5523x; 1.0320x over previous
#include <cuda_runtime.h>
#include <cuda_bf16.h>
#include <cstdint>

#define DD 256
static const int NE  = 50000;
static const int NO  = 100000;
static const int NN  = 150000;
static const int E1N = 400000;
static const int E2N = 800000;

// -------- device scratch --------
__device__ float    g_X  [(size_t)NN * DD];
__device__ float    g_obj[(size_t)NO * DD];
__device__ float    g_msg[(size_t)NO * DD];   // also Xmean[NE*DD] in hgnn layers
__device__ float    g_H  [(size_t)NN * DD];
__device__ float    g_ef [(size_t)NE * DD];
__device__ float    g_snode[NN];
__device__ float    g_sedge[NE];
__device__ float    g_wav[DD];
__device__ unsigned char g_Wprep[6 * 4 * 2 * 256 * 128];
// CSR structures
__device__ int g_cntE[NE],  g_offE[NE],  g_permE[E2N];
__device__ int g_cntN[NN],  g_offN[NN],  g_permN[E2N];
__device__ int g_cntO[NO],  g_offO[NO],  g_permO[E1N];
__device__ int g_cur[NE + NN + NO];
__device__ int g_bsum[512];

// scan block counts
static const int NBE = (NE + 1023) / 1024;           // 49
static const int NBN = (NN + 1023) / 1024;           // 147
static const int NBO = (NO + 1023) / 1024;           // 98
static const int NBT = NBE + NBN + NBO;              // 294

// -------- helpers --------
__device__ __forceinline__ float lrelu_f(float x) { return x >= 0.f ? x : 0.2f * x; }

__device__ __forceinline__ uint32_t smem_to_u32(const void* p) {
    uint32_t a;
    asm("{ .reg .u64 t; cvta.to.shared.u64 t, %1; cvt.u32.u64 %0, t; }" : "=r"(a) : "l"(p));
    return a;
}
__device__ __forceinline__ void ldm_x4(uint32_t addr, uint32_t* r) {
    asm volatile("ldmatrix.sync.aligned.m8n8.x4.shared.b16 {%0,%1,%2,%3}, [%4];"
                 : "=r"(r[0]), "=r"(r[1]), "=r"(r[2]), "=r"(r[3]) : "r"(addr));
}
__device__ __forceinline__ void mma_bf16(float* c, const uint32_t* a, const uint32_t* b) {
    asm volatile("mma.sync.aligned.m16n8k16.row.col.f32.bf16.bf16.f32 "
                 "{%0,%1,%2,%3}, {%4,%5,%6,%7}, {%8,%9}, {%0,%1,%2,%3};"
                 : "+f"(c[0]), "+f"(c[1]), "+f"(c[2]), "+f"(c[3])
                 : "r"(a[0]), "r"(a[1]), "r"(a[2]), "r"(a[3]), "r"(b[0]), "r"(b[1]));
}
__device__ __forceinline__ uint32_t swz(uint32_t row, uint32_t cb) {
    return row * 128u + (cb ^ ((row & 7u) << 4));
}
__device__ __forceinline__ uint32_t swz512(uint32_t row, uint32_t cb) {
    return row * 512u + (cb ^ ((row & 7u) << 4));
}
#define CP_ASYNC16(dst, src) \
    asm volatile("cp.async.cg.shared.global [%0], [%1], 16;" :: "r"(dst), "l"(src) : "memory")
#define CP_COMMIT() asm volatile("cp.async.commit_group;" ::: "memory")
#define CP_WAIT(n)  asm volatile("cp.async.wait_group %0;" :: "n"(n) : "memory")

enum { F_BIAS = 1, F_LRELU = 2, F_RES = 4, F_LRELUA = 8, F_SNODE = 16, F_LN = 32 };

// ======== condensed CSR build (6 launches total) ========
__global__ void zero_misc()
{
    int g = blockIdx.x * blockDim.x + threadIdx.x;
    if (g < NE) g_cntE[g] = 0;
    else if (g < NE + NN) g_cntN[g - NE] = 0;
    else if (g < NE + NN + NO) g_cntO[g - NE - NN] = 0;
    int h = g - (NE + NN + NO);
    if (h >= 0 && h < NE + NN + NO) g_cur[h] = 0;
}
__global__ void count_all(const int* __restrict__ he, const int* __restrict__ hn,
                          const int* __restrict__ oo)
{
    int t = blockIdx.x * blockDim.x + threadIdx.x;
    if (t < E2N) atomicAdd(&g_cntE[he[t]], 1);
    else if (t < 2 * E2N) atomicAdd(&g_cntN[hn[t - E2N]], 1);
    else if (t < 2 * E2N + E1N) atomicAdd(&g_cntO[oo[t - 2 * E2N]], 1);
}
__global__ void scan_all()
{
    __shared__ int sh[1024];
    int b = blockIdx.x;
    const int* cnt; int* off; int nseg; int lb;
    if (b < NBE)            { cnt = g_cntE; off = g_offE; nseg = NE; lb = b; }
    else if (b < NBE + NBN) { cnt = g_cntN; off = g_offN; nseg = NN; lb = b - NBE; }
    else                    { cnt = g_cntO; off = g_offO; nseg = NO; lb = b - NBE - NBN; }
    int g = lb * 1024 + threadIdx.x;
    int v = (g < nseg) ? cnt[g] : 0;
    sh[threadIdx.x] = v;
    __syncthreads();
#pragma unroll
    for (int o = 1; o < 1024; o <<= 1) {
        int t = (threadIdx.x >= o) ? sh[threadIdx.x - o] : 0;
        __syncthreads();
        sh[threadIdx.x] += t;
        __syncthreads();
    }
    if (g < nseg) off[g] = sh[threadIdx.x] - v;
    if (threadIdx.x == 1023) g_bsum[b] = sh[1023];
}
__global__ void scan_small3()
{
    int t = threadIdx.x;
    int s, e;
    if (t == 0)      { s = 0;          e = NBE; }
    else if (t == 1) { s = NBE;        e = NBE + NBN; }
    else if (t == 2) { s = NBE + NBN;  e = NBT; }
    else return;
    int run = 0;
    for (int i = s; i < e; i++) { int v = g_bsum[i]; g_bsum[i] = run; run += v; }
}
__global__ void add_off_all()
{
    int g = blockIdx.x * blockDim.x + threadIdx.x;
    if (g < NE) g_offE[g] += g_bsum[g >> 10];
    else if (g < NE + NN) {
        int l = g - NE; g_offN[l] += g_bsum[NBE + (l >> 10)];
    } else if (g < NE + NN + NO) {
        int l = g - NE - NN; g_offO[l] += g_bsum[NBE + NBN + (l >> 10)];
    }
}
__global__ void fill_all(const int* __restrict__ he, const int* __restrict__ hn,
                         const int* __restrict__ oo)
{
    int t = blockIdx.x * blockDim.x + threadIdx.x;
    if (t < E2N) {
        int s = he[t];
        g_permE[g_offE[s] + atomicAdd(&g_cur[s], 1)] = t;
    } else if (t < 2 * E2N) {
        int e = t - E2N;
        int s = hn[e];
        g_permN[g_offN[s] + atomicAdd(&g_cur[NE + s], 1)] = e;
    } else if (t < 2 * E2N + E1N) {
        int e = t - 2 * E2N;
        int s = oo[e];
        g_permO[g_offO[s] + atomicAdd(&g_cur[NE + NN + s], 1)] = e;
    }
}

// -------- weight prep --------
__global__ void prep_w(const float* W0, const float* W1, const float* W2,
                       const float* W3, const float* W4, const float* W5)
{
    const float* Ws[6] = {W0, W1, W2, W3, W4, W5};
    const float* W = Ws[blockIdx.y];
    unsigned char* base = g_Wprep + (size_t)blockIdx.y * 262144;
    int g = blockIdx.x * 256 + threadIdx.x;
    int n = g >> 5, kg = g & 31, k0 = kg * 8;
    unsigned short hi[8], lo[8];
#pragma unroll
    for (int i = 0; i < 8; i++) {
        float x = W[(size_t)(k0 + i) * DD + n];
        __nv_bfloat16 h = __float2bfloat16(x);
        __nv_bfloat16 l = __float2bfloat16(x - __bfloat162float(h));
        hi[i] = *reinterpret_cast<unsigned short*>(&h);
        lo[i] = *reinterpret_cast<unsigned short*>(&l);
    }
    int chunk = k0 >> 6, kc = k0 & 63;
    uint32_t off = (uint32_t)n * 128u + (((uint32_t)kc * 2u) ^ (((uint32_t)n & 7u) << 4));
    *reinterpret_cast<uint4*>(base + (size_t)(chunk * 2 + 0) * 32768 + off) =
        *reinterpret_cast<uint4*>(hi);
    *reinterpret_cast<uint4*>(base + (size_t)(chunk * 2 + 1) * 32768 + off) =
        *reinterpret_cast<uint4*>(lo);
}

__global__ void prep_wav(const float* __restrict__ W, const float* __restrict__ a,
                         float* __restrict__ w)
{
    int k = blockIdx.x * 8 + (threadIdx.x >> 5);
    if (k >= DD) return;
    int lane = threadIdx.x & 31;
    const float4* rp = reinterpret_cast<const float4*>(W + (size_t)k * DD);
    const float4* ap = reinterpret_cast<const float4*>(a);
    float4 v0 = rp[lane], v1 = rp[lane + 32];
    float4 a0 = ap[lane], a1 = ap[lane + 32];
    float d = v0.x*a0.x + v0.y*a0.y + v0.z*a0.z + v0.w*a0.w
            + v1.x*a1.x + v1.y*a1.y + v1.z*a1.z + v1.w*a1.w;
#pragma unroll
    for (int o = 16; o; o >>= 1) d += __shfl_xor_sync(0xFFFFFFFFu, d, o);
    if (lane == 0) w[k] = d;
}

__global__ void snode_dot(const float* __restrict__ X, const float* __restrict__ w,
                          float* __restrict__ snode, int rows, int act)
{
    int row = blockIdx.x * 8 + (threadIdx.x >> 5);
    if (row >= rows) return;
    int lane = threadIdx.x & 31;
    const float4* rp = reinterpret_cast<const float4*>(X + (size_t)row * DD);
    const float4* ap = reinterpret_cast<const float4*>(w);
    float4 v0 = rp[lane], v1 = rp[lane + 32];
    if (act) {
        v0.x = lrelu_f(v0.x); v0.y = lrelu_f(v0.y); v0.z = lrelu_f(v0.z); v0.w = lrelu_f(v0.w);
        v1.x = lrelu_f(v1.x); v1.y = lrelu_f(v1.y); v1.z = lrelu_f(v1.z); v1.w = lrelu_f(v1.w);
    }
    float4 a0 = ap[lane], a1 = ap[lane + 32];
    float d = v0.x*a0.x + v0.y*a0.y + v0.z*a0.z + v0.w*a0.w
            + v1.x*a1.x + v1.y*a1.y + v1.z*a1.z + v1.w*a1.w;
#pragma unroll
    for (int o = 16; o; o >>= 1) d += __shfl_xor_sync(0xFFFFFFFFu, d, o);
    if (lane == 0) snode[row] = d;
}

// ======== single GEMM (steps 1,2 + hgnn edge GEMM) ========
static const int SMEM_SZ = 196608;

template <int FLAGS>
__global__ __launch_bounds__(512, 1)
void tgemm256(const float* __restrict__ A, const unsigned char* __restrict__ Wp,
              const float* __restrict__ bias, const float* __restrict__ R,
              const float* __restrict__ av, const float* __restrict__ lng,
              const float* __restrict__ lnb, float* __restrict__ C,
              float* __restrict__ snode, int Mrows)
{
    extern __shared__ __align__(128) unsigned char smem[];
    const uint32_t sb = smem_to_u32(smem);
    const int tid = threadIdx.x, lane = tid & 31, wid = tid >> 5;
    const int warpM = wid >> 2, warpN = wid & 3;
    const int rowBase = blockIdx.x * 128;

    int rA[2], cgA[2];
#pragma unroll
    for (int i = 0; i < 2; i++) {
        int g = tid + i * 512;
        rA[i] = g >> 3; cgA[i] = g & 7;
    }
    float4 pref[4];

    auto issueA = [&](int ch) {
#pragma unroll
        for (int i = 0; i < 2; i++) {
            int row = rowBase + rA[i];
            if (row < Mrows) {
                const float4* src = reinterpret_cast<const float4*>(
                    A + (size_t)row * DD + ch * 64 + cgA[i] * 8);
                pref[i * 2]     = src[0];
                pref[i * 2 + 1] = src[1];
            } else {
                pref[i * 2]     = make_float4(0.f, 0.f, 0.f, 0.f);
                pref[i * 2 + 1] = make_float4(0.f, 0.f, 0.f, 0.f);
            }
        }
    };
    auto storeA = [&](int s) {
#pragma unroll
        for (int i = 0; i < 2; i++) {
            float x[8];
            float4 v0 = pref[i * 2], v1 = pref[i * 2 + 1];
            x[0] = v0.x; x[1] = v0.y; x[2] = v0.z; x[3] = v0.w;
            x[4] = v1.x; x[5] = v1.y; x[6] = v1.z; x[7] = v1.w;
            unsigned short hi[8], lo[8];
#pragma unroll
            for (int j = 0; j < 8; j++) {
                if (FLAGS & F_LRELUA) x[j] = lrelu_f(x[j]);
                __nv_bfloat16 h = __float2bfloat16(x[j]);
                __nv_bfloat16 l = __float2bfloat16(x[j] - __bfloat162float(h));
                hi[j] = *reinterpret_cast<unsigned short*>(&h);
                lo[j] = *reinterpret_cast<unsigned short*>(&l);
            }
            uint32_t off = s * 32768u + swz((uint32_t)rA[i], (uint32_t)cgA[i] * 16u);
            *reinterpret_cast<uint4*>(smem + off)         = *reinterpret_cast<uint4*>(hi);
            *reinterpret_cast<uint4*>(smem + 16384 + off) = *reinterpret_cast<uint4*>(lo);
        }
    };
    auto issueB = [&](int ch, int s) {
        const unsigned char* bh = Wp + (size_t)(ch * 2 + 0) * 32768;
        const unsigned char* bl = Wp + (size_t)(ch * 2 + 1) * 32768;
        uint32_t dh = sb + 65536u + (uint32_t)s * 65536u;
        uint32_t dl = dh + 32768u;
#pragma unroll
        for (int i = 0; i < 4; i++) {
            int idx = (tid + i * 512) * 16;
            CP_ASYNC16(dh + idx, bh + idx);
            CP_ASYNC16(dl + idx, bl + idx);
        }
        CP_COMMIT();
    };

    float c[2][8][4];
#pragma unroll
    for (int mt = 0; mt < 2; mt++)
#pragma unroll
        for (int nt = 0; nt < 8; nt++)
#pragma unroll
            for (int q = 0; q < 4; q++) c[mt][nt][q] = 0.f;

    issueA(0);
    issueB(0, 0);
    storeA(0);

    for (int ch = 0; ch < 4; ch++) {
        const int s = ch & 1;
        if (ch < 3) {
            issueA(ch + 1);
            issueB(ch + 1, s ^ 1);
            CP_WAIT(1);
        } else {
            CP_WAIT(0);
        }
        __syncthreads();

        const uint32_t aBase = sb + (uint32_t)s * 32768u;
        const uint32_t bBase = sb + 65536u + (uint32_t)s * 65536u;
#pragma unroll
        for (int ks = 0; ks < 4; ks++) {
            uint32_t ah[2][4], al[2][4];
#pragma unroll
            for (int mt = 0; mt < 2; mt++) {
                uint32_t row = (uint32_t)(warpM * 32 + mt * 16 + (lane & 7) + ((lane >> 3) & 1) * 8);
                uint32_t kb  = (uint32_t)(ks * 32 + ((lane >> 4) & 1) * 16);
                uint32_t addr = aBase + swz(row, kb);
                ldm_x4(addr,         ah[mt]);
                ldm_x4(addr + 16384, al[mt]);
            }
#pragma unroll
            for (int p = 0; p < 4; p++) {
                uint32_t nrow = (uint32_t)(warpN * 64 + p * 16 + (lane & 7) + ((lane >> 4) & 1) * 8);
                uint32_t kb   = (uint32_t)(ks * 32 + ((lane >> 3) & 1) * 16);
                uint32_t addr = bBase + swz(nrow, kb);
                uint32_t bh[4], bl[4];
                ldm_x4(addr,         bh);
                ldm_x4(addr + 32768, bl);
#pragma unroll
                for (int t = 0; t < 2; t++) {
                    const uint32_t* Bh = bh + t * 2;
                    const uint32_t* Bl = bl + t * 2;
#pragma unroll
                    for (int mt = 0; mt < 2; mt++) {
                        float* cc = c[mt][p * 2 + t];
                        mma_bf16(cc, ah[mt], Bh);
                        mma_bf16(cc, ah[mt], Bl);
                        mma_bf16(cc, al[mt], Bh);
                    }
                }
            }
        }
        if (ch < 3) storeA(s ^ 1);
        __syncthreads();
    }

    const int gid = lane >> 2, tig = lane & 3;
    float2* rb = reinterpret_cast<float2*>(smem);

#pragma unroll
    for (int mt = 0; mt < 2; mt++) {
        int r0 = rowBase + warpM * 32 + mt * 16 + gid;
        int r1 = r0 + 8;
        bool v0 = r0 < Mrows, v1 = r1 < Mrows;
#pragma unroll
        for (int nt = 0; nt < 8; nt++) {
            int col = warpN * 64 + nt * 8 + tig * 2;
            float o0 = c[mt][nt][0], o1 = c[mt][nt][1];
            float o2 = c[mt][nt][2], o3 = c[mt][nt][3];
            if (FLAGS & F_BIAS) {
                float2 bv = *reinterpret_cast<const float2*>(bias + col);
                o0 += bv.x; o1 += bv.y; o2 += bv.x; o3 += bv.y;
            }
            if (FLAGS & F_LRELU) {
                o0 = lrelu_f(o0); o1 = lrelu_f(o1); o2 = lrelu_f(o2); o3 = lrelu_f(o3);
            }
            if (FLAGS & F_RES) {
                if (v0) {
                    float2 rv = *reinterpret_cast<const float2*>(R + (size_t)r0 * DD + col);
                    o0 += rv.x; o1 += rv.y;
                }
                if (v1) {
                    float2 rv = *reinterpret_cast<const float2*>(R + (size_t)r1 * DD + col);
                    o2 += rv.x; o3 += rv.y;
                }
            }
            c[mt][nt][0] = o0; c[mt][nt][1] = o1; c[mt][nt][2] = o2; c[mt][nt][3] = o3;
            if (!(FLAGS & F_LN)) {
                if (v0) *reinterpret_cast<float2*>(C + (size_t)r0 * DD + col) = make_float2(o0, o1);
                if (v1) *reinterpret_cast<float2*>(C + (size_t)r1 * DD + col) = make_float2(o2, o3);
            }
        }
    }

    if (FLAGS & F_SNODE) {
#pragma unroll
        for (int mt = 0; mt < 2; mt++) {
            float s0 = 0.f, s1 = 0.f;
#pragma unroll
            for (int nt = 0; nt < 8; nt++) {
                int col = warpN * 64 + nt * 8 + tig * 2;
                float2 avv = *reinterpret_cast<const float2*>(av + col);
                s0 += c[mt][nt][0] * avv.x + c[mt][nt][1] * avv.y;
                s1 += c[mt][nt][2] * avv.x + c[mt][nt][3] * avv.y;
            }
#pragma unroll
            for (int o = 1; o < 4; o <<= 1) {
                s0 += __shfl_xor_sync(0xFFFFFFFFu, s0, o);
                s1 += __shfl_xor_sync(0xFFFFFFFFu, s1, o);
            }
            if (tig == 0) {
                int lr0 = warpM * 32 + mt * 16 + gid;
                rb[lr0 * 4 + warpN]       = make_float2(s0, 0.f);
                rb[(lr0 + 8) * 4 + warpN] = make_float2(s1, 0.f);
            }
        }
        __syncthreads();
        if (warpN == 0 && tig == 0) {
#pragma unroll
            for (int mt = 0; mt < 2; mt++) {
                int lr0 = warpM * 32 + mt * 16 + gid;
#pragma unroll
                for (int h = 0; h < 2; h++) {
                    int lr = lr0 + h * 8;
                    int row = rowBase + lr;
                    if (row < Mrows) {
                        float s = rb[lr * 4 + 0].x + rb[lr * 4 + 1].x
                                + rb[lr * 4 + 2].x + rb[lr * 4 + 3].x;
                        snode[row] = s;
                    }
                }
            }
        }
    }

    if (FLAGS & F_LN) {
#pragma unroll
        for (int mt = 0; mt < 2; mt++) {
            float s0 = 0.f, q0 = 0.f, s1 = 0.f, q1 = 0.f;
#pragma unroll
            for (int nt = 0; nt < 8; nt++) {
                float o0 = c[mt][nt][0], o1 = c[mt][nt][1];
                float o2 = c[mt][nt][2], o3 = c[mt][nt][3];
                s0 += o0 + o1; q0 += o0 * o0 + o1 * o1;
                s1 += o2 + o3; q1 += o2 * o2 + o3 * o3;
            }
#pragma unroll
            for (int o = 1; o < 4; o <<= 1) {
                s0 += __shfl_xor_sync(0xFFFFFFFFu, s0, o);
                q0 += __shfl_xor_sync(0xFFFFFFFFu, q0, o);
                s1 += __shfl_xor_sync(0xFFFFFFFFu, s1, o);
                q1 += __shfl_xor_sync(0xFFFFFFFFu, q1, o);
            }
            if (tig == 0) {
                int lr0 = warpM * 32 + mt * 16 + gid;
                rb[lr0 * 4 + warpN]       = make_float2(s0, q0);
                rb[(lr0 + 8) * 4 + warpN] = make_float2(s1, q1);
            }
        }
        __syncthreads();
#pragma unroll
        for (int mt = 0; mt < 2; mt++) {
            int lr0 = warpM * 32 + mt * 16 + gid;
            int lr1 = lr0 + 8;
            float2 p00 = rb[lr0*4+0], p01 = rb[lr0*4+1], p02 = rb[lr0*4+2], p03 = rb[lr0*4+3];
            float2 p10 = rb[lr1*4+0], p11 = rb[lr1*4+1], p12 = rb[lr1*4+2], p13 = rb[lr1*4+3];
            float sum0 = p00.x + p01.x + p02.x + p03.x;
            float sq0  = p00.y + p01.y + p02.y + p03.y;
            float sum1 = p10.x + p11.x + p12.x + p13.x;
            float sq1  = p10.y + p11.y + p12.y + p13.y;
            float mean0 = sum0 * (1.f / 256.f);
            float var0  = sq0 * (1.f / 256.f) - mean0 * mean0;
            float rstd0 = rsqrtf(var0 + 1e-5f);
            float mean1 = sum1 * (1.f / 256.f);
            float var1  = sq1 * (1.f / 256.f) - mean1 * mean1;
            float rstd1 = rsqrtf(var1 + 1e-5f);
            int r0 = rowBase + lr0, r1 = rowBase + lr1;
            bool v0 = r0 < Mrows, v1 = r1 < Mrows;
#pragma unroll
            for (int nt = 0; nt < 8; nt++) {
                int col = warpN * 64 + nt * 8 + tig * 2;
                float2 gv = *reinterpret_cast<const float2*>(lng + col);
                float2 bv = *reinterpret_cast<const float2*>(lnb + col);
                if (v0) {
                    float o0 = (c[mt][nt][0] - mean0) * rstd0 * gv.x + bv.x;
                    float o1 = (c[mt][nt][1] - mean0) * rstd0 * gv.y + bv.y;
                    *reinterpret_cast<float2*>(C + (size_t)r0 * DD + col) = make_float2(o0, o1);
                }
                if (v1) {
                    float o2 = (c[mt][nt][2] - mean1) * rstd1 * gv.x + bv.x;
                    float o3 = (c[mt][nt][3] - mean1) * rstd1 * gv.y + bv.y;
                    *reinterpret_cast<float2*>(C + (size_t)r1 * DD + col) = make_float2(o2, o3);
                }
            }
        }
    }
}

// ======== fused dual GEMM: obj2 = LN2(lrelu(LN1(lrelu(msg@Wu+bu)+obj)@Wl+bl)+obj1) ========
// Phase-1 smem: B1[s] at s*65536 (hi/lo 32K each); A1[s] at 131072+s*32768 (hi/lo 16K each).
// Phase-2 smem: A2 (obj1 bf16) hi [0,64K) lo [64K,128K), 512 B/row swizzled; B2 at [128K,192K).
__global__ __launch_bounds__(512, 1)
void tgemm_dual(const float* __restrict__ A, const unsigned char* __restrict__ Wp1,
                const float* __restrict__ bias1, const float* __restrict__ R1,
                const float* __restrict__ lng1, const float* __restrict__ lnb1,
                const unsigned char* __restrict__ Wp2, const float* __restrict__ bias2,
                const float* __restrict__ lng2, const float* __restrict__ lnb2,
                float* __restrict__ C2, int Mrows)
{
    extern __shared__ __align__(128) unsigned char smem[];
    const uint32_t sb = smem_to_u32(smem);
    const int tid = threadIdx.x, lane = tid & 31, wid = tid >> 5;
    const int warpM = wid >> 2, warpN = wid & 3;
    const int rowBase = blockIdx.x * 128;

    int rA[2], cgA[2];
#pragma unroll
    for (int i = 0; i < 2; i++) {
        int g = tid + i * 512;
        rA[i] = g >> 3; cgA[i] = g & 7;
    }
    float4 pref[4];

    auto issueA = [&](int ch) {
#pragma unroll
        for (int i = 0; i < 2; i++) {
            int row = rowBase + rA[i];
            if (row < Mrows) {
                const float4* src = reinterpret_cast<const float4*>(
                    A + (size_t)row * DD + ch * 64 + cgA[i] * 8);
                pref[i * 2]     = src[0];
                pref[i * 2 + 1] = src[1];
            } else {
                pref[i * 2]     = make_float4(0.f, 0.f, 0.f, 0.f);
                pref[i * 2 + 1] = make_float4(0.f, 0.f, 0.f, 0.f);
            }
        }
    };
    auto storeA = [&](int s) {
#pragma unroll
        for (int i = 0; i < 2; i++) {
            float x[8];
            float4 v0 = pref[i * 2], v1 = pref[i * 2 + 1];
            x[0] = v0.x; x[1] = v0.y; x[2] = v0.z; x[3] = v0.w;
            x[4] = v1.x; x[5] = v1.y; x[6] = v1.z; x[7] = v1.w;
            unsigned short hi[8], lo[8];
#pragma unroll
            for (int j = 0; j < 8; j++) {
                __nv_bfloat16 h = __float2bfloat16(x[j]);
                __nv_bfloat16 l = __float2bfloat16(x[j] - __bfloat162float(h));
                hi[j] = *reinterpret_cast<unsigned short*>(&h);
                lo[j] = *reinterpret_cast<unsigned short*>(&l);
            }
            uint32_t off = 131072u + s * 32768u + swz((uint32_t)rA[i], (uint32_t)cgA[i] * 16u);
            *reinterpret_cast<uint4*>(smem + off)         = *reinterpret_cast<uint4*>(hi);
            *reinterpret_cast<uint4*>(smem + 16384 + off) = *reinterpret_cast<uint4*>(lo);
        }
    };
    auto issueB1 = [&](int ch, int s) {
        const unsigned char* bh = Wp1 + (size_t)(ch * 2 + 0) * 32768;
        const unsigned char* bl = Wp1 + (size_t)(ch * 2 + 1) * 32768;
        uint32_t dh = sb + (uint32_t)s * 65536u;
        uint32_t dl = dh + 32768u;
#pragma unroll
        for (int i = 0; i < 4; i++) {
            int idx = (tid + i * 512) * 16;
            CP_ASYNC16(dh + idx, bh + idx);
            CP_ASYNC16(dl + idx, bl + idx);
        }
        CP_COMMIT();
    };
    auto issueB2 = [&](int ch) {
        const unsigned char* bh = Wp2 + (size_t)(ch * 2 + 0) * 32768;
        const unsigned char* bl = Wp2 + (size_t)(ch * 2 + 1) * 32768;
        uint32_t dh = sb + 131072u;
        uint32_t dl = dh + 32768u;
#pragma unroll
        for (int i = 0; i < 4; i++) {
            int idx = (tid + i * 512) * 16;
            CP_ASYNC16(dh + idx, bh + idx);
            CP_ASYNC16(dl + idx, bl + idx);
        }
        CP_COMMIT();
    };

    float c[2][8][4];
#pragma unroll
    for (int mt = 0; mt < 2; mt++)
#pragma unroll
        for (int nt = 0; nt < 8; nt++)
#pragma unroll
            for (int q = 0; q < 4; q++) c[mt][nt][q] = 0.f;

    // ---- phase 1 ----
    issueA(0);
    issueB1(0, 0);
    storeA(0);

    for (int ch = 0; ch < 4; ch++) {
        const int s = ch & 1;
        if (ch < 3) {
            issueA(ch + 1);
            issueB1(ch + 1, s ^ 1);
            CP_WAIT(1);
        } else {
            CP_WAIT(0);
        }
        __syncthreads();

        const uint32_t aBase = sb + 131072u + (uint32_t)s * 32768u;
        const uint32_t bBase = sb + (uint32_t)s * 65536u;
#pragma unroll
        for (int ks = 0; ks < 4; ks++) {
            uint32_t ah[2][4], al[2][4];
#pragma unroll
            for (int mt = 0; mt < 2; mt++) {
                uint32_t row = (uint32_t)(warpM * 32 + mt * 16 + (lane & 7) + ((lane >> 3) & 1) * 8);
                uint32_t kb  = (uint32_t)(ks * 32 + ((lane >> 4) & 1) * 16);
                uint32_t addr = aBase + swz(row, kb);
                ldm_x4(addr,         ah[mt]);
                ldm_x4(addr + 16384, al[mt]);
            }
#pragma unroll
            for (int p = 0; p < 4; p++) {
                uint32_t nrow = (uint32_t)(warpN * 64 + p * 16 + (lane & 7) + ((lane >> 4) & 1) * 8);
                uint32_t kb   = (uint32_t)(ks * 32 + ((lane >> 3) & 1) * 16);
                uint32_t addr = bBase + swz(nrow, kb);
                uint32_t bh[4], bl[4];
                ldm_x4(addr,         bh);
                ldm_x4(addr + 32768, bl);
#pragma unroll
                for (int t = 0; t < 2; t++) {
#pragma unroll
                    for (int mt = 0; mt < 2; mt++) {
                        float* cc = c[mt][p * 2 + t];
                        mma_bf16(cc, ah[mt], bh + t * 2);
                        mma_bf16(cc, ah[mt], bl + t * 2);
                        mma_bf16(cc, al[mt], bh + t * 2);
                    }
                }
            }
        }
        if (ch < 3) storeA(s ^ 1);
        __syncthreads();
    }

    // ---- epilogue 1: bias + lrelu + residual(R1) + LN1 -> obj1 in regs ----
    const int gid = lane >> 2, tig = lane & 3;
    float2* rb = reinterpret_cast<float2*>(smem + 131072);

#pragma unroll
    for (int mt = 0; mt < 2; mt++) {
        int r0 = rowBase + warpM * 32 + mt * 16 + gid;
        int r1 = r0 + 8;
        bool v0 = r0 < Mrows, v1 = r1 < Mrows;
#pragma unroll
        for (int nt = 0; nt < 8; nt++) {
            int col = warpN * 64 + nt * 8 + tig * 2;
            float2 bv = *reinterpret_cast<const float2*>(bias1 + col);
            float o0 = lrelu_f(c[mt][nt][0] + bv.x), o1 = lrelu_f(c[mt][nt][1] + bv.y);
            float o2 = lrelu_f(c[mt][nt][2] + bv.x), o3 = lrelu_f(c[mt][nt][3] + bv.y);
            if (v0) {
                float2 rv = *reinterpret_cast<const float2*>(R1 + (size_t)r0 * DD + col);
                o0 += rv.x; o1 += rv.y;
            }
            if (v1) {
                float2 rv = *reinterpret_cast<const float2*>(R1 + (size_t)r1 * DD + col);
                o2 += rv.x; o3 += rv.y;
            }
            c[mt][nt][0] = o0; c[mt][nt][1] = o1; c[mt][nt][2] = o2; c[mt][nt][3] = o3;
        }
    }
    // LN1 stats
#pragma unroll
    for (int mt = 0; mt < 2; mt++) {
        float s0 = 0.f, q0 = 0.f, s1 = 0.f, q1 = 0.f;
#pragma unroll
        for (int nt = 0; nt < 8; nt++) {
            float o0 = c[mt][nt][0], o1 = c[mt][nt][1];
            float o2 = c[mt][nt][2], o3 = c[mt][nt][3];
            s0 += o0 + o1; q0 += o0 * o0 + o1 * o1;
            s1 += o2 + o3; q1 += o2 * o2 + o3 * o3;
        }
#pragma unroll
        for (int o = 1; o < 4; o <<= 1) {
            s0 += __shfl_xor_sync(0xFFFFFFFFu, s0, o);
            q0 += __shfl_xor_sync(0xFFFFFFFFu, q0, o);
            s1 += __shfl_xor_sync(0xFFFFFFFFu, s1, o);
            q1 += __shfl_xor_sync(0xFFFFFFFFu, q1, o);
        }
        if (tig == 0) {
            int lr0 = warpM * 32 + mt * 16 + gid;
            rb[lr0 * 4 + warpN]       = make_float2(s0, q0);
            rb[(lr0 + 8) * 4 + warpN] = make_float2(s1, q1);
        }
    }
    __syncthreads();
#pragma unroll
    for (int mt = 0; mt < 2; mt++) {
        int lr0 = warpM * 32 + mt * 16 + gid;
        int lr1 = lr0 + 8;
        float2 p00 = rb[lr0*4+0], p01 = rb[lr0*4+1], p02 = rb[lr0*4+2], p03 = rb[lr0*4+3];
        float2 p10 = rb[lr1*4+0], p11 = rb[lr1*4+1], p12 = rb[lr1*4+2], p13 = rb[lr1*4+3];
        float sum0 = p00.x + p01.x + p02.x + p03.x;
        float sq0  = p00.y + p01.y + p02.y + p03.y;
        float sum1 = p10.x + p11.x + p12.x + p13.x;
        float sq1  = p10.y + p11.y + p12.y + p13.y;
        float mean0 = sum0 * (1.f / 256.f);
        float rstd0 = rsqrtf(sq0 * (1.f / 256.f) - mean0 * mean0 + 1e-5f);
        float mean1 = sum1 * (1.f / 256.f);
        float rstd1 = rsqrtf(sq1 * (1.f / 256.f) - mean1 * mean1 + 1e-5f);
#pragma unroll
        for (int nt = 0; nt < 8; nt++) {
            int col = warpN * 64 + nt * 8 + tig * 2;
            float2 gv = *reinterpret_cast<const float2*>(lng1 + col);
            float2 bv = *reinterpret_cast<const float2*>(lnb1 + col);
            c[mt][nt][0] = (c[mt][nt][0] - mean0) * rstd0 * gv.x + bv.x;
            c[mt][nt][1] = (c[mt][nt][1] - mean0) * rstd0 * gv.y + bv.y;
            c[mt][nt][2] = (c[mt][nt][2] - mean1) * rstd1 * gv.x + bv.x;
            c[mt][nt][3] = (c[mt][nt][3] - mean1) * rstd1 * gv.y + bv.y;
        }
    }
    __syncthreads();   // rb consumed; smem free

    // ---- store obj1 to A2 smem (hi/lo bf16, 512B rows) + issue B2 chunk 0 ----
    issueB2(0);
#pragma unroll
    for (int mt = 0; mt < 2; mt++) {
        uint32_t lr0 = (uint32_t)(warpM * 32 + mt * 16 + gid);
        uint32_t lr1 = lr0 + 8;
#pragma unroll
        for (int nt = 0; nt < 8; nt++) {
            uint32_t cb = (uint32_t)(warpN * 64 + nt * 8 + tig * 2) * 2u;
            float o0 = c[mt][nt][0], o1 = c[mt][nt][1];
            float o2 = c[mt][nt][2], o3 = c[mt][nt][3];
            __nv_bfloat16 h0 = __float2bfloat16(o0), h1 = __float2bfloat16(o1);
            __nv_bfloat16 h2 = __float2bfloat16(o2), h3 = __float2bfloat16(o3);
            __nv_bfloat16 l0 = __float2bfloat16(o0 - __bfloat162float(h0));
            __nv_bfloat16 l1 = __float2bfloat16(o1 - __bfloat162float(h1));
            __nv_bfloat16 l2 = __float2bfloat16(o2 - __bfloat162float(h2));
            __nv_bfloat16 l3 = __float2bfloat16(o3 - __bfloat162float(h3));
            uint32_t hp0 = ((uint32_t)*reinterpret_cast<unsigned short*>(&h1) << 16)
                         |  (uint32_t)*reinterpret_cast<unsigned short*>(&h0);
            uint32_t lp0 = ((uint32_t)*reinterpret_cast<unsigned short*>(&l1) << 16)
                         |  (uint32_t)*reinterpret_cast<unsigned short*>(&l0);
            uint32_t hp1 = ((uint32_t)*reinterpret_cast<unsigned short*>(&h3) << 16)
                         |  (uint32_t)*reinterpret_cast<unsigned short*>(&h2);
            uint32_t lp1 = ((uint32_t)*reinterpret_cast<unsigned short*>(&l3) << 16)
                         |  (uint32_t)*reinterpret_cast<unsigned short*>(&l2);
            *reinterpret_cast<uint32_t*>(smem + swz512(lr0, cb))           = hp0;
            *reinterpret_cast<uint32_t*>(smem + 65536u + swz512(lr0, cb))  = lp0;
            *reinterpret_cast<uint32_t*>(smem + swz512(lr1, cb))           = hp1;
            *reinterpret_cast<uint32_t*>(smem + 65536u + swz512(lr1, cb))  = lp1;
        }
    }
    // reset accumulators for phase 2
#pragma unroll
    for (int mt = 0; mt < 2; mt++)
#pragma unroll
        for (int nt = 0; nt < 8; nt++)
#pragma unroll
            for (int q = 0; q < 4; q++) c[mt][nt][q] = 0.f;
    __syncthreads();

    // ---- phase 2: obj1 @ Wl ----
    for (int ch = 0; ch < 4; ch++) {
        CP_WAIT(0);
        __syncthreads();
        const uint32_t bBase = sb + 131072u;
#pragma unroll
        for (int ks = 0; ks < 4; ks++) {
            uint32_t ah[2][4], al[2][4];
#pragma unroll
            for (int mt = 0; mt < 2; mt++) {
                uint32_t row = (uint32_t)(warpM * 32 + mt * 16 + (lane & 7) + ((lane >> 3) & 1) * 8);
                uint32_t kb  = (uint32_t)(ch * 128 + ks * 32 + ((lane >> 4) & 1) * 16);
                uint32_t addr = sb + swz512(row, kb);
                ldm_x4(addr,          ah[mt]);
                ldm_x4(addr + 65536u, al[mt]);
            }
#pragma unroll
            for (int p = 0; p < 4; p++) {
                uint32_t nrow = (uint32_t)(warpN * 64 + p * 16 + (lane & 7) + ((lane >> 4) & 1) * 8);
                uint32_t kb   = (uint32_t)(ks * 32 + ((lane >> 3) & 1) * 16);
                uint32_t addr = bBase + swz(nrow, kb);
                uint32_t bh[4], bl[4];
                ldm_x4(addr,          bh);
                ldm_x4(addr + 32768u, bl);
#pragma unroll
                for (int t = 0; t < 2; t++) {
#pragma unroll
                    for (int mt = 0; mt < 2; mt++) {
                        float* cc = c[mt][p * 2 + t];
                        mma_bf16(cc, ah[mt], bh + t * 2);
                        mma_bf16(cc, ah[mt], bl + t * 2);
                        mma_bf16(cc, al[mt], bh + t * 2);
                    }
                }
            }
        }
        __syncthreads();
        if (ch < 3) issueB2(ch + 1);
    }

    // ---- epilogue 2: bias2 + lrelu + residual(obj1 from smem) + LN2 -> C2 ----
#pragma unroll
    for (int mt = 0; mt < 2; mt++) {
        uint32_t lr0 = (uint32_t)(warpM * 32 + mt * 16 + gid);
        uint32_t lr1 = lr0 + 8;
#pragma unroll
        for (int nt = 0; nt < 8; nt++) {
            int col = warpN * 64 + nt * 8 + tig * 2;
            uint32_t cb = (uint32_t)col * 2u;
            float2 bv = *reinterpret_cast<const float2*>(bias2 + col);
            float o0 = lrelu_f(c[mt][nt][0] + bv.x), o1 = lrelu_f(c[mt][nt][1] + bv.y);
            float o2 = lrelu_f(c[mt][nt][2] + bv.x), o3 = lrelu_f(c[mt][nt][3] + bv.y);
            uint32_t hp0 = *reinterpret_cast<uint32_t*>(smem + swz512(lr0, cb));
            uint32_t lp0 = *reinterpret_cast<uint32_t*>(smem + 65536u + swz512(lr0, cb));
            uint32_t hp1 = *reinterpret_cast<uint32_t*>(smem + swz512(lr1, cb));
            uint32_t lp1 = *reinterpret_cast<uint32_t*>(smem + 65536u + swz512(lr1, cb));
            unsigned short u;
            u = (unsigned short)(hp0 & 0xFFFF);
            float r0a = __bfloat162float(*reinterpret_cast<__nv_bfloat16*>(&u));
            u = (unsigned short)(lp0 & 0xFFFF);
            r0a += __bfloat162float(*reinterpret_cast<__nv_bfloat16*>(&u));
            u = (unsigned short)(hp0 >> 16);
            float r0b = __bfloat162float(*reinterpret_cast<__nv_bfloat16*>(&u));
            u = (unsigned short)(lp0 >> 16);
            r0b += __bfloat162float(*reinterpret_cast<__nv_bfloat16*>(&u));
            u = (unsigned short)(hp1 & 0xFFFF);
            float r1a = __bfloat162float(*reinterpret_cast<__nv_bfloat16*>(&u));
            u = (unsigned short)(lp1 & 0xFFFF);
            r1a += __bfloat162float(*reinterpret_cast<__nv_bfloat16*>(&u));
            u = (unsigned short)(hp1 >> 16);
            float r1b = __bfloat162float(*reinterpret_cast<__nv_bfloat16*>(&u));
            u = (unsigned short)(lp1 >> 16);
            r1b += __bfloat162float(*reinterpret_cast<__nv_bfloat16*>(&u));
            c[mt][nt][0] = o0 + r0a; c[mt][nt][1] = o1 + r0b;
            c[mt][nt][2] = o2 + r1a; c[mt][nt][3] = o3 + r1b;
        }
    }
    // LN2
#pragma unroll
    for (int mt = 0; mt < 2; mt++) {
        float s0 = 0.f, q0 = 0.f, s1 = 0.f, q1 = 0.f;
#pragma unroll
        for (int nt = 0; nt < 8; nt++) {
            float o0 = c[mt][nt][0], o1 = c[mt][nt][1];
            float o2 = c[mt][nt][2], o3 = c[mt][nt][3];
            s0 += o0 + o1; q0 += o0 * o0 + o1 * o1;
            s1 += o2 + o3; q1 += o2 * o2 + o3 * o3;
        }
#pragma unroll
        for (int o = 1; o < 4; o <<= 1) {
            s0 += __shfl_xor_sync(0xFFFFFFFFu, s0, o);
            q0 += __shfl_xor_sync(0xFFFFFFFFu, q0, o);
            s1 += __shfl_xor_sync(0xFFFFFFFFu, s1, o);
            q1 += __shfl_xor_sync(0xFFFFFFFFu, q1, o);
        }
        if (tig == 0) {
            int lr0 = warpM * 32 + mt * 16 + gid;
            rb[lr0 * 4 + warpN]       = make_float2(s0, q0);
            rb[(lr0 + 8) * 4 + warpN] = make_float2(s1, q1);
        }
    }
    __syncthreads();
#pragma unroll
    for (int mt = 0; mt < 2; mt++) {
        int lr0 = warpM * 32 + mt * 16 + gid;
        int lr1 = lr0 + 8;
        float2 p00 = rb[lr0*4+0], p01 = rb[lr0*4+1], p02 = rb[lr0*4+2], p03 = rb[lr0*4+3];
        float2 p10 = rb[lr1*4+0], p11 = rb[lr1*4+1], p12 = rb[lr1*4+2], p13 = rb[lr1*4+3];
        float sum0 = p00.x + p01.x + p02.x + p03.x;
        float sq0  = p00.y + p01.y + p02.y + p03.y;
        float sum1 = p10.x + p11.x + p12.x + p13.x;
        float sq1  = p10.y + p11.y + p12.y + p13.y;
        float mean0 = sum0 * (1.f / 256.f);
        float rstd0 = rsqrtf(sq0 * (1.f / 256.f) - mean0 * mean0 + 1e-5f);
        float mean1 = sum1 * (1.f / 256.f);
        float rstd1 = rsqrtf(sq1 * (1.f / 256.f) - mean1 * mean1 + 1e-5f);
        int r0 = rowBase + lr0, r1 = rowBase + lr1;
        bool v0 = r0 < Mrows, v1 = r1 < Mrows;
#pragma unroll
        for (int nt = 0; nt < 8; nt++) {
            int col = warpN * 64 + nt * 8 + tig * 2;
            float2 gv = *reinterpret_cast<const float2*>(lng2 + col);
            float2 bv = *reinterpret_cast<const float2*>(lnb2 + col);
            if (v0) {
                float o0 = (c[mt][nt][0] - mean0) * rstd0 * gv.x + bv.x;
                float o1 = (c[mt][nt][1] - mean0) * rstd0 * gv.y + bv.y;
                *reinterpret_cast<float2*>(C2 + (size_t)r0 * DD + col) = make_float2(o0, o1);
            }
            if (v1) {
                float o2 = (c[mt][nt][2] - mean1) * rstd1 * gv.x + bv.x;
                float o3 = (c[mt][nt][3] - mean1) * rstd1 * gv.y + bv.y;
                *reinterpret_cast<float2*>(C2 + (size_t)r1 * DD + col) = make_float2(o2, o3);
            }
        }
    }
}

// -------- edge gather on raw X --------
__global__ void edge_gatherX(const float* __restrict__ X, const int* __restrict__ hn,
                             const int* __restrict__ permE, const int* __restrict__ offE,
                             const int* __restrict__ cntE, float* __restrict__ Xmean,
                             int act, int nEdges)
{
    int ed = blockIdx.x * 8 + (threadIdx.x >> 5);
    if (ed >= nEdges) return;
    int lane = threadIdx.x & 31;
    int start = offE[ed], deg = cntE[ed];
    float4 a0 = make_float4(0.f,0.f,0.f,0.f), a1 = a0;
    for (int base = 0; base < deg; base += 32) {
        int m = min(32, deg - base);
        int src = 0;
        if (lane < m) src = hn[permE[start + base + lane]];
        for (int i = 0; i < m; i++) {
            int node = __shfl_sync(0xFFFFFFFFu, src, i);
            const float4* rp = reinterpret_cast<const float4*>(X + (size_t)node * DD + lane * 8);
            float4 v0 = rp[0], v1 = rp[1];
            if (act) {
                v0.x = lrelu_f(v0.x); v0.y = lrelu_f(v0.y); v0.z = lrelu_f(v0.z); v0.w = lrelu_f(v0.w);
                v1.x = lrelu_f(v1.x); v1.y = lrelu_f(v1.y); v1.z = lrelu_f(v1.z); v1.w = lrelu_f(v1.w);
            }
            a0.x += v0.x; a0.y += v0.y; a0.z += v0.z; a0.w += v0.w;
            a1.x += v1.x; a1.y += v1.y; a1.z += v1.z; a1.w += v1.w;
        }
    }
    float inv = 1.f / fmaxf((float)deg, 1.f);
    a0.x *= inv; a0.y *= inv; a0.z *= inv; a0.w *= inv;
    a1.x *= inv; a1.y *= inv; a1.z *= inv; a1.w *= inv;
    float4* op = reinterpret_cast<float4*>(Xmean + (size_t)ed * DD + lane * 8);
    op[0] = a0; op[1] = a1;
}

// -------- fused per-node softmax + aggregate --------
__global__ void node_attn_agg(const float* __restrict__ ef, const float* __restrict__ sn,
                              const float* __restrict__ se, const int* __restrict__ he,
                              const int* __restrict__ permN, const int* __restrict__ offN,
                              const int* __restrict__ cntN, float* __restrict__ attn,
                              float* __restrict__ out, int doLrelu, int nNodes)
{
    int n = blockIdx.x * 8 + (threadIdx.x >> 5);
    if (n >= nNodes) return;
    int lane = threadIdx.x & 31;
    int st = offN[n], deg = cntN[n];
    float4 a0 = make_float4(0.f,0.f,0.f,0.f), a1 = a0;

    if (deg > 0) {
        float s0 = sn[n];
        if (deg <= 32) {
            int inc = 0, ed = 0;
            float sc = -3.4e38f;
            if (lane < deg) {
                inc = permN[st + lane];
                ed = he[inc];
                sc = lrelu_f(s0 + se[ed]);
            }
            float mx = sc;
#pragma unroll
            for (int o = 16; o; o >>= 1) mx = fmaxf(mx, __shfl_xor_sync(0xFFFFFFFFu, mx, o));
            float e = (lane < deg) ? expf(sc - mx) : 0.f;
            float z = e;
#pragma unroll
            for (int o = 16; o; o >>= 1) z += __shfl_xor_sync(0xFFFFFFFFu, z, o);
            float w = e / fmaxf(z, 1e-9f);
            if (lane < deg && attn != nullptr) attn[inc] = w;
            for (int i = 0; i < deg; i++) {
                int e_   = __shfl_sync(0xFFFFFFFFu, ed, i);
                float w_ = __shfl_sync(0xFFFFFFFFu, w, i);
                const float4* rp = reinterpret_cast<const float4*>(ef + (size_t)e_ * DD + lane * 8);
                float4 v0 = rp[0], v1 = rp[1];
                a0.x += w_*v0.x; a0.y += w_*v0.y; a0.z += w_*v0.z; a0.w += w_*v0.w;
                a1.x += w_*v1.x; a1.y += w_*v1.y; a1.z += w_*v1.z; a1.w += w_*v1.w;
            }
        } else {
            float mx = -3.4e38f;
            for (int base = 0; base < deg; base += 32) {
                float sc = -3.4e38f;
                if (base + lane < deg) {
                    int inc = permN[st + base + lane];
                    sc = lrelu_f(s0 + se[he[inc]]);
                }
                mx = fmaxf(mx, sc);
            }
#pragma unroll
            for (int o = 16; o; o >>= 1) mx = fmaxf(mx, __shfl_xor_sync(0xFFFFFFFFu, mx, o));
            float z = 0.f;
            for (int base = 0; base < deg; base += 32) {
                if (base + lane < deg) {
                    int inc = permN[st + base + lane];
                    z += expf(lrelu_f(s0 + se[he[inc]]) - mx);
                }
            }
#pragma unroll
            for (int o = 16; o; o >>= 1) z += __shfl_xor_sync(0xFFFFFFFFu, z, o);
            float invz = 1.f / fmaxf(z, 1e-9f);
            for (int base = 0; base < deg; base += 32) {
                int m = min(32, deg - base);
                int ed = 0; float w = 0.f;
                if (lane < m) {
                    int inc = permN[st + base + lane];
                    ed = he[inc];
                    w = expf(lrelu_f(s0 + se[ed]) - mx) * invz;
                    if (attn != nullptr) attn[inc] = w;
                }
                for (int i = 0; i < m; i++) {
                    int e_   = __shfl_sync(0xFFFFFFFFu, ed, i);
                    float w_ = __shfl_sync(0xFFFFFFFFu, w, i);
                    const float4* rp = reinterpret_cast<const float4*>(ef + (size_t)e_ * DD + lane * 8);
                    float4 v0 = rp[0], v1 = rp[1];
                    a0.x += w_*v0.x; a0.y += w_*v0.y; a0.z += w_*v0.z; a0.w += w_*v0.w;
                    a1.x += w_*v1.x; a1.y += w_*v1.y; a1.z += w_*v1.z; a1.w += w_*v1.w;
                }
            }
        }
    }
    if (doLrelu) {
        a0.x = lrelu_f(a0.x); a0.y = lrelu_f(a0.y); a0.z = lrelu_f(a0.z); a0.w = lrelu_f(a0.w);
        a1.x = lrelu_f(a1.x); a1.y = lrelu_f(a1.y); a1.z = lrelu_f(a1.z); a1.w = lrelu_f(a1.w);
    }
    float4* op = reinterpret_cast<float4*>(out + (size_t)n * DD + lane * 8);
    op[0] = a0; op[1] = a1;
}

// -------- object message gather --------
__global__ void obj_gather(const float* __restrict__ ev, const int* __restrict__ oe_ev,
                           const int* __restrict__ permO, const int* __restrict__ offO,
                           const int* __restrict__ cntO, float* __restrict__ msg, int nObj)
{
    int o = blockIdx.x * 8 + (threadIdx.x >> 5);
    if (o >= nObj) return;
    int lane = threadIdx.x & 31;
    int start = offO[o], deg = cntO[o];
    float4 a0 = make_float4(0.f,0.f,0.f,0.f), a1 = a0;
    for (int base = 0; base < deg; base += 32) {
        int m = min(32, deg - base);
        int src = 0;
        if (lane < m) src = oe_ev[permO[start + base + lane]];
        for (int i = 0; i < m; i++) {
            int row = __shfl_sync(0xFFFFFFFFu, src, i);
            const float4* rp = reinterpret_cast<const float4*>(ev + (size_t)row * DD + lane * 8);
            float4 v0 = rp[0], v1 = rp[1];
            a0.x += v0.x; a0.y += v0.y; a0.z += v0.z; a0.w += v0.w;
            a1.x += v1.x; a1.y += v1.y; a1.z += v1.z; a1.w += v1.w;
        }
    }
    float4* op = reinterpret_cast<float4*>(msg + (size_t)o * DD + lane * 8);
    op[0] = a0; op[1] = a1;
}

// ----------------- host orchestration -----------------
struct Ptrs {
    float *X, *obj, *msg, *H, *ef, *snode, *sedge, *wav;
    unsigned char* wp;
    int *cntE, *offE, *permE, *cntN, *offN, *permN, *cntO, *offO, *permO;
};

static void get_ptrs(Ptrs& p) {
    cudaGetSymbolAddress((void**)&p.X,     g_X);
    cudaGetSymbolAddress((void**)&p.obj,   g_obj);
    cudaGetSymbolAddress((void**)&p.msg,   g_msg);
    cudaGetSymbolAddress((void**)&p.H,     g_H);
    cudaGetSymbolAddress((void**)&p.ef,    g_ef);
    cudaGetSymbolAddress((void**)&p.snode, g_snode);
    cudaGetSymbolAddress((void**)&p.sedge, g_sedge);
    cudaGetSymbolAddress((void**)&p.wav,   g_wav);
    cudaGetSymbolAddress((void**)&p.wp,    g_Wprep);
    cudaGetSymbolAddress((void**)&p.cntE,  g_cntE);
    cudaGetSymbolAddress((void**)&p.offE,  g_offE);
    cudaGetSymbolAddress((void**)&p.permE, g_permE);
    cudaGetSymbolAddress((void**)&p.cntN,  g_cntN);
    cudaGetSymbolAddress((void**)&p.offN,  g_offN);
    cudaGetSymbolAddress((void**)&p.permN, g_permN);
    cudaGetSymbolAddress((void**)&p.cntO,  g_cntO);
    cudaGetSymbolAddress((void**)&p.offO,  g_offO);
    cudaGetSymbolAddress((void**)&p.permO, g_permO);
}

template <int FLAGS>
static void launch_tgemm(const float* A, const unsigned char* Wp, const float* bias,
                         const float* R, const float* av, const float* lng, const float* lnb,
                         float* C, float* snode, int Mrows)
{
    cudaFuncSetAttribute(tgemm256<FLAGS>, cudaFuncAttributeMaxDynamicSharedMemorySize, SMEM_SZ);
    tgemm256<FLAGS><<<(Mrows + 127) / 128, 512, SMEM_SZ>>>(A, Wp, bias, R, av, lng, lnb, C, snode, Mrows);
}

static void hgnn_layer(const Ptrs& p, const float* Xin, const float* Wraw,
                       const unsigned char* Wp, const float* a,
                       const int* hg_node, const int* hg_edge,
                       float* outbuf, float* attnOut, bool act, bool lreluOut)
{
    prep_wav<<<(DD + 7) / 8, 256>>>(Wraw, a, p.wav);
    snode_dot<<<(NN + 7) / 8, 256>>>(Xin, p.wav, p.snode, NN, act ? 1 : 0);
    edge_gatherX<<<(NE + 7) / 8, 256>>>(Xin, hg_node, p.permE, p.offE, p.cntE,
                                        p.msg, act ? 1 : 0, NE);
    launch_tgemm<F_SNODE>(p.msg, Wp, nullptr, nullptr, a + DD, nullptr, nullptr,
                          p.ef, p.sedge, NE);
    node_attn_agg<<<(NN + 7) / 8, 256>>>(p.ef, p.snode, p.sedge, hg_edge,
                                         p.permN, p.offN, p.cntN,
                                         attnOut, outbuf, lreluOut ? 1 : 0, NN);
}

extern "C" void kernel_launch(void* const* d_in, const int* in_sizes, int n_in,
                              void* d_out, int out_size)
{
    const float* object_X = (const float*)d_in[0];
    const float* event_X  = (const float*)d_in[1];
    const float* Wo = (const float*)d_in[2];  const float* bo  = (const float*)d_in[3];
    const float* go = (const float*)d_in[4];  const float* bon = (const float*)d_in[5];
    const float* We = (const float*)d_in[6];  const float* be  = (const float*)d_in[7];
    const float* ge = (const float*)d_in[8];  const float* ben = (const float*)d_in[9];
    const float* Wu = (const float*)d_in[10]; const float* bu  = (const float*)d_in[11];
    const float* Wl = (const float*)d_in[12]; const float* bl  = (const float*)d_in[13];
    const float* g1 = (const float*)d_in[14]; const float* b1  = (const float*)d_in[15];
    const float* g2 = (const float*)d_in[16]; const float* b2  = (const float*)d_in[17];
    const float* Wh1 = (const float*)d_in[18]; const float* ah1 = (const float*)d_in[19];
    const float* Wh2 = (const float*)d_in[20]; const float* ah2 = (const float*)d_in[21];
    const int* oe_ev   = (const int*)d_in[22];
    const int* oe_obj  = (const int*)d_in[23];
    const int* hg_node = (const int*)d_in[24];
    const int* hg_edge = (const int*)d_in[25];

    Ptrs p; get_ptrs(p);

    // 0) weight prep + condensed CSR build (6 launches)
    prep_w<<<dim3(32, 6), 256>>>(We, Wo, Wu, Wl, Wh1, Wh2);
    zero_misc<<<(2 * (NE + NN + NO) + 255) / 256, 256>>>();
    count_all<<<(2 * E2N + E1N + 255) / 256, 256>>>(hg_edge, hg_node, oe_obj);
    scan_all<<<NBT, 1024>>>();
    scan_small3<<<1, 32>>>();
    add_off_all<<<(NE + NN + NO + 255) / 256, 256>>>();
    fill_all<<<(2 * E2N + E1N + 255) / 256, 256>>>(hg_edge, hg_node, oe_obj);

    const unsigned char *wpe = p.wp, *wpo = p.wp + 262144, *wpu = p.wp + 2 * 262144,
                        *wpl = p.wp + 3 * 262144, *wph1 = p.wp + 4 * 262144,
                        *wph2 = p.wp + 5 * 262144;

    // 1) ev = LN(lrelu(event_X @ We + be)) -> X[0:NE)
    launch_tgemm<F_BIAS | F_LRELU | F_LN>(event_X, wpe, be, nullptr, nullptr, ge, ben, p.X, nullptr, NE);

    // 2) obj = LN(lrelu(object_X @ Wo + bo))
    launch_tgemm<F_BIAS | F_LRELU | F_LN>(object_X, wpo, bo, nullptr, nullptr, go, bon, p.obj, nullptr, NO);

    // 3) msg = segment_sum(ev[oe_ev], oe_obj)
    obj_gather<<<(NO + 7) / 8, 256>>>(p.X, oe_ev, p.permO, p.offO, p.cntO, p.msg, NO);

    // 4+5) fused: obj2 = LN2(lrelu(LN1(lrelu(msg@Wu+bu)+obj)@Wl+bl)+obj1) -> X[NE:NN)
    cudaFuncSetAttribute(tgemm_dual, cudaFuncAttributeMaxDynamicSharedMemorySize, SMEM_SZ);
    tgemm_dual<<<(NO + 127) / 128, 512, SMEM_SZ>>>(p.msg, wpu, bu, p.obj, g1, b1,
                                                   wpl, bl, g2, b2,
                                                   p.X + (size_t)NE * DD, NO);

    // 6) HGNN layer 1 -> H (attn discarded)
    hgnn_layer(p, p.X, Wh1, wph1, ah1, hg_node, hg_edge, p.H, nullptr, false, false);

    // 7) HGNN layer 2 -> d_out
    float* out = (float*)d_out;
    hgnn_layer(p, p.H, Wh2, wph2, ah2, hg_node, hg_edge, out, out + (size_t)NN * DD, true, true);
}

// round 9
// speedup vs baseline: 2.7173x; 1.0647x over previous
#include <cuda_runtime.h>
#include <cuda_bf16.h>
#include <cstdint>

#define DD 256
static const int NE  = 50000;
static const int NO  = 100000;
static const int NN  = 150000;
static const int E1N = 400000;
static const int E2N = 800000;

// -------- device scratch --------
__device__ float    g_X  [(size_t)NN * DD];
__device__ float    g_obj[(size_t)NO * DD];
__device__ float    g_msg[(size_t)NO * DD];   // also Xmean[NE*DD] in hgnn layers
__device__ float    g_H  [(size_t)NN * DD];
__device__ float    g_ef [(size_t)NE * DD];
__device__ float    g_snode[NN];
__device__ float    g_sedge[NE];
__device__ float    g_wav1[DD];
__device__ float    g_wav2[DD];
__device__ unsigned char g_Wprep[6 * 4 * 2 * 256 * 128];
// CSR structures
__device__ int g_cntE[NE],  g_offE[NE],  g_permE[E2N];
__device__ int g_cntN[NN],  g_offN[NN],  g_permN[E2N];
__device__ int g_cntO[NO],  g_offO[NO],  g_permO[E1N];
__device__ int g_cur[NE + NN + NO];
__device__ int g_bsum[512];

static const int NBE = (NE + 1023) / 1024;
static const int NBN = (NN + 1023) / 1024;
static const int NBO = (NO + 1023) / 1024;
static const int NBT = NBE + NBN + NBO;

// -------- helpers --------
__device__ __forceinline__ float lrelu_f(float x) { return x >= 0.f ? x : 0.2f * x; }

__device__ __forceinline__ uint32_t smem_to_u32(const void* p) {
    uint32_t a;
    asm("{ .reg .u64 t; cvta.to.shared.u64 t, %1; cvt.u32.u64 %0, t; }" : "=r"(a) : "l"(p));
    return a;
}
__device__ __forceinline__ void ldm_x4(uint32_t addr, uint32_t* r) {
    asm volatile("ldmatrix.sync.aligned.m8n8.x4.shared.b16 {%0,%1,%2,%3}, [%4];"
                 : "=r"(r[0]), "=r"(r[1]), "=r"(r[2]), "=r"(r[3]) : "r"(addr));
}
__device__ __forceinline__ void mma_bf16(float* c, const uint32_t* a, const uint32_t* b) {
    asm volatile("mma.sync.aligned.m16n8k16.row.col.f32.bf16.bf16.f32 "
                 "{%0,%1,%2,%3}, {%4,%5,%6,%7}, {%8,%9}, {%0,%1,%2,%3};"
                 : "+f"(c[0]), "+f"(c[1]), "+f"(c[2]), "+f"(c[3])
                 : "r"(a[0]), "r"(a[1]), "r"(a[2]), "r"(a[3]), "r"(b[0]), "r"(b[1]));
}
__device__ __forceinline__ uint32_t swz(uint32_t row, uint32_t cb) {
    return row * 128u + (cb ^ ((row & 7u) << 4));
}
__device__ __forceinline__ uint32_t swz512(uint32_t row, uint32_t cb) {
    return row * 512u + (cb ^ ((row & 7u) << 4));
}
#define CP_ASYNC16(dst, src) \
    asm volatile("cp.async.cg.shared.global [%0], [%1], 16;" :: "r"(dst), "l"(src) : "memory")
#define CP_COMMIT() asm volatile("cp.async.commit_group;" ::: "memory")
#define CP_WAIT(n)  asm volatile("cp.async.wait_group %0;" :: "n"(n) : "memory")

enum { F_SNODE = 16 };

// ======== condensed CSR build ========
__global__ void zero_misc()
{
    int g = blockIdx.x * blockDim.x + threadIdx.x;
    if (g < NE) g_cntE[g] = 0;
    else if (g < NE + NN) g_cntN[g - NE] = 0;
    else if (g < NE + NN + NO) g_cntO[g - NE - NN] = 0;
    int h = g - (NE + NN + NO);
    if (h >= 0 && h < NE + NN + NO) g_cur[h] = 0;
}
__global__ void count_all(const int* __restrict__ he, const int* __restrict__ hn,
                          const int* __restrict__ oo)
{
    int t = blockIdx.x * blockDim.x + threadIdx.x;
    if (t < E2N) atomicAdd(&g_cntE[he[t]], 1);
    else if (t < 2 * E2N) atomicAdd(&g_cntN[hn[t - E2N]], 1);
    else if (t < 2 * E2N + E1N) atomicAdd(&g_cntO[oo[t - 2 * E2N]], 1);
}
__global__ void scan_all()
{
    __shared__ int sh[1024];
    int b = blockIdx.x;
    const int* cnt; int* off; int nseg; int lb;
    if (b < NBE)            { cnt = g_cntE; off = g_offE; nseg = NE; lb = b; }
    else if (b < NBE + NBN) { cnt = g_cntN; off = g_offN; nseg = NN; lb = b - NBE; }
    else                    { cnt = g_cntO; off = g_offO; nseg = NO; lb = b - NBE - NBN; }
    int g = lb * 1024 + threadIdx.x;
    int v = (g < nseg) ? cnt[g] : 0;
    sh[threadIdx.x] = v;
    __syncthreads();
#pragma unroll
    for (int o = 1; o < 1024; o <<= 1) {
        int t = (threadIdx.x >= o) ? sh[threadIdx.x - o] : 0;
        __syncthreads();
        sh[threadIdx.x] += t;
        __syncthreads();
    }
    if (g < nseg) off[g] = sh[threadIdx.x] - v;
    if (threadIdx.x == 1023) g_bsum[b] = sh[1023];
}
__global__ void scan_small3()
{
    int t = threadIdx.x;
    int s, e;
    if (t == 0)      { s = 0;          e = NBE; }
    else if (t == 1) { s = NBE;        e = NBE + NBN; }
    else if (t == 2) { s = NBE + NBN;  e = NBT; }
    else return;
    int run = 0;
    for (int i = s; i < e; i++) { int v = g_bsum[i]; g_bsum[i] = run; run += v; }
}
__global__ void add_off_all()
{
    int g = blockIdx.x * blockDim.x + threadIdx.x;
    if (g < NE) g_offE[g] += g_bsum[g >> 10];
    else if (g < NE + NN) {
        int l = g - NE; g_offN[l] += g_bsum[NBE + (l >> 10)];
    } else if (g < NE + NN + NO) {
        int l = g - NE - NN; g_offO[l] += g_bsum[NBE + NBN + (l >> 10)];
    }
}
__global__ void fill_all(const int* __restrict__ he, const int* __restrict__ hn,
                         const int* __restrict__ oo)
{
    int t = blockIdx.x * blockDim.x + threadIdx.x;
    if (t < E2N) {
        int s = he[t];
        g_permE[g_offE[s] + atomicAdd(&g_cur[s], 1)] = t;
    } else if (t < 2 * E2N) {
        int e = t - E2N;
        int s = hn[e];
        g_permN[g_offN[s] + atomicAdd(&g_cur[NE + s], 1)] = e;
    } else if (t < 2 * E2N + E1N) {
        int e = t - 2 * E2N;
        int s = oo[e];
        g_permO[g_offO[s] + atomicAdd(&g_cur[NE + NN + s], 1)] = e;
    }
}

// -------- weight prep --------
__global__ void prep_w(const float* W0, const float* W1, const float* W2,
                       const float* W3, const float* W4, const float* W5)
{
    const float* Ws[6] = {W0, W1, W2, W3, W4, W5};
    const float* W = Ws[blockIdx.y];
    unsigned char* base = g_Wprep + (size_t)blockIdx.y * 262144;
    int g = blockIdx.x * 256 + threadIdx.x;
    int n = g >> 5, kg = g & 31, k0 = kg * 8;
    unsigned short hi[8], lo[8];
#pragma unroll
    for (int i = 0; i < 8; i++) {
        float x = W[(size_t)(k0 + i) * DD + n];
        __nv_bfloat16 h = __float2bfloat16(x);
        __nv_bfloat16 l = __float2bfloat16(x - __bfloat162float(h));
        hi[i] = *reinterpret_cast<unsigned short*>(&h);
        lo[i] = *reinterpret_cast<unsigned short*>(&l);
    }
    int chunk = k0 >> 6, kc = k0 & 63;
    uint32_t off = (uint32_t)n * 128u + (((uint32_t)kc * 2u) ^ (((uint32_t)n & 7u) << 4));
    *reinterpret_cast<uint4*>(base + (size_t)(chunk * 2 + 0) * 32768 + off) =
        *reinterpret_cast<uint4*>(hi);
    *reinterpret_cast<uint4*>(base + (size_t)(chunk * 2 + 1) * 32768 + off) =
        *reinterpret_cast<uint4*>(lo);
}

__global__ void prep_wav(const float* __restrict__ W, const float* __restrict__ a,
                         float* __restrict__ w)
{
    int k = blockIdx.x * 8 + (threadIdx.x >> 5);
    if (k >= DD) return;
    int lane = threadIdx.x & 31;
    const float4* rp = reinterpret_cast<const float4*>(W + (size_t)k * DD);
    const float4* ap = reinterpret_cast<const float4*>(a);
    float4 v0 = rp[lane], v1 = rp[lane + 32];
    float4 a0 = ap[lane], a1 = ap[lane + 32];
    float d = v0.x*a0.x + v0.y*a0.y + v0.z*a0.z + v0.w*a0.w
            + v1.x*a1.x + v1.y*a1.y + v1.z*a1.z + v1.w*a1.w;
#pragma unroll
    for (int o = 16; o; o >>= 1) d += __shfl_xor_sync(0xFFFFFFFFu, d, o);
    if (lane == 0) w[k] = d;
}

static const int SMEM_SZ = 196608;

// ======== combined projection GEMM (steps 1+2): C = LN(lrelu(A@W + b)), opt snode ========
__global__ __launch_bounds__(512, 1)
void proj_gemm(const float* __restrict__ A0, const unsigned char* __restrict__ Wp0,
               const float* __restrict__ bias0, const float* __restrict__ lng0,
               const float* __restrict__ lnb0, float* __restrict__ C0,
               const float* __restrict__ av0, float* __restrict__ snode0, int M0, int nb0,
               const float* __restrict__ A1, const unsigned char* __restrict__ Wp1,
               const float* __restrict__ bias1, const float* __restrict__ lng1,
               const float* __restrict__ lnb1, float* __restrict__ C1, int M1)
{
    extern __shared__ __align__(128) unsigned char smem[];
    const uint32_t sb = smem_to_u32(smem);
    const int tid = threadIdx.x, lane = tid & 31, wid = tid >> 5;
    const int warpM = wid >> 2, warpN = wid & 3;

    const float* A; const unsigned char* Wp; const float* bias;
    const float* lng; const float* lnb; float* C;
    const float* av; float* snode; int Mrows, rowBase;
    if ((int)blockIdx.x < nb0) {
        A = A0; Wp = Wp0; bias = bias0; lng = lng0; lnb = lnb0; C = C0;
        av = av0; snode = snode0; Mrows = M0; rowBase = blockIdx.x * 128;
    } else {
        A = A1; Wp = Wp1; bias = bias1; lng = lng1; lnb = lnb1; C = C1;
        av = nullptr; snode = nullptr; Mrows = M1; rowBase = (blockIdx.x - nb0) * 128;
    }

    int rA[2], cgA[2];
#pragma unroll
    for (int i = 0; i < 2; i++) {
        int g = tid + i * 512;
        rA[i] = g >> 3; cgA[i] = g & 7;
    }
    float4 pref[4];

    auto issueA = [&](int ch) {
#pragma unroll
        for (int i = 0; i < 2; i++) {
            int row = rowBase + rA[i];
            if (row < Mrows) {
                const float4* src = reinterpret_cast<const float4*>(
                    A + (size_t)row * DD + ch * 64 + cgA[i] * 8);
                pref[i * 2]     = src[0];
                pref[i * 2 + 1] = src[1];
            } else {
                pref[i * 2]     = make_float4(0.f, 0.f, 0.f, 0.f);
                pref[i * 2 + 1] = make_float4(0.f, 0.f, 0.f, 0.f);
            }
        }
    };
    auto storeA = [&](int s) {
#pragma unroll
        for (int i = 0; i < 2; i++) {
            float x[8];
            float4 v0 = pref[i * 2], v1 = pref[i * 2 + 1];
            x[0] = v0.x; x[1] = v0.y; x[2] = v0.z; x[3] = v0.w;
            x[4] = v1.x; x[5] = v1.y; x[6] = v1.z; x[7] = v1.w;
            unsigned short hi[8], lo[8];
#pragma unroll
            for (int j = 0; j < 8; j++) {
                __nv_bfloat16 h = __float2bfloat16(x[j]);
                __nv_bfloat16 l = __float2bfloat16(x[j] - __bfloat162float(h));
                hi[j] = *reinterpret_cast<unsigned short*>(&h);
                lo[j] = *reinterpret_cast<unsigned short*>(&l);
            }
            uint32_t off = s * 32768u + swz((uint32_t)rA[i], (uint32_t)cgA[i] * 16u);
            *reinterpret_cast<uint4*>(smem + off)         = *reinterpret_cast<uint4*>(hi);
            *reinterpret_cast<uint4*>(smem + 16384 + off) = *reinterpret_cast<uint4*>(lo);
        }
    };
    auto issueB = [&](int ch, int s) {
        const unsigned char* bh = Wp + (size_t)(ch * 2 + 0) * 32768;
        const unsigned char* bl = Wp + (size_t)(ch * 2 + 1) * 32768;
        uint32_t dh = sb + 65536u + (uint32_t)s * 65536u;
        uint32_t dl = dh + 32768u;
#pragma unroll
        for (int i = 0; i < 4; i++) {
            int idx = (tid + i * 512) * 16;
            CP_ASYNC16(dh + idx, bh + idx);
            CP_ASYNC16(dl + idx, bl + idx);
        }
        CP_COMMIT();
    };

    float c[2][8][4];
#pragma unroll
    for (int mt = 0; mt < 2; mt++)
#pragma unroll
        for (int nt = 0; nt < 8; nt++)
#pragma unroll
            for (int q = 0; q < 4; q++) c[mt][nt][q] = 0.f;

    issueA(0);
    issueB(0, 0);
    storeA(0);

    for (int ch = 0; ch < 4; ch++) {
        const int s = ch & 1;
        if (ch < 3) {
            issueA(ch + 1);
            issueB(ch + 1, s ^ 1);
            CP_WAIT(1);
        } else {
            CP_WAIT(0);
        }
        __syncthreads();

        const uint32_t aBase = sb + (uint32_t)s * 32768u;
        const uint32_t bBase = sb + 65536u + (uint32_t)s * 65536u;
#pragma unroll
        for (int ks = 0; ks < 4; ks++) {
            uint32_t ah[2][4], al[2][4];
#pragma unroll
            for (int mt = 0; mt < 2; mt++) {
                uint32_t row = (uint32_t)(warpM * 32 + mt * 16 + (lane & 7) + ((lane >> 3) & 1) * 8);
                uint32_t kb  = (uint32_t)(ks * 32 + ((lane >> 4) & 1) * 16);
                uint32_t addr = aBase + swz(row, kb);
                ldm_x4(addr,         ah[mt]);
                ldm_x4(addr + 16384, al[mt]);
            }
#pragma unroll
            for (int p = 0; p < 4; p++) {
                uint32_t nrow = (uint32_t)(warpN * 64 + p * 16 + (lane & 7) + ((lane >> 4) & 1) * 8);
                uint32_t kb   = (uint32_t)(ks * 32 + ((lane >> 3) & 1) * 16);
                uint32_t addr = bBase + swz(nrow, kb);
                uint32_t bh[4], bl[4];
                ldm_x4(addr,         bh);
                ldm_x4(addr + 32768, bl);
#pragma unroll
                for (int t = 0; t < 2; t++) {
#pragma unroll
                    for (int mt = 0; mt < 2; mt++) {
                        float* cc = c[mt][p * 2 + t];
                        mma_bf16(cc, ah[mt], bh + t * 2);
                        mma_bf16(cc, ah[mt], bl + t * 2);
                        mma_bf16(cc, al[mt], bh + t * 2);
                    }
                }
            }
        }
        if (ch < 3) storeA(s ^ 1);
        __syncthreads();
    }

    // ---- epilogue: bias + lrelu + LN (+ optional snode post-LN) ----
    const int gid = lane >> 2, tig = lane & 3;
    float2* rb = reinterpret_cast<float2*>(smem);

#pragma unroll
    for (int mt = 0; mt < 2; mt++)
#pragma unroll
        for (int nt = 0; nt < 8; nt++) {
            int col = warpN * 64 + nt * 8 + tig * 2;
            float2 bv = *reinterpret_cast<const float2*>(bias + col);
            c[mt][nt][0] = lrelu_f(c[mt][nt][0] + bv.x);
            c[mt][nt][1] = lrelu_f(c[mt][nt][1] + bv.y);
            c[mt][nt][2] = lrelu_f(c[mt][nt][2] + bv.x);
            c[mt][nt][3] = lrelu_f(c[mt][nt][3] + bv.y);
        }

    // LN stats
#pragma unroll
    for (int mt = 0; mt < 2; mt++) {
        float s0 = 0.f, q0 = 0.f, s1 = 0.f, q1 = 0.f;
#pragma unroll
        for (int nt = 0; nt < 8; nt++) {
            float o0 = c[mt][nt][0], o1 = c[mt][nt][1];
            float o2 = c[mt][nt][2], o3 = c[mt][nt][3];
            s0 += o0 + o1; q0 += o0 * o0 + o1 * o1;
            s1 += o2 + o3; q1 += o2 * o2 + o3 * o3;
        }
#pragma unroll
        for (int o = 1; o < 4; o <<= 1) {
            s0 += __shfl_xor_sync(0xFFFFFFFFu, s0, o);
            q0 += __shfl_xor_sync(0xFFFFFFFFu, q0, o);
            s1 += __shfl_xor_sync(0xFFFFFFFFu, s1, o);
            q1 += __shfl_xor_sync(0xFFFFFFFFu, q1, o);
        }
        if (tig == 0) {
            int lr0 = warpM * 32 + mt * 16 + gid;
            rb[lr0 * 4 + warpN]       = make_float2(s0, q0);
            rb[(lr0 + 8) * 4 + warpN] = make_float2(s1, q1);
        }
    }
    __syncthreads();

    float sd[2][2] = {{0.f, 0.f}, {0.f, 0.f}};
#pragma unroll
    for (int mt = 0; mt < 2; mt++) {
        int lr0 = warpM * 32 + mt * 16 + gid;
        int lr1 = lr0 + 8;
        float2 p00 = rb[lr0*4+0], p01 = rb[lr0*4+1], p02 = rb[lr0*4+2], p03 = rb[lr0*4+3];
        float2 p10 = rb[lr1*4+0], p11 = rb[lr1*4+1], p12 = rb[lr1*4+2], p13 = rb[lr1*4+3];
        float sum0 = p00.x + p01.x + p02.x + p03.x;
        float sq0  = p00.y + p01.y + p02.y + p03.y;
        float sum1 = p10.x + p11.x + p12.x + p13.x;
        float sq1  = p10.y + p11.y + p12.y + p13.y;
        float mean0 = sum0 * (1.f / 256.f);
        float rstd0 = rsqrtf(sq0 * (1.f / 256.f) - mean0 * mean0 + 1e-5f);
        float mean1 = sum1 * (1.f / 256.f);
        float rstd1 = rsqrtf(sq1 * (1.f / 256.f) - mean1 * mean1 + 1e-5f);
        int r0 = rowBase + lr0, r1 = rowBase + lr1;
        bool v0 = r0 < Mrows, v1 = r1 < Mrows;
#pragma unroll
        for (int nt = 0; nt < 8; nt++) {
            int col = warpN * 64 + nt * 8 + tig * 2;
            float2 gv = *reinterpret_cast<const float2*>(lng + col);
            float2 bv = *reinterpret_cast<const float2*>(lnb + col);
            float o0 = (c[mt][nt][0] - mean0) * rstd0 * gv.x + bv.x;
            float o1 = (c[mt][nt][1] - mean0) * rstd0 * gv.y + bv.y;
            float o2 = (c[mt][nt][2] - mean1) * rstd1 * gv.x + bv.x;
            float o3 = (c[mt][nt][3] - mean1) * rstd1 * gv.y + bv.y;
            if (v0) *reinterpret_cast<float2*>(C + (size_t)r0 * DD + col) = make_float2(o0, o1);
            if (v1) *reinterpret_cast<float2*>(C + (size_t)r1 * DD + col) = make_float2(o2, o3);
            if (snode != nullptr) {
                float2 avv = *reinterpret_cast<const float2*>(av + col);
                sd[mt][0] += o0 * avv.x + o1 * avv.y;
                sd[mt][1] += o2 * avv.x + o3 * avv.y;
            }
        }
    }

    if (snode != nullptr) {
        __syncthreads();
#pragma unroll
        for (int mt = 0; mt < 2; mt++) {
            float s0 = sd[mt][0], s1 = sd[mt][1];
#pragma unroll
            for (int o = 1; o < 4; o <<= 1) {
                s0 += __shfl_xor_sync(0xFFFFFFFFu, s0, o);
                s1 += __shfl_xor_sync(0xFFFFFFFFu, s1, o);
            }
            if (tig == 0) {
                int lr0 = warpM * 32 + mt * 16 + gid;
                rb[lr0 * 4 + warpN]       = make_float2(s0, 0.f);
                rb[(lr0 + 8) * 4 + warpN] = make_float2(s1, 0.f);
            }
        }
        __syncthreads();
        if (warpN == 0 && tig == 0) {
#pragma unroll
            for (int mt = 0; mt < 2; mt++) {
                int lr0 = warpM * 32 + mt * 16 + gid;
#pragma unroll
                for (int h = 0; h < 2; h++) {
                    int lr = lr0 + h * 8;
                    int row = rowBase + lr;
                    if (row < Mrows) {
                        snode[row] = rb[lr * 4 + 0].x + rb[lr * 4 + 1].x
                                   + rb[lr * 4 + 2].x + rb[lr * 4 + 3].x;
                    }
                }
            }
        }
    }
}

// ======== hgnn edge GEMM: C = Xmean@W, sedge = C·a2 (no LN) ========
template <int FLAGS>
__global__ __launch_bounds__(512, 1)
void tgemm256(const float* __restrict__ A, const unsigned char* __restrict__ Wp,
              const float* __restrict__ av, float* __restrict__ C,
              float* __restrict__ snode, int Mrows)
{
    extern __shared__ __align__(128) unsigned char smem[];
    const uint32_t sb = smem_to_u32(smem);
    const int tid = threadIdx.x, lane = tid & 31, wid = tid >> 5;
    const int warpM = wid >> 2, warpN = wid & 3;
    const int rowBase = blockIdx.x * 128;

    int rA[2], cgA[2];
#pragma unroll
    for (int i = 0; i < 2; i++) {
        int g = tid + i * 512;
        rA[i] = g >> 3; cgA[i] = g & 7;
    }
    float4 pref[4];

    auto issueA = [&](int ch) {
#pragma unroll
        for (int i = 0; i < 2; i++) {
            int row = rowBase + rA[i];
            if (row < Mrows) {
                const float4* src = reinterpret_cast<const float4*>(
                    A + (size_t)row * DD + ch * 64 + cgA[i] * 8);
                pref[i * 2]     = src[0];
                pref[i * 2 + 1] = src[1];
            } else {
                pref[i * 2]     = make_float4(0.f, 0.f, 0.f, 0.f);
                pref[i * 2 + 1] = make_float4(0.f, 0.f, 0.f, 0.f);
            }
        }
    };
    auto storeA = [&](int s) {
#pragma unroll
        for (int i = 0; i < 2; i++) {
            float x[8];
            float4 v0 = pref[i * 2], v1 = pref[i * 2 + 1];
            x[0] = v0.x; x[1] = v0.y; x[2] = v0.z; x[3] = v0.w;
            x[4] = v1.x; x[5] = v1.y; x[6] = v1.z; x[7] = v1.w;
            unsigned short hi[8], lo[8];
#pragma unroll
            for (int j = 0; j < 8; j++) {
                __nv_bfloat16 h = __float2bfloat16(x[j]);
                __nv_bfloat16 l = __float2bfloat16(x[j] - __bfloat162float(h));
                hi[j] = *reinterpret_cast<unsigned short*>(&h);
                lo[j] = *reinterpret_cast<unsigned short*>(&l);
            }
            uint32_t off = s * 32768u + swz((uint32_t)rA[i], (uint32_t)cgA[i] * 16u);
            *reinterpret_cast<uint4*>(smem + off)         = *reinterpret_cast<uint4*>(hi);
            *reinterpret_cast<uint4*>(smem + 16384 + off) = *reinterpret_cast<uint4*>(lo);
        }
    };
    auto issueB = [&](int ch, int s) {
        const unsigned char* bh = Wp + (size_t)(ch * 2 + 0) * 32768;
        const unsigned char* bl = Wp + (size_t)(ch * 2 + 1) * 32768;
        uint32_t dh = sb + 65536u + (uint32_t)s * 65536u;
        uint32_t dl = dh + 32768u;
#pragma unroll
        for (int i = 0; i < 4; i++) {
            int idx = (tid + i * 512) * 16;
            CP_ASYNC16(dh + idx, bh + idx);
            CP_ASYNC16(dl + idx, bl + idx);
        }
        CP_COMMIT();
    };

    float c[2][8][4];
#pragma unroll
    for (int mt = 0; mt < 2; mt++)
#pragma unroll
        for (int nt = 0; nt < 8; nt++)
#pragma unroll
            for (int q = 0; q < 4; q++) c[mt][nt][q] = 0.f;

    issueA(0);
    issueB(0, 0);
    storeA(0);

    for (int ch = 0; ch < 4; ch++) {
        const int s = ch & 1;
        if (ch < 3) {
            issueA(ch + 1);
            issueB(ch + 1, s ^ 1);
            CP_WAIT(1);
        } else {
            CP_WAIT(0);
        }
        __syncthreads();

        const uint32_t aBase = sb + (uint32_t)s * 32768u;
        const uint32_t bBase = sb + 65536u + (uint32_t)s * 65536u;
#pragma unroll
        for (int ks = 0; ks < 4; ks++) {
            uint32_t ah[2][4], al[2][4];
#pragma unroll
            for (int mt = 0; mt < 2; mt++) {
                uint32_t row = (uint32_t)(warpM * 32 + mt * 16 + (lane & 7) + ((lane >> 3) & 1) * 8);
                uint32_t kb  = (uint32_t)(ks * 32 + ((lane >> 4) & 1) * 16);
                uint32_t addr = aBase + swz(row, kb);
                ldm_x4(addr,         ah[mt]);
                ldm_x4(addr + 16384, al[mt]);
            }
#pragma unroll
            for (int p = 0; p < 4; p++) {
                uint32_t nrow = (uint32_t)(warpN * 64 + p * 16 + (lane & 7) + ((lane >> 4) & 1) * 8);
                uint32_t kb   = (uint32_t)(ks * 32 + ((lane >> 3) & 1) * 16);
                uint32_t addr = bBase + swz(nrow, kb);
                uint32_t bh[4], bl[4];
                ldm_x4(addr,         bh);
                ldm_x4(addr + 32768, bl);
#pragma unroll
                for (int t = 0; t < 2; t++) {
#pragma unroll
                    for (int mt = 0; mt < 2; mt++) {
                        float* cc = c[mt][p * 2 + t];
                        mma_bf16(cc, ah[mt], bh + t * 2);
                        mma_bf16(cc, ah[mt], bl + t * 2);
                        mma_bf16(cc, al[mt], bh + t * 2);
                    }
                }
            }
        }
        if (ch < 3) storeA(s ^ 1);
        __syncthreads();
    }

    const int gid = lane >> 2, tig = lane & 3;
    float2* rb = reinterpret_cast<float2*>(smem);

#pragma unroll
    for (int mt = 0; mt < 2; mt++) {
        int r0 = rowBase + warpM * 32 + mt * 16 + gid;
        int r1 = r0 + 8;
        bool v0 = r0 < Mrows, v1 = r1 < Mrows;
#pragma unroll
        for (int nt = 0; nt < 8; nt++) {
            int col = warpN * 64 + nt * 8 + tig * 2;
            if (v0) *reinterpret_cast<float2*>(C + (size_t)r0 * DD + col)
                        = make_float2(c[mt][nt][0], c[mt][nt][1]);
            if (v1) *reinterpret_cast<float2*>(C + (size_t)r1 * DD + col)
                        = make_float2(c[mt][nt][2], c[mt][nt][3]);
        }
    }

    if (FLAGS & F_SNODE) {
#pragma unroll
        for (int mt = 0; mt < 2; mt++) {
            float s0 = 0.f, s1 = 0.f;
#pragma unroll
            for (int nt = 0; nt < 8; nt++) {
                int col = warpN * 64 + nt * 8 + tig * 2;
                float2 avv = *reinterpret_cast<const float2*>(av + col);
                s0 += c[mt][nt][0] * avv.x + c[mt][nt][1] * avv.y;
                s1 += c[mt][nt][2] * avv.x + c[mt][nt][3] * avv.y;
            }
#pragma unroll
            for (int o = 1; o < 4; o <<= 1) {
                s0 += __shfl_xor_sync(0xFFFFFFFFu, s0, o);
                s1 += __shfl_xor_sync(0xFFFFFFFFu, s1, o);
            }
            if (tig == 0) {
                int lr0 = warpM * 32 + mt * 16 + gid;
                rb[lr0 * 4 + warpN]       = make_float2(s0, 0.f);
                rb[(lr0 + 8) * 4 + warpN] = make_float2(s1, 0.f);
            }
        }
        __syncthreads();
        if (warpN == 0 && tig == 0) {
#pragma unroll
            for (int mt = 0; mt < 2; mt++) {
                int lr0 = warpM * 32 + mt * 16 + gid;
#pragma unroll
                for (int h = 0; h < 2; h++) {
                    int lr = lr0 + h * 8;
                    int row = rowBase + lr;
                    if (row < Mrows) {
                        snode[row] = rb[lr * 4 + 0].x + rb[lr * 4 + 1].x
                                   + rb[lr * 4 + 2].x + rb[lr * 4 + 3].x;
                    }
                }
            }
        }
    }
}

// ======== fused dual GEMM with snode fusion post-LN2 ========
__global__ __launch_bounds__(512, 1)
void tgemm_dual(const float* __restrict__ A, const unsigned char* __restrict__ Wp1,
                const float* __restrict__ bias1, const float* __restrict__ R1,
                const float* __restrict__ lng1, const float* __restrict__ lnb1,
                const unsigned char* __restrict__ Wp2, const float* __restrict__ bias2,
                const float* __restrict__ lng2, const float* __restrict__ lnb2,
                float* __restrict__ C2, const float* __restrict__ av,
                float* __restrict__ snode, int Mrows)
{
    extern __shared__ __align__(128) unsigned char smem[];
    const uint32_t sb = smem_to_u32(smem);
    const int tid = threadIdx.x, lane = tid & 31, wid = tid >> 5;
    const int warpM = wid >> 2, warpN = wid & 3;
    const int rowBase = blockIdx.x * 128;

    int rA[2], cgA[2];
#pragma unroll
    for (int i = 0; i < 2; i++) {
        int g = tid + i * 512;
        rA[i] = g >> 3; cgA[i] = g & 7;
    }
    float4 pref[4];

    auto issueA = [&](int ch) {
#pragma unroll
        for (int i = 0; i < 2; i++) {
            int row = rowBase + rA[i];
            if (row < Mrows) {
                const float4* src = reinterpret_cast<const float4*>(
                    A + (size_t)row * DD + ch * 64 + cgA[i] * 8);
                pref[i * 2]     = src[0];
                pref[i * 2 + 1] = src[1];
            } else {
                pref[i * 2]     = make_float4(0.f, 0.f, 0.f, 0.f);
                pref[i * 2 + 1] = make_float4(0.f, 0.f, 0.f, 0.f);
            }
        }
    };
    auto storeA = [&](int s) {
#pragma unroll
        for (int i = 0; i < 2; i++) {
            float x[8];
            float4 v0 = pref[i * 2], v1 = pref[i * 2 + 1];
            x[0] = v0.x; x[1] = v0.y; x[2] = v0.z; x[3] = v0.w;
            x[4] = v1.x; x[5] = v1.y; x[6] = v1.z; x[7] = v1.w;
            unsigned short hi[8], lo[8];
#pragma unroll
            for (int j = 0; j < 8; j++) {
                __nv_bfloat16 h = __float2bfloat16(x[j]);
                __nv_bfloat16 l = __float2bfloat16(x[j] - __bfloat162float(h));
                hi[j] = *reinterpret_cast<unsigned short*>(&h);
                lo[j] = *reinterpret_cast<unsigned short*>(&l);
            }
            uint32_t off = 131072u + s * 32768u + swz((uint32_t)rA[i], (uint32_t)cgA[i] * 16u);
            *reinterpret_cast<uint4*>(smem + off)         = *reinterpret_cast<uint4*>(hi);
            *reinterpret_cast<uint4*>(smem + 16384 + off) = *reinterpret_cast<uint4*>(lo);
        }
    };
    auto issueB1 = [&](int ch, int s) {
        const unsigned char* bh = Wp1 + (size_t)(ch * 2 + 0) * 32768;
        const unsigned char* bl = Wp1 + (size_t)(ch * 2 + 1) * 32768;
        uint32_t dh = sb + (uint32_t)s * 65536u;
        uint32_t dl = dh + 32768u;
#pragma unroll
        for (int i = 0; i < 4; i++) {
            int idx = (tid + i * 512) * 16;
            CP_ASYNC16(dh + idx, bh + idx);
            CP_ASYNC16(dl + idx, bl + idx);
        }
        CP_COMMIT();
    };
    auto issueB2 = [&](int ch) {
        const unsigned char* bh = Wp2 + (size_t)(ch * 2 + 0) * 32768;
        const unsigned char* bl = Wp2 + (size_t)(ch * 2 + 1) * 32768;
        uint32_t dh = sb + 131072u;
        uint32_t dl = dh + 32768u;
#pragma unroll
        for (int i = 0; i < 4; i++) {
            int idx = (tid + i * 512) * 16;
            CP_ASYNC16(dh + idx, bh + idx);
            CP_ASYNC16(dl + idx, bl + idx);
        }
        CP_COMMIT();
    };

    float c[2][8][4];
#pragma unroll
    for (int mt = 0; mt < 2; mt++)
#pragma unroll
        for (int nt = 0; nt < 8; nt++)
#pragma unroll
            for (int q = 0; q < 4; q++) c[mt][nt][q] = 0.f;

    // ---- phase 1 ----
    issueA(0);
    issueB1(0, 0);
    storeA(0);

    for (int ch = 0; ch < 4; ch++) {
        const int s = ch & 1;
        if (ch < 3) {
            issueA(ch + 1);
            issueB1(ch + 1, s ^ 1);
            CP_WAIT(1);
        } else {
            CP_WAIT(0);
        }
        __syncthreads();

        const uint32_t aBase = sb + 131072u + (uint32_t)s * 32768u;
        const uint32_t bBase = sb + (uint32_t)s * 65536u;
#pragma unroll
        for (int ks = 0; ks < 4; ks++) {
            uint32_t ah[2][4], al[2][4];
#pragma unroll
            for (int mt = 0; mt < 2; mt++) {
                uint32_t row = (uint32_t)(warpM * 32 + mt * 16 + (lane & 7) + ((lane >> 3) & 1) * 8);
                uint32_t kb  = (uint32_t)(ks * 32 + ((lane >> 4) & 1) * 16);
                uint32_t addr = aBase + swz(row, kb);
                ldm_x4(addr,         ah[mt]);
                ldm_x4(addr + 16384, al[mt]);
            }
#pragma unroll
            for (int p = 0; p < 4; p++) {
                uint32_t nrow = (uint32_t)(warpN * 64 + p * 16 + (lane & 7) + ((lane >> 4) & 1) * 8);
                uint32_t kb   = (uint32_t)(ks * 32 + ((lane >> 3) & 1) * 16);
                uint32_t addr = bBase + swz(nrow, kb);
                uint32_t bh[4], bl[4];
                ldm_x4(addr,         bh);
                ldm_x4(addr + 32768, bl);
#pragma unroll
                for (int t = 0; t < 2; t++) {
#pragma unroll
                    for (int mt = 0; mt < 2; mt++) {
                        float* cc = c[mt][p * 2 + t];
                        mma_bf16(cc, ah[mt], bh + t * 2);
                        mma_bf16(cc, ah[mt], bl + t * 2);
                        mma_bf16(cc, al[mt], bh + t * 2);
                    }
                }
            }
        }
        if (ch < 3) storeA(s ^ 1);
        __syncthreads();
    }

    // ---- epilogue 1 ----
    const int gid = lane >> 2, tig = lane & 3;
    float2* rb = reinterpret_cast<float2*>(smem + 131072);

#pragma unroll
    for (int mt = 0; mt < 2; mt++) {
        int r0 = rowBase + warpM * 32 + mt * 16 + gid;
        int r1 = r0 + 8;
        bool v0 = r0 < Mrows, v1 = r1 < Mrows;
#pragma unroll
        for (int nt = 0; nt < 8; nt++) {
            int col = warpN * 64 + nt * 8 + tig * 2;
            float2 bv = *reinterpret_cast<const float2*>(bias1 + col);
            float o0 = lrelu_f(c[mt][nt][0] + bv.x), o1 = lrelu_f(c[mt][nt][1] + bv.y);
            float o2 = lrelu_f(c[mt][nt][2] + bv.x), o3 = lrelu_f(c[mt][nt][3] + bv.y);
            if (v0) {
                float2 rv = *reinterpret_cast<const float2*>(R1 + (size_t)r0 * DD + col);
                o0 += rv.x; o1 += rv.y;
            }
            if (v1) {
                float2 rv = *reinterpret_cast<const float2*>(R1 + (size_t)r1 * DD + col);
                o2 += rv.x; o3 += rv.y;
            }
            c[mt][nt][0] = o0; c[mt][nt][1] = o1; c[mt][nt][2] = o2; c[mt][nt][3] = o3;
        }
    }
#pragma unroll
    for (int mt = 0; mt < 2; mt++) {
        float s0 = 0.f, q0 = 0.f, s1 = 0.f, q1 = 0.f;
#pragma unroll
        for (int nt = 0; nt < 8; nt++) {
            float o0 = c[mt][nt][0], o1 = c[mt][nt][1];
            float o2 = c[mt][nt][2], o3 = c[mt][nt][3];
            s0 += o0 + o1; q0 += o0 * o0 + o1 * o1;
            s1 += o2 + o3; q1 += o2 * o2 + o3 * o3;
        }
#pragma unroll
        for (int o = 1; o < 4; o <<= 1) {
            s0 += __shfl_xor_sync(0xFFFFFFFFu, s0, o);
            q0 += __shfl_xor_sync(0xFFFFFFFFu, q0, o);
            s1 += __shfl_xor_sync(0xFFFFFFFFu, s1, o);
            q1 += __shfl_xor_sync(0xFFFFFFFFu, q1, o);
        }
        if (tig == 0) {
            int lr0 = warpM * 32 + mt * 16 + gid;
            rb[lr0 * 4 + warpN]       = make_float2(s0, q0);
            rb[(lr0 + 8) * 4 + warpN] = make_float2(s1, q1);
        }
    }
    __syncthreads();
#pragma unroll
    for (int mt = 0; mt < 2; mt++) {
        int lr0 = warpM * 32 + mt * 16 + gid;
        int lr1 = lr0 + 8;
        float2 p00 = rb[lr0*4+0], p01 = rb[lr0*4+1], p02 = rb[lr0*4+2], p03 = rb[lr0*4+3];
        float2 p10 = rb[lr1*4+0], p11 = rb[lr1*4+1], p12 = rb[lr1*4+2], p13 = rb[lr1*4+3];
        float sum0 = p00.x + p01.x + p02.x + p03.x;
        float sq0  = p00.y + p01.y + p02.y + p03.y;
        float sum1 = p10.x + p11.x + p12.x + p13.x;
        float sq1  = p10.y + p11.y + p12.y + p13.y;
        float mean0 = sum0 * (1.f / 256.f);
        float rstd0 = rsqrtf(sq0 * (1.f / 256.f) - mean0 * mean0 + 1e-5f);
        float mean1 = sum1 * (1.f / 256.f);
        float rstd1 = rsqrtf(sq1 * (1.f / 256.f) - mean1 * mean1 + 1e-5f);
#pragma unroll
        for (int nt = 0; nt < 8; nt++) {
            int col = warpN * 64 + nt * 8 + tig * 2;
            float2 gv = *reinterpret_cast<const float2*>(lng1 + col);
            float2 bv = *reinterpret_cast<const float2*>(lnb1 + col);
            c[mt][nt][0] = (c[mt][nt][0] - mean0) * rstd0 * gv.x + bv.x;
            c[mt][nt][1] = (c[mt][nt][1] - mean0) * rstd0 * gv.y + bv.y;
            c[mt][nt][2] = (c[mt][nt][2] - mean1) * rstd1 * gv.x + bv.x;
            c[mt][nt][3] = (c[mt][nt][3] - mean1) * rstd1 * gv.y + bv.y;
        }
    }
    __syncthreads();

    // ---- store obj1 to A2 smem + issue B2 chunk 0 ----
    issueB2(0);
#pragma unroll
    for (int mt = 0; mt < 2; mt++) {
        uint32_t lr0 = (uint32_t)(warpM * 32 + mt * 16 + gid);
        uint32_t lr1 = lr0 + 8;
#pragma unroll
        for (int nt = 0; nt < 8; nt++) {
            uint32_t cb = (uint32_t)(warpN * 64 + nt * 8 + tig * 2) * 2u;
            float o0 = c[mt][nt][0], o1 = c[mt][nt][1];
            float o2 = c[mt][nt][2], o3 = c[mt][nt][3];
            __nv_bfloat16 h0 = __float2bfloat16(o0), h1 = __float2bfloat16(o1);
            __nv_bfloat16 h2 = __float2bfloat16(o2), h3 = __float2bfloat16(o3);
            __nv_bfloat16 l0 = __float2bfloat16(o0 - __bfloat162float(h0));
            __nv_bfloat16 l1 = __float2bfloat16(o1 - __bfloat162float(h1));
            __nv_bfloat16 l2 = __float2bfloat16(o2 - __bfloat162float(h2));
            __nv_bfloat16 l3 = __float2bfloat16(o3 - __bfloat162float(h3));
            uint32_t hp0 = ((uint32_t)*reinterpret_cast<unsigned short*>(&h1) << 16)
                         |  (uint32_t)*reinterpret_cast<unsigned short*>(&h0);
            uint32_t lp0 = ((uint32_t)*reinterpret_cast<unsigned short*>(&l1) << 16)
                         |  (uint32_t)*reinterpret_cast<unsigned short*>(&l0);
            uint32_t hp1 = ((uint32_t)*reinterpret_cast<unsigned short*>(&h3) << 16)
                         |  (uint32_t)*reinterpret_cast<unsigned short*>(&h2);
            uint32_t lp1 = ((uint32_t)*reinterpret_cast<unsigned short*>(&l3) << 16)
                         |  (uint32_t)*reinterpret_cast<unsigned short*>(&l2);
            *reinterpret_cast<uint32_t*>(smem + swz512(lr0, cb))           = hp0;
            *reinterpret_cast<uint32_t*>(smem + 65536u + swz512(lr0, cb))  = lp0;
            *reinterpret_cast<uint32_t*>(smem + swz512(lr1, cb))           = hp1;
            *reinterpret_cast<uint32_t*>(smem + 65536u + swz512(lr1, cb))  = lp1;
        }
    }
#pragma unroll
    for (int mt = 0; mt < 2; mt++)
#pragma unroll
        for (int nt = 0; nt < 8; nt++)
#pragma unroll
            for (int q = 0; q < 4; q++) c[mt][nt][q] = 0.f;
    __syncthreads();

    // ---- phase 2 ----
    for (int ch = 0; ch < 4; ch++) {
        CP_WAIT(0);
        __syncthreads();
        const uint32_t bBase = sb + 131072u;
#pragma unroll
        for (int ks = 0; ks < 4; ks++) {
            uint32_t ah[2][4], al[2][4];
#pragma unroll
            for (int mt = 0; mt < 2; mt++) {
                uint32_t row = (uint32_t)(warpM * 32 + mt * 16 + (lane & 7) + ((lane >> 3) & 1) * 8);
                uint32_t kb  = (uint32_t)(ch * 128 + ks * 32 + ((lane >> 4) & 1) * 16);
                uint32_t addr = sb + swz512(row, kb);
                ldm_x4(addr,          ah[mt]);
                ldm_x4(addr + 65536u, al[mt]);
            }
#pragma unroll
            for (int p = 0; p < 4; p++) {
                uint32_t nrow = (uint32_t)(warpN * 64 + p * 16 + (lane & 7) + ((lane >> 4) & 1) * 8);
                uint32_t kb   = (uint32_t)(ks * 32 + ((lane >> 3) & 1) * 16);
                uint32_t addr = bBase + swz(nrow, kb);
                uint32_t bh[4], bl[4];
                ldm_x4(addr,          bh);
                ldm_x4(addr + 32768u, bl);
#pragma unroll
                for (int t = 0; t < 2; t++) {
#pragma unroll
                    for (int mt = 0; mt < 2; mt++) {
                        float* cc = c[mt][p * 2 + t];
                        mma_bf16(cc, ah[mt], bh + t * 2);
                        mma_bf16(cc, ah[mt], bl + t * 2);
                        mma_bf16(cc, al[mt], bh + t * 2);
                    }
                }
            }
        }
        __syncthreads();
        if (ch < 3) issueB2(ch + 1);
    }

    // ---- epilogue 2: bias2 + lrelu + residual(obj1) + LN2 + snode ----
#pragma unroll
    for (int mt = 0; mt < 2; mt++) {
        uint32_t lr0 = (uint32_t)(warpM * 32 + mt * 16 + gid);
        uint32_t lr1 = lr0 + 8;
#pragma unroll
        for (int nt = 0; nt < 8; nt++) {
            int col = warpN * 64 + nt * 8 + tig * 2;
            uint32_t cb = (uint32_t)col * 2u;
            float2 bv = *reinterpret_cast<const float2*>(bias2 + col);
            float o0 = lrelu_f(c[mt][nt][0] + bv.x), o1 = lrelu_f(c[mt][nt][1] + bv.y);
            float o2 = lrelu_f(c[mt][nt][2] + bv.x), o3 = lrelu_f(c[mt][nt][3] + bv.y);
            uint32_t hp0 = *reinterpret_cast<uint32_t*>(smem + swz512(lr0, cb));
            uint32_t lp0 = *reinterpret_cast<uint32_t*>(smem + 65536u + swz512(lr0, cb));
            uint32_t hp1 = *reinterpret_cast<uint32_t*>(smem + swz512(lr1, cb));
            uint32_t lp1 = *reinterpret_cast<uint32_t*>(smem + 65536u + swz512(lr1, cb));
            unsigned short u;
            u = (unsigned short)(hp0 & 0xFFFF);
            float r0a = __bfloat162float(*reinterpret_cast<__nv_bfloat16*>(&u));
            u = (unsigned short)(lp0 & 0xFFFF);
            r0a += __bfloat162float(*reinterpret_cast<__nv_bfloat16*>(&u));
            u = (unsigned short)(hp0 >> 16);
            float r0b = __bfloat162float(*reinterpret_cast<__nv_bfloat16*>(&u));
            u = (unsigned short)(lp0 >> 16);
            r0b += __bfloat162float(*reinterpret_cast<__nv_bfloat16*>(&u));
            u = (unsigned short)(hp1 & 0xFFFF);
            float r1a = __bfloat162float(*reinterpret_cast<__nv_bfloat16*>(&u));
            u = (unsigned short)(lp1 & 0xFFFF);
            r1a += __bfloat162float(*reinterpret_cast<__nv_bfloat16*>(&u));
            u = (unsigned short)(hp1 >> 16);
            float r1b = __bfloat162float(*reinterpret_cast<__nv_bfloat16*>(&u));
            u = (unsigned short)(lp1 >> 16);
            r1b += __bfloat162float(*reinterpret_cast<__nv_bfloat16*>(&u));
            c[mt][nt][0] = o0 + r0a; c[mt][nt][1] = o1 + r0b;
            c[mt][nt][2] = o2 + r1a; c[mt][nt][3] = o3 + r1b;
        }
    }
#pragma unroll
    for (int mt = 0; mt < 2; mt++) {
        float s0 = 0.f, q0 = 0.f, s1 = 0.f, q1 = 0.f;
#pragma unroll
        for (int nt = 0; nt < 8; nt++) {
            float o0 = c[mt][nt][0], o1 = c[mt][nt][1];
            float o2 = c[mt][nt][2], o3 = c[mt][nt][3];
            s0 += o0 + o1; q0 += o0 * o0 + o1 * o1;
            s1 += o2 + o3; q1 += o2 * o2 + o3 * o3;
        }
#pragma unroll
        for (int o = 1; o < 4; o <<= 1) {
            s0 += __shfl_xor_sync(0xFFFFFFFFu, s0, o);
            q0 += __shfl_xor_sync(0xFFFFFFFFu, q0, o);
            s1 += __shfl_xor_sync(0xFFFFFFFFu, s1, o);
            q1 += __shfl_xor_sync(0xFFFFFFFFu, q1, o);
        }
        if (tig == 0) {
            int lr0 = warpM * 32 + mt * 16 + gid;
            rb[lr0 * 4 + warpN]       = make_float2(s0, q0);
            rb[(lr0 + 8) * 4 + warpN] = make_float2(s1, q1);
        }
    }
    __syncthreads();
    float sd[2][2] = {{0.f, 0.f}, {0.f, 0.f}};
#pragma unroll
    for (int mt = 0; mt < 2; mt++) {
        int lr0 = warpM * 32 + mt * 16 + gid;
        int lr1 = lr0 + 8;
        float2 p00 = rb[lr0*4+0], p01 = rb[lr0*4+1], p02 = rb[lr0*4+2], p03 = rb[lr0*4+3];
        float2 p10 = rb[lr1*4+0], p11 = rb[lr1*4+1], p12 = rb[lr1*4+2], p13 = rb[lr1*4+3];
        float sum0 = p00.x + p01.x + p02.x + p03.x;
        float sq0  = p00.y + p01.y + p02.y + p03.y;
        float sum1 = p10.x + p11.x + p12.x + p13.x;
        float sq1  = p10.y + p11.y + p12.y + p13.y;
        float mean0 = sum0 * (1.f / 256.f);
        float rstd0 = rsqrtf(sq0 * (1.f / 256.f) - mean0 * mean0 + 1e-5f);
        float mean1 = sum1 * (1.f / 256.f);
        float rstd1 = rsqrtf(sq1 * (1.f / 256.f) - mean1 * mean1 + 1e-5f);
        int r0 = rowBase + lr0, r1 = rowBase + lr1;
        bool v0 = r0 < Mrows, v1 = r1 < Mrows;
#pragma unroll
        for (int nt = 0; nt < 8; nt++) {
            int col = warpN * 64 + nt * 8 + tig * 2;
            float2 gv = *reinterpret_cast<const float2*>(lng2 + col);
            float2 bv = *reinterpret_cast<const float2*>(lnb2 + col);
            float o0 = (c[mt][nt][0] - mean0) * rstd0 * gv.x + bv.x;
            float o1 = (c[mt][nt][1] - mean0) * rstd0 * gv.y + bv.y;
            float o2 = (c[mt][nt][2] - mean1) * rstd1 * gv.x + bv.x;
            float o3 = (c[mt][nt][3] - mean1) * rstd1 * gv.y + bv.y;
            if (v0) *reinterpret_cast<float2*>(C2 + (size_t)r0 * DD + col) = make_float2(o0, o1);
            if (v1) *reinterpret_cast<float2*>(C2 + (size_t)r1 * DD + col) = make_float2(o2, o3);
            float2 avv = *reinterpret_cast<const float2*>(av + col);
            sd[mt][0] += o0 * avv.x + o1 * avv.y;
            sd[mt][1] += o2 * avv.x + o3 * avv.y;
        }
    }
    __syncthreads();
#pragma unroll
    for (int mt = 0; mt < 2; mt++) {
        float s0 = sd[mt][0], s1 = sd[mt][1];
#pragma unroll
        for (int o = 1; o < 4; o <<= 1) {
            s0 += __shfl_xor_sync(0xFFFFFFFFu, s0, o);
            s1 += __shfl_xor_sync(0xFFFFFFFFu, s1, o);
        }
        if (tig == 0) {
            int lr0 = warpM * 32 + mt * 16 + gid;
            rb[lr0 * 4 + warpN]       = make_float2(s0, 0.f);
            rb[(lr0 + 8) * 4 + warpN] = make_float2(s1, 0.f);
        }
    }
    __syncthreads();
    if (warpN == 0 && tig == 0) {
#pragma unroll
        for (int mt = 0; mt < 2; mt++) {
            int lr0 = warpM * 32 + mt * 16 + gid;
#pragma unroll
            for (int h = 0; h < 2; h++) {
                int lr = lr0 + h * 8;
                int row = rowBase + lr;
                if (row < Mrows) {
                    snode[row] = rb[lr * 4 + 0].x + rb[lr * 4 + 1].x
                               + rb[lr * 4 + 2].x + rb[lr * 4 + 3].x;
                }
            }
        }
    }
}

// -------- edge gather on raw X --------
__global__ void edge_gatherX(const float* __restrict__ X, const int* __restrict__ hn,
                             const int* __restrict__ permE, const int* __restrict__ offE,
                             const int* __restrict__ cntE, float* __restrict__ Xmean,
                             int act, int nEdges)
{
    int ed = blockIdx.x * 8 + (threadIdx.x >> 5);
    if (ed >= nEdges) return;
    int lane = threadIdx.x & 31;
    int start = offE[ed], deg = cntE[ed];
    float4 a0 = make_float4(0.f,0.f,0.f,0.f), a1 = a0;
    for (int base = 0; base < deg; base += 32) {
        int m = min(32, deg - base);
        int src = 0;
        if (lane < m) src = hn[permE[start + base + lane]];
        for (int i = 0; i < m; i++) {
            int node = __shfl_sync(0xFFFFFFFFu, src, i);
            const float4* rp = reinterpret_cast<const float4*>(X + (size_t)node * DD + lane * 8);
            float4 v0 = rp[0], v1 = rp[1];
            if (act) {
                v0.x = lrelu_f(v0.x); v0.y = lrelu_f(v0.y); v0.z = lrelu_f(v0.z); v0.w = lrelu_f(v0.w);
                v1.x = lrelu_f(v1.x); v1.y = lrelu_f(v1.y); v1.z = lrelu_f(v1.z); v1.w = lrelu_f(v1.w);
            }
            a0.x += v0.x; a0.y += v0.y; a0.z += v0.z; a0.w += v0.w;
            a1.x += v1.x; a1.y += v1.y; a1.z += v1.z; a1.w += v1.w;
        }
    }
    float inv = 1.f / fmaxf((float)deg, 1.f);
    a0.x *= inv; a0.y *= inv; a0.z *= inv; a0.w *= inv;
    a1.x *= inv; a1.y *= inv; a1.z *= inv; a1.w *= inv;
    float4* op = reinterpret_cast<float4*>(Xmean + (size_t)ed * DD + lane * 8);
    op[0] = a0; op[1] = a1;
}

// -------- fused per-node softmax + aggregate (+ optional next-layer snode) --------
__global__ void node_attn_agg(const float* __restrict__ ef, const float* __restrict__ sn,
                              const float* __restrict__ se, const int* __restrict__ he,
                              const int* __restrict__ permN, const int* __restrict__ offN,
                              const int* __restrict__ cntN, float* __restrict__ attn,
                              float* __restrict__ out, const float* __restrict__ av,
                              float* __restrict__ snodeOut, int doLrelu, int nNodes)
{
    int n = blockIdx.x * 8 + (threadIdx.x >> 5);
    if (n >= nNodes) return;
    int lane = threadIdx.x & 31;
    int st = offN[n], deg = cntN[n];
    float4 a0 = make_float4(0.f,0.f,0.f,0.f), a1 = a0;

    if (deg > 0) {
        float s0 = sn[n];
        if (deg <= 32) {
            int inc = 0, ed = 0;
            float sc = -3.4e38f;
            if (lane < deg) {
                inc = permN[st + lane];
                ed = he[inc];
                sc = lrelu_f(s0 + se[ed]);
            }
            float mx = sc;
#pragma unroll
            for (int o = 16; o; o >>= 1) mx = fmaxf(mx, __shfl_xor_sync(0xFFFFFFFFu, mx, o));
            float e = (lane < deg) ? expf(sc - mx) : 0.f;
            float z = e;
#pragma unroll
            for (int o = 16; o; o >>= 1) z += __shfl_xor_sync(0xFFFFFFFFu, z, o);
            float w = e / fmaxf(z, 1e-9f);
            if (lane < deg && attn != nullptr) attn[inc] = w;
            for (int i = 0; i < deg; i++) {
                int e_   = __shfl_sync(0xFFFFFFFFu, ed, i);
                float w_ = __shfl_sync(0xFFFFFFFFu, w, i);
                const float4* rp = reinterpret_cast<const float4*>(ef + (size_t)e_ * DD + lane * 8);
                float4 v0 = rp[0], v1 = rp[1];
                a0.x += w_*v0.x; a0.y += w_*v0.y; a0.z += w_*v0.z; a0.w += w_*v0.w;
                a1.x += w_*v1.x; a1.y += w_*v1.y; a1.z += w_*v1.z; a1.w += w_*v1.w;
            }
        } else {
            float mx = -3.4e38f;
            for (int base = 0; base < deg; base += 32) {
                float sc = -3.4e38f;
                if (base + lane < deg) {
                    int inc = permN[st + base + lane];
                    sc = lrelu_f(s0 + se[he[inc]]);
                }
                mx = fmaxf(mx, sc);
            }
#pragma unroll
            for (int o = 16; o; o >>= 1) mx = fmaxf(mx, __shfl_xor_sync(0xFFFFFFFFu, mx, o));
            float z = 0.f;
            for (int base = 0; base < deg; base += 32) {
                if (base + lane < deg) {
                    int inc = permN[st + base + lane];
                    z += expf(lrelu_f(s0 + se[he[inc]]) - mx);
                }
            }
#pragma unroll
            for (int o = 16; o; o >>= 1) z += __shfl_xor_sync(0xFFFFFFFFu, z, o);
            float invz = 1.f / fmaxf(z, 1e-9f);
            for (int base = 0; base < deg; base += 32) {
                int m = min(32, deg - base);
                int ed = 0; float w = 0.f;
                if (lane < m) {
                    int inc = permN[st + base + lane];
                    ed = he[inc];
                    w = expf(lrelu_f(s0 + se[ed]) - mx) * invz;
                    if (attn != nullptr) attn[inc] = w;
                }
                for (int i = 0; i < m; i++) {
                    int e_   = __shfl_sync(0xFFFFFFFFu, ed, i);
                    float w_ = __shfl_sync(0xFFFFFFFFu, w, i);
                    const float4* rp = reinterpret_cast<const float4*>(ef + (size_t)e_ * DD + lane * 8);
                    float4 v0 = rp[0], v1 = rp[1];
                    a0.x += w_*v0.x; a0.y += w_*v0.y; a0.z += w_*v0.z; a0.w += w_*v0.w;
                    a1.x += w_*v1.x; a1.y += w_*v1.y; a1.z += w_*v1.z; a1.w += w_*v1.w;
                }
            }
        }
    }
    // next-layer snode: dot(lrelu(row), av) — computed before output activation
    if (snodeOut != nullptr) {
        const float4* ap = reinterpret_cast<const float4*>(av + lane * 8);
        float4 w0 = ap[0], w1 = ap[1];
        float d = lrelu_f(a0.x)*w0.x + lrelu_f(a0.y)*w0.y + lrelu_f(a0.z)*w0.z + lrelu_f(a0.w)*w0.w
                + lrelu_f(a1.x)*w1.x + lrelu_f(a1.y)*w1.y + lrelu_f(a1.z)*w1.z + lrelu_f(a1.w)*w1.w;
#pragma unroll
        for (int o = 16; o; o >>= 1) d += __shfl_xor_sync(0xFFFFFFFFu, d, o);
        if (lane == 0) snodeOut[n] = d;
    }
    if (doLrelu) {
        a0.x = lrelu_f(a0.x); a0.y = lrelu_f(a0.y); a0.z = lrelu_f(a0.z); a0.w = lrelu_f(a0.w);
        a1.x = lrelu_f(a1.x); a1.y = lrelu_f(a1.y); a1.z = lrelu_f(a1.z); a1.w = lrelu_f(a1.w);
    }
    float4* op = reinterpret_cast<float4*>(out + (size_t)n * DD + lane * 8);
    op[0] = a0; op[1] = a1;
}

// -------- object message gather --------
__global__ void obj_gather(const float* __restrict__ ev, const int* __restrict__ oe_ev,
                           const int* __restrict__ permO, const int* __restrict__ offO,
                           const int* __restrict__ cntO, float* __restrict__ msg, int nObj)
{
    int o = blockIdx.x * 8 + (threadIdx.x >> 5);
    if (o >= nObj) return;
    int lane = threadIdx.x & 31;
    int start = offO[o], deg = cntO[o];
    float4 a0 = make_float4(0.f,0.f,0.f,0.f), a1 = a0;
    for (int base = 0; base < deg; base += 32) {
        int m = min(32, deg - base);
        int src = 0;
        if (lane < m) src = oe_ev[permO[start + base + lane]];
        for (int i = 0; i < m; i++) {
            int row = __shfl_sync(0xFFFFFFFFu, src, i);
            const float4* rp = reinterpret_cast<const float4*>(ev + (size_t)row * DD + lane * 8);
            float4 v0 = rp[0], v1 = rp[1];
            a0.x += v0.x; a0.y += v0.y; a0.z += v0.z; a0.w += v0.w;
            a1.x += v1.x; a1.y += v1.y; a1.z += v1.z; a1.w += v1.w;
        }
    }
    float4* op = reinterpret_cast<float4*>(msg + (size_t)o * DD + lane * 8);
    op[0] = a0; op[1] = a1;
}

// ----------------- host orchestration -----------------
struct Ptrs {
    float *X, *obj, *msg, *H, *ef, *snode, *sedge, *wav1, *wav2;
    unsigned char* wp;
    int *cntE, *offE, *permE, *cntN, *offN, *permN, *cntO, *offO, *permO;
};

static void get_ptrs(Ptrs& p) {
    cudaGetSymbolAddress((void**)&p.X,     g_X);
    cudaGetSymbolAddress((void**)&p.obj,   g_obj);
    cudaGetSymbolAddress((void**)&p.msg,   g_msg);
    cudaGetSymbolAddress((void**)&p.H,     g_H);
    cudaGetSymbolAddress((void**)&p.ef,    g_ef);
    cudaGetSymbolAddress((void**)&p.snode, g_snode);
    cudaGetSymbolAddress((void**)&p.sedge, g_sedge);
    cudaGetSymbolAddress((void**)&p.wav1,  g_wav1);
    cudaGetSymbolAddress((void**)&p.wav2,  g_wav2);
    cudaGetSymbolAddress((void**)&p.wp,    g_Wprep);
    cudaGetSymbolAddress((void**)&p.cntE,  g_cntE);
    cudaGetSymbolAddress((void**)&p.offE,  g_offE);
    cudaGetSymbolAddress((void**)&p.permE, g_permE);
    cudaGetSymbolAddress((void**)&p.cntN,  g_cntN);
    cudaGetSymbolAddress((void**)&p.offN,  g_offN);
    cudaGetSymbolAddress((void**)&p.permN, g_permN);
    cudaGetSymbolAddress((void**)&p.cntO,  g_cntO);
    cudaGetSymbolAddress((void**)&p.offO,  g_offO);
    cudaGetSymbolAddress((void**)&p.permO, g_permO);
}

extern "C" void kernel_launch(void* const* d_in, const int* in_sizes, int n_in,
                              void* d_out, int out_size)
{
    const float* object_X = (const float*)d_in[0];
    const float* event_X  = (const float*)d_in[1];
    const float* Wo = (const float*)d_in[2];  const float* bo  = (const float*)d_in[3];
    const float* go = (const float*)d_in[4];  const float* bon = (const float*)d_in[5];
    const float* We = (const float*)d_in[6];  const float* be  = (const float*)d_in[7];
    const float* ge = (const float*)d_in[8];  const float* ben = (const float*)d_in[9];
    const float* Wu = (const float*)d_in[10]; const float* bu  = (const float*)d_in[11];
    const float* Wl = (const float*)d_in[12]; const float* bl  = (const float*)d_in[13];
    const float* g1 = (const float*)d_in[14]; const float* b1  = (const float*)d_in[15];
    const float* g2 = (const float*)d_in[16]; const float* b2  = (const float*)d_in[17];
    const float* Wh1 = (const float*)d_in[18]; const float* ah1 = (const float*)d_in[19];
    const float* Wh2 = (const float*)d_in[20]; const float* ah2 = (const float*)d_in[21];
    const int* oe_ev   = (const int*)d_in[22];
    const int* oe_obj  = (const int*)d_in[23];
    const int* hg_node = (const int*)d_in[24];
    const int* hg_edge = (const int*)d_in[25];

    Ptrs p; get_ptrs(p);

    // 0) preps + CSR
    prep_w<<<dim3(32, 6), 256>>>(We, Wo, Wu, Wl, Wh1, Wh2);
    prep_wav<<<(DD + 7) / 8, 256>>>(Wh1, ah1, p.wav1);
    prep_wav<<<(DD + 7) / 8, 256>>>(Wh2, ah2, p.wav2);
    zero_misc<<<(2 * (NE + NN + NO) + 255) / 256, 256>>>();
    count_all<<<(2 * E2N + E1N + 255) / 256, 256>>>(hg_edge, hg_node, oe_obj);
    scan_all<<<NBT, 1024>>>();
    scan_small3<<<1, 32>>>();
    add_off_all<<<(NE + NN + NO + 255) / 256, 256>>>();
    fill_all<<<(2 * E2N + E1N + 255) / 256, 256>>>(hg_edge, hg_node, oe_obj);

    const unsigned char *wpe = p.wp, *wpo = p.wp + 262144, *wpu = p.wp + 2 * 262144,
                        *wpl = p.wp + 3 * 262144, *wph1 = p.wp + 4 * 262144,
                        *wph2 = p.wp + 5 * 262144;

    // 1+2) combined projection: ev (-> X[0:NE), snode fused) and obj
    cudaFuncSetAttribute(proj_gemm, cudaFuncAttributeMaxDynamicSharedMemorySize, SMEM_SZ);
    int nb0 = (NE + 127) / 128, nb1 = (NO + 127) / 128;
    proj_gemm<<<nb0 + nb1, 512, SMEM_SZ>>>(
        event_X, wpe, be, ge, ben, p.X, p.wav1, p.snode, NE, nb0,
        object_X, wpo, bo, go, bon, p.obj, NO);

    // 3) msg = segment_sum(ev[oe_ev], oe_obj)
    obj_gather<<<(NO + 7) / 8, 256>>>(p.X, oe_ev, p.permO, p.offO, p.cntO, p.msg, NO);

    // 4+5) fused dual GEMM -> X[NE:NN) + snode for obj rows
    cudaFuncSetAttribute(tgemm_dual, cudaFuncAttributeMaxDynamicSharedMemorySize, SMEM_SZ);
    tgemm_dual<<<(NO + 127) / 128, 512, SMEM_SZ>>>(p.msg, wpu, bu, p.obj, g1, b1,
                                                   wpl, bl, g2, b2,
                                                   p.X + (size_t)NE * DD,
                                                   p.wav1, p.snode + NE, NO);

    // 6) HGNN layer 1 -> H; snode2 fused into node_attn_agg
    cudaFuncSetAttribute(tgemm256<F_SNODE>, cudaFuncAttributeMaxDynamicSharedMemorySize, SMEM_SZ);
    edge_gatherX<<<(NE + 7) / 8, 256>>>(p.X, hg_node, p.permE, p.offE, p.cntE, p.msg, 0, NE);
    tgemm256<F_SNODE><<<(NE + 127) / 128, 512, SMEM_SZ>>>(p.msg, wph1, ah1 + DD, p.ef, p.sedge, NE);
    node_attn_agg<<<(NN + 7) / 8, 256>>>(p.ef, p.snode, p.sedge, hg_edge,
                                         p.permN, p.offN, p.cntN,
                                         nullptr, p.H, p.wav2, p.snode, 0, NN);

    // 7) HGNN layer 2 -> d_out
    float* out = (float*)d_out;
    edge_gatherX<<<(NE + 7) / 8, 256>>>(p.H, hg_node, p.permE, p.offE, p.cntE, p.msg, 1, NE);
    tgemm256<F_SNODE><<<(NE + 127) / 128, 512, SMEM_SZ>>>(p.msg, wph2, ah2 + DD, p.ef, p.sedge, NE);
    node_attn_agg<<<(NN + 7) / 8, 256>>>(p.ef, p.snode, p.sedge, hg_edge,
                                         p.permN, p.offN, p.cntN,
                                         out + (size_t)NN * DD, out, nullptr, nullptr, 1, NN);
}

// round 10
// speedup vs baseline: 2.8043x; 1.0320x over previous
#include <cuda_runtime.h>
#include <cuda_bf16.h>
#include <cstdint>

#define DD 256
static const int NE  = 50000;
static const int NO  = 100000;
static const int NN  = 150000;
static const int E1N = 400000;
static const int E2N = 800000;

// -------- device scratch --------
__device__ float    g_X  [(size_t)NN * DD];
__device__ float    g_obj[(size_t)NO * DD];
__device__ float    g_msg[(size_t)NO * DD];   // also Xmean[NE*DD] in hgnn layers
__device__ float    g_H  [(size_t)NN * DD];
__device__ float    g_ef [(size_t)NE * DD];
__device__ float    g_snode[NN];
__device__ float    g_sedge[NE];
__device__ float    g_wav1[DD];
__device__ float    g_wav2[DD];
__device__ unsigned char g_Wprep[6 * 4 * 2 * 256 * 128];
// CSR structures (value-direct)
__device__ int g_cntE[NE],  g_offE[NE],  g_nodeE[E2N];   // node ids per edge
__device__ int g_cntN[NN],  g_offN[NN],  g_permN[E2N], g_edN[E2N];  // inc ids + edge ids per node
__device__ int g_cntO[NO],  g_offO[NO],  g_srcO[E1N];   // event row ids per object
__device__ int g_cur[NE + NN + NO];
__device__ int g_bsum[512];

static const int NBE = (NE + 1023) / 1024;
static const int NBN = (NN + 1023) / 1024;
static const int NBO = (NO + 1023) / 1024;
static const int NBT = NBE + NBN + NBO;

// -------- helpers --------
__device__ __forceinline__ float lrelu_f(float x) { return x >= 0.f ? x : 0.2f * x; }

__device__ __forceinline__ uint32_t smem_to_u32(const void* p) {
    uint32_t a;
    asm("{ .reg .u64 t; cvta.to.shared.u64 t, %1; cvt.u32.u64 %0, t; }" : "=r"(a) : "l"(p));
    return a;
}
__device__ __forceinline__ void ldm_x4(uint32_t addr, uint32_t* r) {
    asm volatile("ldmatrix.sync.aligned.m8n8.x4.shared.b16 {%0,%1,%2,%3}, [%4];"
                 : "=r"(r[0]), "=r"(r[1]), "=r"(r[2]), "=r"(r[3]) : "r"(addr));
}
__device__ __forceinline__ void mma_bf16(float* c, const uint32_t* a, const uint32_t* b) {
    asm volatile("mma.sync.aligned.m16n8k16.row.col.f32.bf16.bf16.f32 "
                 "{%0,%1,%2,%3}, {%4,%5,%6,%7}, {%8,%9}, {%0,%1,%2,%3};"
                 : "+f"(c[0]), "+f"(c[1]), "+f"(c[2]), "+f"(c[3])
                 : "r"(a[0]), "r"(a[1]), "r"(a[2]), "r"(a[3]), "r"(b[0]), "r"(b[1]));
}
__device__ __forceinline__ uint32_t swz(uint32_t row, uint32_t cb) {
    return row * 128u + (cb ^ ((row & 7u) << 4));
}
__device__ __forceinline__ uint32_t swz512(uint32_t row, uint32_t cb) {
    return row * 512u + (cb ^ ((row & 7u) << 4));
}
#define CP_ASYNC16(dst, src) \
    asm volatile("cp.async.cg.shared.global [%0], [%1], 16;" :: "r"(dst), "l"(src) : "memory")
#define CP_COMMIT() asm volatile("cp.async.commit_group;" ::: "memory")
#define CP_WAIT(n)  asm volatile("cp.async.wait_group %0;" :: "n"(n) : "memory")

enum { F_SNODE = 16 };

// ======== condensed CSR build ========
__global__ void zero_misc()
{
    int g = blockIdx.x * blockDim.x + threadIdx.x;
    if (g < NE) g_cntE[g] = 0;
    else if (g < NE + NN) g_cntN[g - NE] = 0;
    else if (g < NE + NN + NO) g_cntO[g - NE - NN] = 0;
    int h = g - (NE + NN + NO);
    if (h >= 0 && h < NE + NN + NO) g_cur[h] = 0;
}
__global__ void count_all(const int* __restrict__ he, const int* __restrict__ hn,
                          const int* __restrict__ oo)
{
    int t = blockIdx.x * blockDim.x + threadIdx.x;
    if (t < E2N) atomicAdd(&g_cntE[he[t]], 1);
    else if (t < 2 * E2N) atomicAdd(&g_cntN[hn[t - E2N]], 1);
    else if (t < 2 * E2N + E1N) atomicAdd(&g_cntO[oo[t - 2 * E2N]], 1);
}
__global__ void scan_all()
{
    __shared__ int sh[1024];
    int b = blockIdx.x;
    const int* cnt; int* off; int nseg; int lb;
    if (b < NBE)            { cnt = g_cntE; off = g_offE; nseg = NE; lb = b; }
    else if (b < NBE + NBN) { cnt = g_cntN; off = g_offN; nseg = NN; lb = b - NBE; }
    else                    { cnt = g_cntO; off = g_offO; nseg = NO; lb = b - NBE - NBN; }
    int g = lb * 1024 + threadIdx.x;
    int v = (g < nseg) ? cnt[g] : 0;
    sh[threadIdx.x] = v;
    __syncthreads();
#pragma unroll
    for (int o = 1; o < 1024; o <<= 1) {
        int t = (threadIdx.x >= o) ? sh[threadIdx.x - o] : 0;
        __syncthreads();
        sh[threadIdx.x] += t;
        __syncthreads();
    }
    if (g < nseg) off[g] = sh[threadIdx.x] - v;
    if (threadIdx.x == 1023) g_bsum[b] = sh[1023];
}
__global__ void scan_small3()
{
    int t = threadIdx.x;
    int s, e;
    if (t == 0)      { s = 0;          e = NBE; }
    else if (t == 1) { s = NBE;        e = NBE + NBN; }
    else if (t == 2) { s = NBE + NBN;  e = NBT; }
    else return;
    int run = 0;
    for (int i = s; i < e; i++) { int v = g_bsum[i]; g_bsum[i] = run; run += v; }
}
__global__ void add_off_all()
{
    int g = blockIdx.x * blockDim.x + threadIdx.x;
    if (g < NE) g_offE[g] += g_bsum[g >> 10];
    else if (g < NE + NN) {
        int l = g - NE; g_offN[l] += g_bsum[NBE + (l >> 10)];
    } else if (g < NE + NN + NO) {
        int l = g - NE - NN; g_offO[l] += g_bsum[NBE + NBN + (l >> 10)];
    }
}
__global__ void fill_all(const int* __restrict__ he, const int* __restrict__ hn,
                         const int* __restrict__ oo, const int* __restrict__ oev)
{
    int t = blockIdx.x * blockDim.x + threadIdx.x;
    if (t < E2N) {
        int s = he[t];
        int pos = g_offE[s] + atomicAdd(&g_cur[s], 1);
        g_nodeE[pos] = hn[t];                      // store node id directly
    } else if (t < 2 * E2N) {
        int e = t - E2N;
        int s = hn[e];
        int pos = g_offN[s] + atomicAdd(&g_cur[NE + s], 1);
        g_permN[pos] = e;
        g_edN[pos]   = he[e];                      // store edge id directly
    } else if (t < 2 * E2N + E1N) {
        int e = t - 2 * E2N;
        int s = oo[e];
        int pos = g_offO[s] + atomicAdd(&g_cur[NE + NN + s], 1);
        g_srcO[pos] = oev[e];                      // store event row directly
    }
}

// -------- weight prep --------
__global__ void prep_w(const float* W0, const float* W1, const float* W2,
                       const float* W3, const float* W4, const float* W5)
{
    const float* Ws[6] = {W0, W1, W2, W3, W4, W5};
    const float* W = Ws[blockIdx.y];
    unsigned char* base = g_Wprep + (size_t)blockIdx.y * 262144;
    int g = blockIdx.x * 256 + threadIdx.x;
    int n = g >> 5, kg = g & 31, k0 = kg * 8;
    unsigned short hi[8], lo[8];
#pragma unroll
    for (int i = 0; i < 8; i++) {
        float x = W[(size_t)(k0 + i) * DD + n];
        __nv_bfloat16 h = __float2bfloat16(x);
        __nv_bfloat16 l = __float2bfloat16(x - __bfloat162float(h));
        hi[i] = *reinterpret_cast<unsigned short*>(&h);
        lo[i] = *reinterpret_cast<unsigned short*>(&l);
    }
    int chunk = k0 >> 6, kc = k0 & 63;
    uint32_t off = (uint32_t)n * 128u + (((uint32_t)kc * 2u) ^ (((uint32_t)n & 7u) << 4));
    *reinterpret_cast<uint4*>(base + (size_t)(chunk * 2 + 0) * 32768 + off) =
        *reinterpret_cast<uint4*>(hi);
    *reinterpret_cast<uint4*>(base + (size_t)(chunk * 2 + 1) * 32768 + off) =
        *reinterpret_cast<uint4*>(lo);
}

__global__ void prep_wav(const float* __restrict__ W, const float* __restrict__ a,
                         float* __restrict__ w)
{
    int k = blockIdx.x * 8 + (threadIdx.x >> 5);
    if (k >= DD) return;
    int lane = threadIdx.x & 31;
    const float4* rp = reinterpret_cast<const float4*>(W + (size_t)k * DD);
    const float4* ap = reinterpret_cast<const float4*>(a);
    float4 v0 = rp[lane], v1 = rp[lane + 32];
    float4 a0 = ap[lane], a1 = ap[lane + 32];
    float d = v0.x*a0.x + v0.y*a0.y + v0.z*a0.z + v0.w*a0.w
            + v1.x*a1.x + v1.y*a1.y + v1.z*a1.z + v1.w*a1.w;
#pragma unroll
    for (int o = 16; o; o >>= 1) d += __shfl_xor_sync(0xFFFFFFFFu, d, o);
    if (lane == 0) w[k] = d;
}

static const int SMEM_SZ = 196608;

// ======== combined projection GEMM ========
__global__ __launch_bounds__(512, 1)
void proj_gemm(const float* __restrict__ A0, const unsigned char* __restrict__ Wp0,
               const float* __restrict__ bias0, const float* __restrict__ lng0,
               const float* __restrict__ lnb0, float* __restrict__ C0,
               const float* __restrict__ av0, float* __restrict__ snode0, int M0, int nb0,
               const float* __restrict__ A1, const unsigned char* __restrict__ Wp1,
               const float* __restrict__ bias1, const float* __restrict__ lng1,
               const float* __restrict__ lnb1, float* __restrict__ C1, int M1)
{
    extern __shared__ __align__(128) unsigned char smem[];
    const uint32_t sb = smem_to_u32(smem);
    const int tid = threadIdx.x, lane = tid & 31, wid = tid >> 5;
    const int warpM = wid >> 2, warpN = wid & 3;

    const float* A; const unsigned char* Wp; const float* bias;
    const float* lng; const float* lnb; float* C;
    const float* av; float* snode; int Mrows, rowBase;
    if ((int)blockIdx.x < nb0) {
        A = A0; Wp = Wp0; bias = bias0; lng = lng0; lnb = lnb0; C = C0;
        av = av0; snode = snode0; Mrows = M0; rowBase = blockIdx.x * 128;
    } else {
        A = A1; Wp = Wp1; bias = bias1; lng = lng1; lnb = lnb1; C = C1;
        av = nullptr; snode = nullptr; Mrows = M1; rowBase = (blockIdx.x - nb0) * 128;
    }

    int rA[2], cgA[2];
#pragma unroll
    for (int i = 0; i < 2; i++) {
        int g = tid + i * 512;
        rA[i] = g >> 3; cgA[i] = g & 7;
    }
    float4 pref[4];

    auto issueA = [&](int ch) {
#pragma unroll
        for (int i = 0; i < 2; i++) {
            int row = rowBase + rA[i];
            if (row < Mrows) {
                const float4* src = reinterpret_cast<const float4*>(
                    A + (size_t)row * DD + ch * 64 + cgA[i] * 8);
                pref[i * 2]     = src[0];
                pref[i * 2 + 1] = src[1];
            } else {
                pref[i * 2]     = make_float4(0.f, 0.f, 0.f, 0.f);
                pref[i * 2 + 1] = make_float4(0.f, 0.f, 0.f, 0.f);
            }
        }
    };
    auto storeA = [&](int s) {
#pragma unroll
        for (int i = 0; i < 2; i++) {
            float x[8];
            float4 v0 = pref[i * 2], v1 = pref[i * 2 + 1];
            x[0] = v0.x; x[1] = v0.y; x[2] = v0.z; x[3] = v0.w;
            x[4] = v1.x; x[5] = v1.y; x[6] = v1.z; x[7] = v1.w;
            unsigned short hi[8], lo[8];
#pragma unroll
            for (int j = 0; j < 8; j++) {
                __nv_bfloat16 h = __float2bfloat16(x[j]);
                __nv_bfloat16 l = __float2bfloat16(x[j] - __bfloat162float(h));
                hi[j] = *reinterpret_cast<unsigned short*>(&h);
                lo[j] = *reinterpret_cast<unsigned short*>(&l);
            }
            uint32_t off = s * 32768u + swz((uint32_t)rA[i], (uint32_t)cgA[i] * 16u);
            *reinterpret_cast<uint4*>(smem + off)         = *reinterpret_cast<uint4*>(hi);
            *reinterpret_cast<uint4*>(smem + 16384 + off) = *reinterpret_cast<uint4*>(lo);
        }
    };
    auto issueB = [&](int ch, int s) {
        const unsigned char* bh = Wp + (size_t)(ch * 2 + 0) * 32768;
        const unsigned char* bl = Wp + (size_t)(ch * 2 + 1) * 32768;
        uint32_t dh = sb + 65536u + (uint32_t)s * 65536u;
        uint32_t dl = dh + 32768u;
#pragma unroll
        for (int i = 0; i < 4; i++) {
            int idx = (tid + i * 512) * 16;
            CP_ASYNC16(dh + idx, bh + idx);
            CP_ASYNC16(dl + idx, bl + idx);
        }
        CP_COMMIT();
    };

    float c[2][8][4];
#pragma unroll
    for (int mt = 0; mt < 2; mt++)
#pragma unroll
        for (int nt = 0; nt < 8; nt++)
#pragma unroll
            for (int q = 0; q < 4; q++) c[mt][nt][q] = 0.f;

    issueA(0);
    issueB(0, 0);
    storeA(0);

    for (int ch = 0; ch < 4; ch++) {
        const int s = ch & 1;
        if (ch < 3) {
            issueA(ch + 1);
            issueB(ch + 1, s ^ 1);
            CP_WAIT(1);
        } else {
            CP_WAIT(0);
        }
        __syncthreads();

        const uint32_t aBase = sb + (uint32_t)s * 32768u;
        const uint32_t bBase = sb + 65536u + (uint32_t)s * 65536u;
#pragma unroll
        for (int ks = 0; ks < 4; ks++) {
            uint32_t ah[2][4], al[2][4];
#pragma unroll
            for (int mt = 0; mt < 2; mt++) {
                uint32_t row = (uint32_t)(warpM * 32 + mt * 16 + (lane & 7) + ((lane >> 3) & 1) * 8);
                uint32_t kb  = (uint32_t)(ks * 32 + ((lane >> 4) & 1) * 16);
                uint32_t addr = aBase + swz(row, kb);
                ldm_x4(addr,         ah[mt]);
                ldm_x4(addr + 16384, al[mt]);
            }
#pragma unroll
            for (int p = 0; p < 4; p++) {
                uint32_t nrow = (uint32_t)(warpN * 64 + p * 16 + (lane & 7) + ((lane >> 4) & 1) * 8);
                uint32_t kb   = (uint32_t)(ks * 32 + ((lane >> 3) & 1) * 16);
                uint32_t addr = bBase + swz(nrow, kb);
                uint32_t bh[4], bl[4];
                ldm_x4(addr,         bh);
                ldm_x4(addr + 32768, bl);
#pragma unroll
                for (int t = 0; t < 2; t++) {
#pragma unroll
                    for (int mt = 0; mt < 2; mt++) {
                        float* cc = c[mt][p * 2 + t];
                        mma_bf16(cc, ah[mt], bh + t * 2);
                        mma_bf16(cc, ah[mt], bl + t * 2);
                        mma_bf16(cc, al[mt], bh + t * 2);
                    }
                }
            }
        }
        if (ch < 3) storeA(s ^ 1);
        __syncthreads();
    }

    const int gid = lane >> 2, tig = lane & 3;
    float2* rb = reinterpret_cast<float2*>(smem);

#pragma unroll
    for (int mt = 0; mt < 2; mt++)
#pragma unroll
        for (int nt = 0; nt < 8; nt++) {
            int col = warpN * 64 + nt * 8 + tig * 2;
            float2 bv = *reinterpret_cast<const float2*>(bias + col);
            c[mt][nt][0] = lrelu_f(c[mt][nt][0] + bv.x);
            c[mt][nt][1] = lrelu_f(c[mt][nt][1] + bv.y);
            c[mt][nt][2] = lrelu_f(c[mt][nt][2] + bv.x);
            c[mt][nt][3] = lrelu_f(c[mt][nt][3] + bv.y);
        }

#pragma unroll
    for (int mt = 0; mt < 2; mt++) {
        float s0 = 0.f, q0 = 0.f, s1 = 0.f, q1 = 0.f;
#pragma unroll
        for (int nt = 0; nt < 8; nt++) {
            float o0 = c[mt][nt][0], o1 = c[mt][nt][1];
            float o2 = c[mt][nt][2], o3 = c[mt][nt][3];
            s0 += o0 + o1; q0 += o0 * o0 + o1 * o1;
            s1 += o2 + o3; q1 += o2 * o2 + o3 * o3;
        }
#pragma unroll
        for (int o = 1; o < 4; o <<= 1) {
            s0 += __shfl_xor_sync(0xFFFFFFFFu, s0, o);
            q0 += __shfl_xor_sync(0xFFFFFFFFu, q0, o);
            s1 += __shfl_xor_sync(0xFFFFFFFFu, s1, o);
            q1 += __shfl_xor_sync(0xFFFFFFFFu, q1, o);
        }
        if (tig == 0) {
            int lr0 = warpM * 32 + mt * 16 + gid;
            rb[lr0 * 4 + warpN]       = make_float2(s0, q0);
            rb[(lr0 + 8) * 4 + warpN] = make_float2(s1, q1);
        }
    }
    __syncthreads();

    float sd[2][2] = {{0.f, 0.f}, {0.f, 0.f}};
#pragma unroll
    for (int mt = 0; mt < 2; mt++) {
        int lr0 = warpM * 32 + mt * 16 + gid;
        int lr1 = lr0 + 8;
        float2 p00 = rb[lr0*4+0], p01 = rb[lr0*4+1], p02 = rb[lr0*4+2], p03 = rb[lr0*4+3];
        float2 p10 = rb[lr1*4+0], p11 = rb[lr1*4+1], p12 = rb[lr1*4+2], p13 = rb[lr1*4+3];
        float sum0 = p00.x + p01.x + p02.x + p03.x;
        float sq0  = p00.y + p01.y + p02.y + p03.y;
        float sum1 = p10.x + p11.x + p12.x + p13.x;
        float sq1  = p10.y + p11.y + p12.y + p13.y;
        float mean0 = sum0 * (1.f / 256.f);
        float rstd0 = rsqrtf(sq0 * (1.f / 256.f) - mean0 * mean0 + 1e-5f);
        float mean1 = sum1 * (1.f / 256.f);
        float rstd1 = rsqrtf(sq1 * (1.f / 256.f) - mean1 * mean1 + 1e-5f);
        int r0 = rowBase + lr0, r1 = rowBase + lr1;
        bool v0 = r0 < Mrows, v1 = r1 < Mrows;
#pragma unroll
        for (int nt = 0; nt < 8; nt++) {
            int col = warpN * 64 + nt * 8 + tig * 2;
            float2 gv = *reinterpret_cast<const float2*>(lng + col);
            float2 bv = *reinterpret_cast<const float2*>(lnb + col);
            float o0 = (c[mt][nt][0] - mean0) * rstd0 * gv.x + bv.x;
            float o1 = (c[mt][nt][1] - mean0) * rstd0 * gv.y + bv.y;
            float o2 = (c[mt][nt][2] - mean1) * rstd1 * gv.x + bv.x;
            float o3 = (c[mt][nt][3] - mean1) * rstd1 * gv.y + bv.y;
            if (v0) *reinterpret_cast<float2*>(C + (size_t)r0 * DD + col) = make_float2(o0, o1);
            if (v1) *reinterpret_cast<float2*>(C + (size_t)r1 * DD + col) = make_float2(o2, o3);
            if (snode != nullptr) {
                float2 avv = *reinterpret_cast<const float2*>(av + col);
                sd[mt][0] += o0 * avv.x + o1 * avv.y;
                sd[mt][1] += o2 * avv.x + o3 * avv.y;
            }
        }
    }

    if (snode != nullptr) {
        __syncthreads();
#pragma unroll
        for (int mt = 0; mt < 2; mt++) {
            float s0 = sd[mt][0], s1 = sd[mt][1];
#pragma unroll
            for (int o = 1; o < 4; o <<= 1) {
                s0 += __shfl_xor_sync(0xFFFFFFFFu, s0, o);
                s1 += __shfl_xor_sync(0xFFFFFFFFu, s1, o);
            }
            if (tig == 0) {
                int lr0 = warpM * 32 + mt * 16 + gid;
                rb[lr0 * 4 + warpN]       = make_float2(s0, 0.f);
                rb[(lr0 + 8) * 4 + warpN] = make_float2(s1, 0.f);
            }
        }
        __syncthreads();
        if (warpN == 0 && tig == 0) {
#pragma unroll
            for (int mt = 0; mt < 2; mt++) {
                int lr0 = warpM * 32 + mt * 16 + gid;
#pragma unroll
                for (int h = 0; h < 2; h++) {
                    int lr = lr0 + h * 8;
                    int row = rowBase + lr;
                    if (row < Mrows) {
                        snode[row] = rb[lr * 4 + 0].x + rb[lr * 4 + 1].x
                                   + rb[lr * 4 + 2].x + rb[lr * 4 + 3].x;
                    }
                }
            }
        }
    }
}

// ======== hgnn edge GEMM ========
template <int FLAGS>
__global__ __launch_bounds__(512, 1)
void tgemm256(const float* __restrict__ A, const unsigned char* __restrict__ Wp,
              const float* __restrict__ av, float* __restrict__ C,
              float* __restrict__ snode, int Mrows)
{
    extern __shared__ __align__(128) unsigned char smem[];
    const uint32_t sb = smem_to_u32(smem);
    const int tid = threadIdx.x, lane = tid & 31, wid = tid >> 5;
    const int warpM = wid >> 2, warpN = wid & 3;
    const int rowBase = blockIdx.x * 128;

    int rA[2], cgA[2];
#pragma unroll
    for (int i = 0; i < 2; i++) {
        int g = tid + i * 512;
        rA[i] = g >> 3; cgA[i] = g & 7;
    }
    float4 pref[4];

    auto issueA = [&](int ch) {
#pragma unroll
        for (int i = 0; i < 2; i++) {
            int row = rowBase + rA[i];
            if (row < Mrows) {
                const float4* src = reinterpret_cast<const float4*>(
                    A + (size_t)row * DD + ch * 64 + cgA[i] * 8);
                pref[i * 2]     = src[0];
                pref[i * 2 + 1] = src[1];
            } else {
                pref[i * 2]     = make_float4(0.f, 0.f, 0.f, 0.f);
                pref[i * 2 + 1] = make_float4(0.f, 0.f, 0.f, 0.f);
            }
        }
    };
    auto storeA = [&](int s) {
#pragma unroll
        for (int i = 0; i < 2; i++) {
            float x[8];
            float4 v0 = pref[i * 2], v1 = pref[i * 2 + 1];
            x[0] = v0.x; x[1] = v0.y; x[2] = v0.z; x[3] = v0.w;
            x[4] = v1.x; x[5] = v1.y; x[6] = v1.z; x[7] = v1.w;
            unsigned short hi[8], lo[8];
#pragma unroll
            for (int j = 0; j < 8; j++) {
                __nv_bfloat16 h = __float2bfloat16(x[j]);
                __nv_bfloat16 l = __float2bfloat16(x[j] - __bfloat162float(h));
                hi[j] = *reinterpret_cast<unsigned short*>(&h);
                lo[j] = *reinterpret_cast<unsigned short*>(&l);
            }
            uint32_t off = s * 32768u + swz((uint32_t)rA[i], (uint32_t)cgA[i] * 16u);
            *reinterpret_cast<uint4*>(smem + off)         = *reinterpret_cast<uint4*>(hi);
            *reinterpret_cast<uint4*>(smem + 16384 + off) = *reinterpret_cast<uint4*>(lo);
        }
    };
    auto issueB = [&](int ch, int s) {
        const unsigned char* bh = Wp + (size_t)(ch * 2 + 0) * 32768;
        const unsigned char* bl = Wp + (size_t)(ch * 2 + 1) * 32768;
        uint32_t dh = sb + 65536u + (uint32_t)s * 65536u;
        uint32_t dl = dh + 32768u;
#pragma unroll
        for (int i = 0; i < 4; i++) {
            int idx = (tid + i * 512) * 16;
            CP_ASYNC16(dh + idx, bh + idx);
            CP_ASYNC16(dl + idx, bl + idx);
        }
        CP_COMMIT();
    };

    float c[2][8][4];
#pragma unroll
    for (int mt = 0; mt < 2; mt++)
#pragma unroll
        for (int nt = 0; nt < 8; nt++)
#pragma unroll
            for (int q = 0; q < 4; q++) c[mt][nt][q] = 0.f;

    issueA(0);
    issueB(0, 0);
    storeA(0);

    for (int ch = 0; ch < 4; ch++) {
        const int s = ch & 1;
        if (ch < 3) {
            issueA(ch + 1);
            issueB(ch + 1, s ^ 1);
            CP_WAIT(1);
        } else {
            CP_WAIT(0);
        }
        __syncthreads();

        const uint32_t aBase = sb + (uint32_t)s * 32768u;
        const uint32_t bBase = sb + 65536u + (uint32_t)s * 65536u;
#pragma unroll
        for (int ks = 0; ks < 4; ks++) {
            uint32_t ah[2][4], al[2][4];
#pragma unroll
            for (int mt = 0; mt < 2; mt++) {
                uint32_t row = (uint32_t)(warpM * 32 + mt * 16 + (lane & 7) + ((lane >> 3) & 1) * 8);
                uint32_t kb  = (uint32_t)(ks * 32 + ((lane >> 4) & 1) * 16);
                uint32_t addr = aBase + swz(row, kb);
                ldm_x4(addr,         ah[mt]);
                ldm_x4(addr + 16384, al[mt]);
            }
#pragma unroll
            for (int p = 0; p < 4; p++) {
                uint32_t nrow = (uint32_t)(warpN * 64 + p * 16 + (lane & 7) + ((lane >> 4) & 1) * 8);
                uint32_t kb   = (uint32_t)(ks * 32 + ((lane >> 3) & 1) * 16);
                uint32_t addr = bBase + swz(nrow, kb);
                uint32_t bh[4], bl[4];
                ldm_x4(addr,         bh);
                ldm_x4(addr + 32768, bl);
#pragma unroll
                for (int t = 0; t < 2; t++) {
#pragma unroll
                    for (int mt = 0; mt < 2; mt++) {
                        float* cc = c[mt][p * 2 + t];
                        mma_bf16(cc, ah[mt], bh + t * 2);
                        mma_bf16(cc, ah[mt], bl + t * 2);
                        mma_bf16(cc, al[mt], bh + t * 2);
                    }
                }
            }
        }
        if (ch < 3) storeA(s ^ 1);
        __syncthreads();
    }

    const int gid = lane >> 2, tig = lane & 3;
    float2* rb = reinterpret_cast<float2*>(smem);

#pragma unroll
    for (int mt = 0; mt < 2; mt++) {
        int r0 = rowBase + warpM * 32 + mt * 16 + gid;
        int r1 = r0 + 8;
        bool v0 = r0 < Mrows, v1 = r1 < Mrows;
#pragma unroll
        for (int nt = 0; nt < 8; nt++) {
            int col = warpN * 64 + nt * 8 + tig * 2;
            if (v0) *reinterpret_cast<float2*>(C + (size_t)r0 * DD + col)
                        = make_float2(c[mt][nt][0], c[mt][nt][1]);
            if (v1) *reinterpret_cast<float2*>(C + (size_t)r1 * DD + col)
                        = make_float2(c[mt][nt][2], c[mt][nt][3]);
        }
    }

    if (FLAGS & F_SNODE) {
#pragma unroll
        for (int mt = 0; mt < 2; mt++) {
            float s0 = 0.f, s1 = 0.f;
#pragma unroll
            for (int nt = 0; nt < 8; nt++) {
                int col = warpN * 64 + nt * 8 + tig * 2;
                float2 avv = *reinterpret_cast<const float2*>(av + col);
                s0 += c[mt][nt][0] * avv.x + c[mt][nt][1] * avv.y;
                s1 += c[mt][nt][2] * avv.x + c[mt][nt][3] * avv.y;
            }
#pragma unroll
            for (int o = 1; o < 4; o <<= 1) {
                s0 += __shfl_xor_sync(0xFFFFFFFFu, s0, o);
                s1 += __shfl_xor_sync(0xFFFFFFFFu, s1, o);
            }
            if (tig == 0) {
                int lr0 = warpM * 32 + mt * 16 + gid;
                rb[lr0 * 4 + warpN]       = make_float2(s0, 0.f);
                rb[(lr0 + 8) * 4 + warpN] = make_float2(s1, 0.f);
            }
        }
        __syncthreads();
        if (warpN == 0 && tig == 0) {
#pragma unroll
            for (int mt = 0; mt < 2; mt++) {
                int lr0 = warpM * 32 + mt * 16 + gid;
#pragma unroll
                for (int h = 0; h < 2; h++) {
                    int lr = lr0 + h * 8;
                    int row = rowBase + lr;
                    if (row < Mrows) {
                        snode[row] = rb[lr * 4 + 0].x + rb[lr * 4 + 1].x
                                   + rb[lr * 4 + 2].x + rb[lr * 4 + 3].x;
                    }
                }
            }
        }
    }
}

// ======== fused dual GEMM ========
__global__ __launch_bounds__(512, 1)
void tgemm_dual(const float* __restrict__ A, const unsigned char* __restrict__ Wp1,
                const float* __restrict__ bias1, const float* __restrict__ R1,
                const float* __restrict__ lng1, const float* __restrict__ lnb1,
                const unsigned char* __restrict__ Wp2, const float* __restrict__ bias2,
                const float* __restrict__ lng2, const float* __restrict__ lnb2,
                float* __restrict__ C2, const float* __restrict__ av,
                float* __restrict__ snode, int Mrows)
{
    extern __shared__ __align__(128) unsigned char smem[];
    const uint32_t sb = smem_to_u32(smem);
    const int tid = threadIdx.x, lane = tid & 31, wid = tid >> 5;
    const int warpM = wid >> 2, warpN = wid & 3;
    const int rowBase = blockIdx.x * 128;

    int rA[2], cgA[2];
#pragma unroll
    for (int i = 0; i < 2; i++) {
        int g = tid + i * 512;
        rA[i] = g >> 3; cgA[i] = g & 7;
    }
    float4 pref[4];

    auto issueA = [&](int ch) {
#pragma unroll
        for (int i = 0; i < 2; i++) {
            int row = rowBase + rA[i];
            if (row < Mrows) {
                const float4* src = reinterpret_cast<const float4*>(
                    A + (size_t)row * DD + ch * 64 + cgA[i] * 8);
                pref[i * 2]     = src[0];
                pref[i * 2 + 1] = src[1];
            } else {
                pref[i * 2]     = make_float4(0.f, 0.f, 0.f, 0.f);
                pref[i * 2 + 1] = make_float4(0.f, 0.f, 0.f, 0.f);
            }
        }
    };
    auto storeA = [&](int s) {
#pragma unroll
        for (int i = 0; i < 2; i++) {
            float x[8];
            float4 v0 = pref[i * 2], v1 = pref[i * 2 + 1];
            x[0] = v0.x; x[1] = v0.y; x[2] = v0.z; x[3] = v0.w;
            x[4] = v1.x; x[5] = v1.y; x[6] = v1.z; x[7] = v1.w;
            unsigned short hi[8], lo[8];
#pragma unroll
            for (int j = 0; j < 8; j++) {
                __nv_bfloat16 h = __float2bfloat16(x[j]);
                __nv_bfloat16 l = __float2bfloat16(x[j] - __bfloat162float(h));
                hi[j] = *reinterpret_cast<unsigned short*>(&h);
                lo[j] = *reinterpret_cast<unsigned short*>(&l);
            }
            uint32_t off = 131072u + s * 32768u + swz((uint32_t)rA[i], (uint32_t)cgA[i] * 16u);
            *reinterpret_cast<uint4*>(smem + off)         = *reinterpret_cast<uint4*>(hi);
            *reinterpret_cast<uint4*>(smem + 16384 + off) = *reinterpret_cast<uint4*>(lo);
        }
    };
    auto issueB1 = [&](int ch, int s) {
        const unsigned char* bh = Wp1 + (size_t)(ch * 2 + 0) * 32768;
        const unsigned char* bl = Wp1 + (size_t)(ch * 2 + 1) * 32768;
        uint32_t dh = sb + (uint32_t)s * 65536u;
        uint32_t dl = dh + 32768u;
#pragma unroll
        for (int i = 0; i < 4; i++) {
            int idx = (tid + i * 512) * 16;
            CP_ASYNC16(dh + idx, bh + idx);
            CP_ASYNC16(dl + idx, bl + idx);
        }
        CP_COMMIT();
    };
    auto issueB2 = [&](int ch) {
        const unsigned char* bh = Wp2 + (size_t)(ch * 2 + 0) * 32768;
        const unsigned char* bl = Wp2 + (size_t)(ch * 2 + 1) * 32768;
        uint32_t dh = sb + 131072u;
        uint32_t dl = dh + 32768u;
#pragma unroll
        for (int i = 0; i < 4; i++) {
            int idx = (tid + i * 512) * 16;
            CP_ASYNC16(dh + idx, bh + idx);
            CP_ASYNC16(dl + idx, bl + idx);
        }
        CP_COMMIT();
    };

    float c[2][8][4];
#pragma unroll
    for (int mt = 0; mt < 2; mt++)
#pragma unroll
        for (int nt = 0; nt < 8; nt++)
#pragma unroll
            for (int q = 0; q < 4; q++) c[mt][nt][q] = 0.f;

    // ---- phase 1 ----
    issueA(0);
    issueB1(0, 0);
    storeA(0);

    for (int ch = 0; ch < 4; ch++) {
        const int s = ch & 1;
        if (ch < 3) {
            issueA(ch + 1);
            issueB1(ch + 1, s ^ 1);
            CP_WAIT(1);
        } else {
            CP_WAIT(0);
        }
        __syncthreads();

        const uint32_t aBase = sb + 131072u + (uint32_t)s * 32768u;
        const uint32_t bBase = sb + (uint32_t)s * 65536u;
#pragma unroll
        for (int ks = 0; ks < 4; ks++) {
            uint32_t ah[2][4], al[2][4];
#pragma unroll
            for (int mt = 0; mt < 2; mt++) {
                uint32_t row = (uint32_t)(warpM * 32 + mt * 16 + (lane & 7) + ((lane >> 3) & 1) * 8);
                uint32_t kb  = (uint32_t)(ks * 32 + ((lane >> 4) & 1) * 16);
                uint32_t addr = aBase + swz(row, kb);
                ldm_x4(addr,         ah[mt]);
                ldm_x4(addr + 16384, al[mt]);
            }
#pragma unroll
            for (int p = 0; p < 4; p++) {
                uint32_t nrow = (uint32_t)(warpN * 64 + p * 16 + (lane & 7) + ((lane >> 4) & 1) * 8);
                uint32_t kb   = (uint32_t)(ks * 32 + ((lane >> 3) & 1) * 16);
                uint32_t addr = bBase + swz(nrow, kb);
                uint32_t bh[4], bl[4];
                ldm_x4(addr,         bh);
                ldm_x4(addr + 32768, bl);
#pragma unroll
                for (int t = 0; t < 2; t++) {
#pragma unroll
                    for (int mt = 0; mt < 2; mt++) {
                        float* cc = c[mt][p * 2 + t];
                        mma_bf16(cc, ah[mt], bh + t * 2);
                        mma_bf16(cc, ah[mt], bl + t * 2);
                        mma_bf16(cc, al[mt], bh + t * 2);
                    }
                }
            }
        }
        if (ch < 3) storeA(s ^ 1);
        __syncthreads();
    }

    // ---- epilogue 1 ----
    const int gid = lane >> 2, tig = lane & 3;
    float2* rb = reinterpret_cast<float2*>(smem + 131072);

#pragma unroll
    for (int mt = 0; mt < 2; mt++) {
        int r0 = rowBase + warpM * 32 + mt * 16 + gid;
        int r1 = r0 + 8;
        bool v0 = r0 < Mrows, v1 = r1 < Mrows;
#pragma unroll
        for (int nt = 0; nt < 8; nt++) {
            int col = warpN * 64 + nt * 8 + tig * 2;
            float2 bv = *reinterpret_cast<const float2*>(bias1 + col);
            float o0 = lrelu_f(c[mt][nt][0] + bv.x), o1 = lrelu_f(c[mt][nt][1] + bv.y);
            float o2 = lrelu_f(c[mt][nt][2] + bv.x), o3 = lrelu_f(c[mt][nt][3] + bv.y);
            if (v0) {
                float2 rv = *reinterpret_cast<const float2*>(R1 + (size_t)r0 * DD + col);
                o0 += rv.x; o1 += rv.y;
            }
            if (v1) {
                float2 rv = *reinterpret_cast<const float2*>(R1 + (size_t)r1 * DD + col);
                o2 += rv.x; o3 += rv.y;
            }
            c[mt][nt][0] = o0; c[mt][nt][1] = o1; c[mt][nt][2] = o2; c[mt][nt][3] = o3;
        }
    }
#pragma unroll
    for (int mt = 0; mt < 2; mt++) {
        float s0 = 0.f, q0 = 0.f, s1 = 0.f, q1 = 0.f;
#pragma unroll
        for (int nt = 0; nt < 8; nt++) {
            float o0 = c[mt][nt][0], o1 = c[mt][nt][1];
            float o2 = c[mt][nt][2], o3 = c[mt][nt][3];
            s0 += o0 + o1; q0 += o0 * o0 + o1 * o1;
            s1 += o2 + o3; q1 += o2 * o2 + o3 * o3;
        }
#pragma unroll
        for (int o = 1; o < 4; o <<= 1) {
            s0 += __shfl_xor_sync(0xFFFFFFFFu, s0, o);
            q0 += __shfl_xor_sync(0xFFFFFFFFu, q0, o);
            s1 += __shfl_xor_sync(0xFFFFFFFFu, s1, o);
            q1 += __shfl_xor_sync(0xFFFFFFFFu, q1, o);
        }
        if (tig == 0) {
            int lr0 = warpM * 32 + mt * 16 + gid;
            rb[lr0 * 4 + warpN]       = make_float2(s0, q0);
            rb[(lr0 + 8) * 4 + warpN] = make_float2(s1, q1);
        }
    }
    __syncthreads();
#pragma unroll
    for (int mt = 0; mt < 2; mt++) {
        int lr0 = warpM * 32 + mt * 16 + gid;
        int lr1 = lr0 + 8;
        float2 p00 = rb[lr0*4+0], p01 = rb[lr0*4+1], p02 = rb[lr0*4+2], p03 = rb[lr0*4+3];
        float2 p10 = rb[lr1*4+0], p11 = rb[lr1*4+1], p12 = rb[lr1*4+2], p13 = rb[lr1*4+3];
        float sum0 = p00.x + p01.x + p02.x + p03.x;
        float sq0  = p00.y + p01.y + p02.y + p03.y;
        float sum1 = p10.x + p11.x + p12.x + p13.x;
        float sq1  = p10.y + p11.y + p12.y + p13.y;
        float mean0 = sum0 * (1.f / 256.f);
        float rstd0 = rsqrtf(sq0 * (1.f / 256.f) - mean0 * mean0 + 1e-5f);
        float mean1 = sum1 * (1.f / 256.f);
        float rstd1 = rsqrtf(sq1 * (1.f / 256.f) - mean1 * mean1 + 1e-5f);
#pragma unroll
        for (int nt = 0; nt < 8; nt++) {
            int col = warpN * 64 + nt * 8 + tig * 2;
            float2 gv = *reinterpret_cast<const float2*>(lng1 + col);
            float2 bv = *reinterpret_cast<const float2*>(lnb1 + col);
            c[mt][nt][0] = (c[mt][nt][0] - mean0) * rstd0 * gv.x + bv.x;
            c[mt][nt][1] = (c[mt][nt][1] - mean0) * rstd0 * gv.y + bv.y;
            c[mt][nt][2] = (c[mt][nt][2] - mean1) * rstd1 * gv.x + bv.x;
            c[mt][nt][3] = (c[mt][nt][3] - mean1) * rstd1 * gv.y + bv.y;
        }
    }
    __syncthreads();

    // ---- store obj1 to A2 smem + issue B2 chunk 0 ----
    issueB2(0);
#pragma unroll
    for (int mt = 0; mt < 2; mt++) {
        uint32_t lr0 = (uint32_t)(warpM * 32 + mt * 16 + gid);
        uint32_t lr1 = lr0 + 8;
#pragma unroll
        for (int nt = 0; nt < 8; nt++) {
            uint32_t cb = (uint32_t)(warpN * 64 + nt * 8 + tig * 2) * 2u;
            float o0 = c[mt][nt][0], o1 = c[mt][nt][1];
            float o2 = c[mt][nt][2], o3 = c[mt][nt][3];
            __nv_bfloat16 h0 = __float2bfloat16(o0), h1 = __float2bfloat16(o1);
            __nv_bfloat16 h2 = __float2bfloat16(o2), h3 = __float2bfloat16(o3);
            __nv_bfloat16 l0 = __float2bfloat16(o0 - __bfloat162float(h0));
            __nv_bfloat16 l1 = __float2bfloat16(o1 - __bfloat162float(h1));
            __nv_bfloat16 l2 = __float2bfloat16(o2 - __bfloat162float(h2));
            __nv_bfloat16 l3 = __float2bfloat16(o3 - __bfloat162float(h3));
            uint32_t hp0 = ((uint32_t)*reinterpret_cast<unsigned short*>(&h1) << 16)
                         |  (uint32_t)*reinterpret_cast<unsigned short*>(&h0);
            uint32_t lp0 = ((uint32_t)*reinterpret_cast<unsigned short*>(&l1) << 16)
                         |  (uint32_t)*reinterpret_cast<unsigned short*>(&l0);
            uint32_t hp1 = ((uint32_t)*reinterpret_cast<unsigned short*>(&h3) << 16)
                         |  (uint32_t)*reinterpret_cast<unsigned short*>(&h2);
            uint32_t lp1 = ((uint32_t)*reinterpret_cast<unsigned short*>(&l3) << 16)
                         |  (uint32_t)*reinterpret_cast<unsigned short*>(&l2);
            *reinterpret_cast<uint32_t*>(smem + swz512(lr0, cb))           = hp0;
            *reinterpret_cast<uint32_t*>(smem + 65536u + swz512(lr0, cb))  = lp0;
            *reinterpret_cast<uint32_t*>(smem + swz512(lr1, cb))           = hp1;
            *reinterpret_cast<uint32_t*>(smem + 65536u + swz512(lr1, cb))  = lp1;
        }
    }
#pragma unroll
    for (int mt = 0; mt < 2; mt++)
#pragma unroll
        for (int nt = 0; nt < 8; nt++)
#pragma unroll
            for (int q = 0; q < 4; q++) c[mt][nt][q] = 0.f;
    __syncthreads();

    // ---- phase 2 ----
    for (int ch = 0; ch < 4; ch++) {
        CP_WAIT(0);
        __syncthreads();
        const uint32_t bBase = sb + 131072u;
#pragma unroll
        for (int ks = 0; ks < 4; ks++) {
            uint32_t ah[2][4], al[2][4];
#pragma unroll
            for (int mt = 0; mt < 2; mt++) {
                uint32_t row = (uint32_t)(warpM * 32 + mt * 16 + (lane & 7) + ((lane >> 3) & 1) * 8);
                uint32_t kb  = (uint32_t)(ch * 128 + ks * 32 + ((lane >> 4) & 1) * 16);
                uint32_t addr = sb + swz512(row, kb);
                ldm_x4(addr,          ah[mt]);
                ldm_x4(addr + 65536u, al[mt]);
            }
#pragma unroll
            for (int p = 0; p < 4; p++) {
                uint32_t nrow = (uint32_t)(warpN * 64 + p * 16 + (lane & 7) + ((lane >> 4) & 1) * 8);
                uint32_t kb   = (uint32_t)(ks * 32 + ((lane >> 3) & 1) * 16);
                uint32_t addr = bBase + swz(nrow, kb);
                uint32_t bh[4], bl[4];
                ldm_x4(addr,          bh);
                ldm_x4(addr + 32768u, bl);
#pragma unroll
                for (int t = 0; t < 2; t++) {
#pragma unroll
                    for (int mt = 0; mt < 2; mt++) {
                        float* cc = c[mt][p * 2 + t];
                        mma_bf16(cc, ah[mt], bh + t * 2);
                        mma_bf16(cc, ah[mt], bl + t * 2);
                        mma_bf16(cc, al[mt], bh + t * 2);
                    }
                }
            }
        }
        __syncthreads();
        if (ch < 3) issueB2(ch + 1);
    }

    // ---- epilogue 2 ----
#pragma unroll
    for (int mt = 0; mt < 2; mt++) {
        uint32_t lr0 = (uint32_t)(warpM * 32 + mt * 16 + gid);
        uint32_t lr1 = lr0 + 8;
#pragma unroll
        for (int nt = 0; nt < 8; nt++) {
            int col = warpN * 64 + nt * 8 + tig * 2;
            uint32_t cb = (uint32_t)col * 2u;
            float2 bv = *reinterpret_cast<const float2*>(bias2 + col);
            float o0 = lrelu_f(c[mt][nt][0] + bv.x), o1 = lrelu_f(c[mt][nt][1] + bv.y);
            float o2 = lrelu_f(c[mt][nt][2] + bv.x), o3 = lrelu_f(c[mt][nt][3] + bv.y);
            uint32_t hp0 = *reinterpret_cast<uint32_t*>(smem + swz512(lr0, cb));
            uint32_t lp0 = *reinterpret_cast<uint32_t*>(smem + 65536u + swz512(lr0, cb));
            uint32_t hp1 = *reinterpret_cast<uint32_t*>(smem + swz512(lr1, cb));
            uint32_t lp1 = *reinterpret_cast<uint32_t*>(smem + 65536u + swz512(lr1, cb));
            unsigned short u;
            u = (unsigned short)(hp0 & 0xFFFF);
            float r0a = __bfloat162float(*reinterpret_cast<__nv_bfloat16*>(&u));
            u = (unsigned short)(lp0 & 0xFFFF);
            r0a += __bfloat162float(*reinterpret_cast<__nv_bfloat16*>(&u));
            u = (unsigned short)(hp0 >> 16);
            float r0b = __bfloat162float(*reinterpret_cast<__nv_bfloat16*>(&u));
            u = (unsigned short)(lp0 >> 16);
            r0b += __bfloat162float(*reinterpret_cast<__nv_bfloat16*>(&u));
            u = (unsigned short)(hp1 & 0xFFFF);
            float r1a = __bfloat162float(*reinterpret_cast<__nv_bfloat16*>(&u));
            u = (unsigned short)(lp1 & 0xFFFF);
            r1a += __bfloat162float(*reinterpret_cast<__nv_bfloat16*>(&u));
            u = (unsigned short)(hp1 >> 16);
            float r1b = __bfloat162float(*reinterpret_cast<__nv_bfloat16*>(&u));
            u = (unsigned short)(lp1 >> 16);
            r1b += __bfloat162float(*reinterpret_cast<__nv_bfloat16*>(&u));
            c[mt][nt][0] = o0 + r0a; c[mt][nt][1] = o1 + r0b;
            c[mt][nt][2] = o2 + r1a; c[mt][nt][3] = o3 + r1b;
        }
    }
#pragma unroll
    for (int mt = 0; mt < 2; mt++) {
        float s0 = 0.f, q0 = 0.f, s1 = 0.f, q1 = 0.f;
#pragma unroll
        for (int nt = 0; nt < 8; nt++) {
            float o0 = c[mt][nt][0], o1 = c[mt][nt][1];
            float o2 = c[mt][nt][2], o3 = c[mt][nt][3];
            s0 += o0 + o1; q0 += o0 * o0 + o1 * o1;
            s1 += o2 + o3; q1 += o2 * o2 + o3 * o3;
        }
#pragma unroll
        for (int o = 1; o < 4; o <<= 1) {
            s0 += __shfl_xor_sync(0xFFFFFFFFu, s0, o);
            q0 += __shfl_xor_sync(0xFFFFFFFFu, q0, o);
            s1 += __shfl_xor_sync(0xFFFFFFFFu, s1, o);
            q1 += __shfl_xor_sync(0xFFFFFFFFu, q1, o);
        }
        if (tig == 0) {
            int lr0 = warpM * 32 + mt * 16 + gid;
            rb[lr0 * 4 + warpN]       = make_float2(s0, q0);
            rb[(lr0 + 8) * 4 + warpN] = make_float2(s1, q1);
        }
    }
    __syncthreads();
    float sd[2][2] = {{0.f, 0.f}, {0.f, 0.f}};
#pragma unroll
    for (int mt = 0; mt < 2; mt++) {
        int lr0 = warpM * 32 + mt * 16 + gid;
        int lr1 = lr0 + 8;
        float2 p00 = rb[lr0*4+0], p01 = rb[lr0*4+1], p02 = rb[lr0*4+2], p03 = rb[lr0*4+3];
        float2 p10 = rb[lr1*4+0], p11 = rb[lr1*4+1], p12 = rb[lr1*4+2], p13 = rb[lr1*4+3];
        float sum0 = p00.x + p01.x + p02.x + p03.x;
        float sq0  = p00.y + p01.y + p02.y + p03.y;
        float sum1 = p10.x + p11.x + p12.x + p13.x;
        float sq1  = p10.y + p11.y + p12.y + p13.y;
        float mean0 = sum0 * (1.f / 256.f);
        float rstd0 = rsqrtf(sq0 * (1.f / 256.f) - mean0 * mean0 + 1e-5f);
        float mean1 = sum1 * (1.f / 256.f);
        float rstd1 = rsqrtf(sq1 * (1.f / 256.f) - mean1 * mean1 + 1e-5f);
        int r0 = rowBase + lr0, r1 = rowBase + lr1;
        bool v0 = r0 < Mrows, v1 = r1 < Mrows;
#pragma unroll
        for (int nt = 0; nt < 8; nt++) {
            int col = warpN * 64 + nt * 8 + tig * 2;
            float2 gv = *reinterpret_cast<const float2*>(lng2 + col);
            float2 bv = *reinterpret_cast<const float2*>(lnb2 + col);
            float o0 = (c[mt][nt][0] - mean0) * rstd0 * gv.x + bv.x;
            float o1 = (c[mt][nt][1] - mean0) * rstd0 * gv.y + bv.y;
            float o2 = (c[mt][nt][2] - mean1) * rstd1 * gv.x + bv.x;
            float o3 = (c[mt][nt][3] - mean1) * rstd1 * gv.y + bv.y;
            if (v0) *reinterpret_cast<float2*>(C2 + (size_t)r0 * DD + col) = make_float2(o0, o1);
            if (v1) *reinterpret_cast<float2*>(C2 + (size_t)r1 * DD + col) = make_float2(o2, o3);
            float2 avv = *reinterpret_cast<const float2*>(av + col);
            sd[mt][0] += o0 * avv.x + o1 * avv.y;
            sd[mt][1] += o2 * avv.x + o3 * avv.y;
        }
    }
    __syncthreads();
#pragma unroll
    for (int mt = 0; mt < 2; mt++) {
        float s0 = sd[mt][0], s1 = sd[mt][1];
#pragma unroll
        for (int o = 1; o < 4; o <<= 1) {
            s0 += __shfl_xor_sync(0xFFFFFFFFu, s0, o);
            s1 += __shfl_xor_sync(0xFFFFFFFFu, s1, o);
        }
        if (tig == 0) {
            int lr0 = warpM * 32 + mt * 16 + gid;
            rb[lr0 * 4 + warpN]       = make_float2(s0, 0.f);
            rb[(lr0 + 8) * 4 + warpN] = make_float2(s1, 0.f);
        }
    }
    __syncthreads();
    if (warpN == 0 && tig == 0) {
#pragma unroll
        for (int mt = 0; mt < 2; mt++) {
            int lr0 = warpM * 32 + mt * 16 + gid;
#pragma unroll
            for (int h = 0; h < 2; h++) {
                int lr = lr0 + h * 8;
                int row = rowBase + lr;
                if (row < Mrows) {
                    snode[row] = rb[lr * 4 + 0].x + rb[lr * 4 + 1].x
                               + rb[lr * 4 + 2].x + rb[lr * 4 + 3].x;
                }
            }
        }
    }
}

// -------- edge gather (value-direct node ids) --------
__global__ void edge_gatherX(const float* __restrict__ X, const int* __restrict__ nodeE,
                             const int* __restrict__ offE, const int* __restrict__ cntE,
                             float* __restrict__ Xmean, int act, int nEdges)
{
    int ed = blockIdx.x * 8 + (threadIdx.x >> 5);
    if (ed >= nEdges) return;
    int lane = threadIdx.x & 31;
    int start = offE[ed], deg = cntE[ed];
    float4 a0 = make_float4(0.f,0.f,0.f,0.f), a1 = a0;
    for (int base = 0; base < deg; base += 32) {
        int m = min(32, deg - base);
        int src = 0;
        if (lane < m) src = nodeE[start + base + lane];
        for (int i = 0; i < m; i++) {
            int node = __shfl_sync(0xFFFFFFFFu, src, i);
            const float4* rp = reinterpret_cast<const float4*>(X + (size_t)node * DD + lane * 8);
            float4 v0 = rp[0], v1 = rp[1];
            if (act) {
                v0.x = lrelu_f(v0.x); v0.y = lrelu_f(v0.y); v0.z = lrelu_f(v0.z); v0.w = lrelu_f(v0.w);
                v1.x = lrelu_f(v1.x); v1.y = lrelu_f(v1.y); v1.z = lrelu_f(v1.z); v1.w = lrelu_f(v1.w);
            }
            a0.x += v0.x; a0.y += v0.y; a0.z += v0.z; a0.w += v0.w;
            a1.x += v1.x; a1.y += v1.y; a1.z += v1.z; a1.w += v1.w;
        }
    }
    float inv = 1.f / fmaxf((float)deg, 1.f);
    a0.x *= inv; a0.y *= inv; a0.z *= inv; a0.w *= inv;
    a1.x *= inv; a1.y *= inv; a1.z *= inv; a1.w *= inv;
    float4* op = reinterpret_cast<float4*>(Xmean + (size_t)ed * DD + lane * 8);
    op[0] = a0; op[1] = a1;
}

// -------- fused per-node softmax + aggregate (value-direct edge ids) --------
__global__ void node_attn_agg(const float* __restrict__ ef, const float* __restrict__ sn,
                              const float* __restrict__ se, const int* __restrict__ edN,
                              const int* __restrict__ permN, const int* __restrict__ offN,
                              const int* __restrict__ cntN, float* __restrict__ attn,
                              float* __restrict__ out, const float* __restrict__ av,
                              float* __restrict__ snodeOut, int doLrelu, int nNodes)
{
    int n = blockIdx.x * 8 + (threadIdx.x >> 5);
    if (n >= nNodes) return;
    int lane = threadIdx.x & 31;
    int st = offN[n], deg = cntN[n];
    float4 a0 = make_float4(0.f,0.f,0.f,0.f), a1 = a0;

    if (deg > 0) {
        float s0 = sn[n];
        if (deg <= 32) {
            int ed = 0;
            float sc = -3.4e38f;
            if (lane < deg) {
                ed = edN[st + lane];
                sc = lrelu_f(s0 + se[ed]);
            }
            float mx = sc;
#pragma unroll
            for (int o = 16; o; o >>= 1) mx = fmaxf(mx, __shfl_xor_sync(0xFFFFFFFFu, mx, o));
            float e = (lane < deg) ? expf(sc - mx) : 0.f;
            float z = e;
#pragma unroll
            for (int o = 16; o; o >>= 1) z += __shfl_xor_sync(0xFFFFFFFFu, z, o);
            float w = e / fmaxf(z, 1e-9f);
            if (lane < deg && attn != nullptr) attn[permN[st + lane]] = w;
            for (int i = 0; i < deg; i++) {
                int e_   = __shfl_sync(0xFFFFFFFFu, ed, i);
                float w_ = __shfl_sync(0xFFFFFFFFu, w, i);
                const float4* rp = reinterpret_cast<const float4*>(ef + (size_t)e_ * DD + lane * 8);
                float4 v0 = rp[0], v1 = rp[1];
                a0.x += w_*v0.x; a0.y += w_*v0.y; a0.z += w_*v0.z; a0.w += w_*v0.w;
                a1.x += w_*v1.x; a1.y += w_*v1.y; a1.z += w_*v1.z; a1.w += w_*v1.w;
            }
        } else {
            float mx = -3.4e38f;
            for (int base = 0; base < deg; base += 32) {
                float sc = -3.4e38f;
                if (base + lane < deg)
                    sc = lrelu_f(s0 + se[edN[st + base + lane]]);
                mx = fmaxf(mx, sc);
            }
#pragma unroll
            for (int o = 16; o; o >>= 1) mx = fmaxf(mx, __shfl_xor_sync(0xFFFFFFFFu, mx, o));
            float z = 0.f;
            for (int base = 0; base < deg; base += 32) {
                if (base + lane < deg)
                    z += expf(lrelu_f(s0 + se[edN[st + base + lane]]) - mx);
            }
#pragma unroll
            for (int o = 16; o; o >>= 1) z += __shfl_xor_sync(0xFFFFFFFFu, z, o);
            float invz = 1.f / fmaxf(z, 1e-9f);
            for (int base = 0; base < deg; base += 32) {
                int m = min(32, deg - base);
                int ed = 0; float w = 0.f;
                if (lane < m) {
                    ed = edN[st + base + lane];
                    w = expf(lrelu_f(s0 + se[ed]) - mx) * invz;
                    if (attn != nullptr) attn[permN[st + base + lane]] = w;
                }
                for (int i = 0; i < m; i++) {
                    int e_   = __shfl_sync(0xFFFFFFFFu, ed, i);
                    float w_ = __shfl_sync(0xFFFFFFFFu, w, i);
                    const float4* rp = reinterpret_cast<const float4*>(ef + (size_t)e_ * DD + lane * 8);
                    float4 v0 = rp[0], v1 = rp[1];
                    a0.x += w_*v0.x; a0.y += w_*v0.y; a0.z += w_*v0.z; a0.w += w_*v0.w;
                    a1.x += w_*v1.x; a1.y += w_*v1.y; a1.z += w_*v1.z; a1.w += w_*v1.w;
                }
            }
        }
    }
    if (snodeOut != nullptr) {
        const float4* ap = reinterpret_cast<const float4*>(av + lane * 8);
        float4 w0 = ap[0], w1 = ap[1];
        float d = lrelu_f(a0.x)*w0.x + lrelu_f(a0.y)*w0.y + lrelu_f(a0.z)*w0.z + lrelu_f(a0.w)*w0.w
                + lrelu_f(a1.x)*w1.x + lrelu_f(a1.y)*w1.y + lrelu_f(a1.z)*w1.z + lrelu_f(a1.w)*w1.w;
#pragma unroll
        for (int o = 16; o; o >>= 1) d += __shfl_xor_sync(0xFFFFFFFFu, d, o);
        if (lane == 0) snodeOut[n] = d;
    }
    if (doLrelu) {
        a0.x = lrelu_f(a0.x); a0.y = lrelu_f(a0.y); a0.z = lrelu_f(a0.z); a0.w = lrelu_f(a0.w);
        a1.x = lrelu_f(a1.x); a1.y = lrelu_f(a1.y); a1.z = lrelu_f(a1.z); a1.w = lrelu_f(a1.w);
    }
    float4* op = reinterpret_cast<float4*>(out + (size_t)n * DD + lane * 8);
    op[0] = a0; op[1] = a1;
}

// -------- object message gather (value-direct event rows) --------
__global__ void obj_gather(const float* __restrict__ ev, const int* __restrict__ srcO,
                           const int* __restrict__ offO, const int* __restrict__ cntO,
                           float* __restrict__ msg, int nObj)
{
    int o = blockIdx.x * 8 + (threadIdx.x >> 5);
    if (o >= nObj) return;
    int lane = threadIdx.x & 31;
    int start = offO[o], deg = cntO[o];
    float4 a0 = make_float4(0.f,0.f,0.f,0.f), a1 = a0;
    for (int base = 0; base < deg; base += 32) {
        int m = min(32, deg - base);
        int src = 0;
        if (lane < m) src = srcO[start + base + lane];
        for (int i = 0; i < m; i++) {
            int row = __shfl_sync(0xFFFFFFFFu, src, i);
            const float4* rp = reinterpret_cast<const float4*>(ev + (size_t)row * DD + lane * 8);
            float4 v0 = rp[0], v1 = rp[1];
            a0.x += v0.x; a0.y += v0.y; a0.z += v0.z; a0.w += v0.w;
            a1.x += v1.x; a1.y += v1.y; a1.z += v1.z; a1.w += v1.w;
        }
    }
    float4* op = reinterpret_cast<float4*>(msg + (size_t)o * DD + lane * 8);
    op[0] = a0; op[1] = a1;
}

// ----------------- host orchestration -----------------
struct Ptrs {
    float *X, *obj, *msg, *H, *ef, *snode, *sedge, *wav1, *wav2;
    unsigned char* wp;
    int *cntE, *offE, *nodeE, *cntN, *offN, *permN, *edN, *cntO, *offO, *srcO;
};

static void get_ptrs(Ptrs& p) {
    cudaGetSymbolAddress((void**)&p.X,     g_X);
    cudaGetSymbolAddress((void**)&p.obj,   g_obj);
    cudaGetSymbolAddress((void**)&p.msg,   g_msg);
    cudaGetSymbolAddress((void**)&p.H,     g_H);
    cudaGetSymbolAddress((void**)&p.ef,    g_ef);
    cudaGetSymbolAddress((void**)&p.snode, g_snode);
    cudaGetSymbolAddress((void**)&p.sedge, g_sedge);
    cudaGetSymbolAddress((void**)&p.wav1,  g_wav1);
    cudaGetSymbolAddress((void**)&p.wav2,  g_wav2);
    cudaGetSymbolAddress((void**)&p.wp,    g_Wprep);
    cudaGetSymbolAddress((void**)&p.cntE,  g_cntE);
    cudaGetSymbolAddress((void**)&p.offE,  g_offE);
    cudaGetSymbolAddress((void**)&p.nodeE, g_nodeE);
    cudaGetSymbolAddress((void**)&p.cntN,  g_cntN);
    cudaGetSymbolAddress((void**)&p.offN,  g_offN);
    cudaGetSymbolAddress((void**)&p.permN, g_permN);
    cudaGetSymbolAddress((void**)&p.edN,   g_edN);
    cudaGetSymbolAddress((void**)&p.cntO,  g_cntO);
    cudaGetSymbolAddress((void**)&p.offO,  g_offO);
    cudaGetSymbolAddress((void**)&p.srcO,  g_srcO);
}

extern "C" void kernel_launch(void* const* d_in, const int* in_sizes, int n_in,
                              void* d_out, int out_size)
{
    const float* object_X = (const float*)d_in[0];
    const float* event_X  = (const float*)d_in[1];
    const float* Wo = (const float*)d_in[2];  const float* bo  = (const float*)d_in[3];
    const float* go = (const float*)d_in[4];  const float* bon = (const float*)d_in[5];
    const float* We = (const float*)d_in[6];  const float* be  = (const float*)d_in[7];
    const float* ge = (const float*)d_in[8];  const float* ben = (const float*)d_in[9];
    const float* Wu = (const float*)d_in[10]; const float* bu  = (const float*)d_in[11];
    const float* Wl = (const float*)d_in[12]; const float* bl  = (const float*)d_in[13];
    const float* g1 = (const float*)d_in[14]; const float* b1  = (const float*)d_in[15];
    const float* g2 = (const float*)d_in[16]; const float* b2  = (const float*)d_in[17];
    const float* Wh1 = (const float*)d_in[18]; const float* ah1 = (const float*)d_in[19];
    const float* Wh2 = (const float*)d_in[20]; const float* ah2 = (const float*)d_in[21];
    const int* oe_ev   = (const int*)d_in[22];
    const int* oe_obj  = (const int*)d_in[23];
    const int* hg_node = (const int*)d_in[24];
    const int* hg_edge = (const int*)d_in[25];

    Ptrs p; get_ptrs(p);

    // Static side-stream + events (created on the uncaptured correctness call)
    static cudaStream_t s2 = nullptr;
    static cudaEvent_t evFork = nullptr, evJoin = nullptr;
    if (s2 == nullptr) {
        cudaStreamCreateWithFlags(&s2, cudaStreamNonBlocking);
        cudaEventCreateWithFlags(&evFork, cudaEventDisableTiming);
        cudaEventCreateWithFlags(&evJoin, cudaEventDisableTiming);
    }

    // ---- fork: CSR build on side stream, overlapped with weight prep + proj GEMM ----
    cudaEventRecord(evFork, 0);
    cudaStreamWaitEvent(s2, evFork, 0);
    zero_misc<<<(2 * (NE + NN + NO) + 255) / 256, 256, 0, s2>>>();
    count_all<<<(2 * E2N + E1N + 255) / 256, 256, 0, s2>>>(hg_edge, hg_node, oe_obj);
    scan_all<<<NBT, 1024, 0, s2>>>();
    scan_small3<<<1, 32, 0, s2>>>();
    add_off_all<<<(NE + NN + NO + 255) / 256, 256, 0, s2>>>();
    fill_all<<<(2 * E2N + E1N + 255) / 256, 256, 0, s2>>>(hg_edge, hg_node, oe_obj, oe_ev);
    cudaEventRecord(evJoin, s2);

    // ---- main stream: weight prep + projections ----
    prep_w<<<dim3(32, 6), 256>>>(We, Wo, Wu, Wl, Wh1, Wh2);
    prep_wav<<<(DD + 7) / 8, 256>>>(Wh1, ah1, p.wav1);
    prep_wav<<<(DD + 7) / 8, 256>>>(Wh2, ah2, p.wav2);

    const unsigned char *wpe = p.wp, *wpo = p.wp + 262144, *wpu = p.wp + 2 * 262144,
                        *wpl = p.wp + 3 * 262144, *wph1 = p.wp + 4 * 262144,
                        *wph2 = p.wp + 5 * 262144;

    cudaFuncSetAttribute(proj_gemm, cudaFuncAttributeMaxDynamicSharedMemorySize, SMEM_SZ);
    int nb0 = (NE + 127) / 128, nb1 = (NO + 127) / 128;
    proj_gemm<<<nb0 + nb1, 512, SMEM_SZ>>>(
        event_X, wpe, be, ge, ben, p.X, p.wav1, p.snode, NE, nb0,
        object_X, wpo, bo, go, bon, p.obj, NO);

    // ---- join: CSR must be ready before gathers ----
    cudaStreamWaitEvent(0, evJoin, 0);

    // 3) msg = segment_sum(ev[oe_ev], oe_obj)
    obj_gather<<<(NO + 7) / 8, 256>>>(p.X, p.srcO, p.offO, p.cntO, p.msg, NO);

    // 4+5) fused dual GEMM -> X[NE:NN) + snode for obj rows
    cudaFuncSetAttribute(tgemm_dual, cudaFuncAttributeMaxDynamicSharedMemorySize, SMEM_SZ);
    tgemm_dual<<<(NO + 127) / 128, 512, SMEM_SZ>>>(p.msg, wpu, bu, p.obj, g1, b1,
                                                   wpl, bl, g2, b2,
                                                   p.X + (size_t)NE * DD,
                                                   p.wav1, p.snode + NE, NO);

    // 6) HGNN layer 1 -> H; snode2 fused into node_attn_agg
    cudaFuncSetAttribute(tgemm256<F_SNODE>, cudaFuncAttributeMaxDynamicSharedMemorySize, SMEM_SZ);
    edge_gatherX<<<(NE + 7) / 8, 256>>>(p.X, p.nodeE, p.offE, p.cntE, p.msg, 0, NE);
    tgemm256<F_SNODE><<<(NE + 127) / 128, 512, SMEM_SZ>>>(p.msg, wph1, ah1 + DD, p.ef, p.sedge, NE);
    node_attn_agg<<<(NN + 7) / 8, 256>>>(p.ef, p.snode, p.sedge, p.edN,
                                         p.permN, p.offN, p.cntN,
                                         nullptr, p.H, p.wav2, p.snode, 0, NN);

    // 7) HGNN layer 2 -> d_out
    float* out = (float*)d_out;
    edge_gatherX<<<(NE + 7) / 8, 256>>>(p.H, p.nodeE, p.offE, p.cntE, p.msg, 1, NE);
    tgemm256<F_SNODE><<<(NE + 127) / 128, 512, SMEM_SZ>>>(p.msg, wph2, ah2 + DD, p.ef, p.sedge, NE);
    node_attn_agg<<<(NN + 7) / 8, 256>>>(p.ef, p.snode, p.sedge, p.edN,
                                         p.permN, p.offN, p.cntN,
                                         out + (size_t)NN * DD, out, nullptr, nullptr, 1, NN);
}